// round 1
// baseline (speedup 1.0000x reference)
#include <cuda_runtime.h>
#include <cstdint>

#define NS   8192
#define TSTEPS 72
#define HH   64
#define GG   256      // 4*H gates
#define SPAD 132      // padded sample stride in smem

// ---------------- scratch (device globals; no allocation allowed) ----------
__device__ float g_xt_obs[TSTEPS * 32 * NS];   // [T][C1][N]  75.5 MB
__device__ float g_xt_wrf[TSTEPS * 56 * NS];   // [T][C2][N]  132 MB
__device__ float g_featT[128 * NS];            // [128][N]    4 MB (h_obs rows 0..63, h_wrf rows 64..127)

// ---------------- helpers --------------------------------------------------
__device__ __forceinline__ float sigm_f(float x) {
    return __fdividef(1.0f, 1.0f + __expf(-x));
}
__device__ __forceinline__ float tanh_f(float x) {
    // tanh(x) = 2*sigmoid(2x) - 1 ; exact at extremes with __expf saturation
    return __fdividef(2.0f, 1.0f + __expf(-2.0f * x)) - 1.0f;
}
__device__ __forceinline__ void cp_async16(float* dst, const float* src) {
    unsigned sa = (unsigned)__cvta_generic_to_shared(dst);
    asm volatile("cp.async.ca.shared.global [%0], [%1], 16;\n" :: "r"(sa), "l"(src));
}
__device__ __forceinline__ void cp_commit()   { asm volatile("cp.async.commit_group;\n"); }
__device__ __forceinline__ void cp_wait_all() { asm volatile("cp.async.wait_all;\n"); }

// ---------------- kernel 1: transpose [N][C][T] -> [T][C][N] ----------------
__global__ void athx_transpose_kernel(const float* __restrict__ in, int C, int which) {
    __shared__ float tile[32][33];
    float* out = which ? g_xt_wrf : g_xt_obs;
    const int c  = blockIdx.z;
    const int n0 = blockIdx.x * 32;
    const int t0 = blockIdx.y * 32;
    const int tx = threadIdx.x, ty = threadIdx.y;
    #pragma unroll
    for (int r = 0; r < 4; ++r) {
        int n = n0 + ty + r * 8;
        int t = t0 + tx;
        if (t < TSTEPS)
            tile[ty + r * 8][tx] = in[((size_t)n * C + c) * TSTEPS + t];
    }
    __syncthreads();
    #pragma unroll
    for (int r = 0; r < 4; ++r) {
        int t = t0 + ty + r * 8;
        int n = n0 + tx;
        if (t < TSTEPS)
            out[((size_t)t * C + c) * NS + n] = tile[tx][ty + r * 8];
    }
}

// ---------------- kernel 2: fused dual-LSTM, persistent per-sample-tile -----
// grid 128 CTAs: blocks 0..63 -> obs LSTM, 64..127 -> wrf LSTM, 128 samples each.
// Per thread: 8 samples x 16 gate-cols (cols = 4*gx+jj + 64*q, q=gate type),
// so each thread owns all 4 gate types of its (sample, j) pairs -> c stays in regs.
__global__ __launch_bounds__(256, 1) void athx_lstm_kernel(
    const float* __restrict__ oWih, const float* __restrict__ oWhh,
    const float* __restrict__ obih, const float* __restrict__ obhh,
    const float* __restrict__ wWih, const float* __restrict__ wWhh,
    const float* __restrict__ wbih, const float* __restrict__ wbhh)
{
    extern __shared__ float sm[];
    const bool wrf = (blockIdx.x >= 64);
    const int  C   = wrf ? 56 : 32;
    const int  K   = C + HH;
    const float* xt  = wrf ? g_xt_wrf : g_xt_obs;
    const float* Wih = wrf ? wWih : oWih;
    const float* Whh = wrf ? wWhh : oWhh;
    const float* bih = wrf ? wbih : obih;
    const float* bhh = wrf ? wbhh : obhh;
    const int n0  = (blockIdx.x & 63) * 128;
    const int tid = threadIdx.x;
    const int gx  = tid & 15;      // gate-column group
    const int sx  = tid >> 4;      // sample group

    float* Wsm = sm;                   // [K][256]   fused [Wih|Whh]^T
    float* Hsm = sm + K * GG;          // [64][SPAD] h, k-major
    float* Xsm = Hsm + HH * SPAD;      // [2][C][SPAD] double-buffered x_t

    // load weights (transposed) into smem: Wsm[k][g]
    for (int idx = tid; idx < GG * C; idx += 256) {
        int g = idx / C, c = idx - g * C;
        Wsm[c * GG + g] = Wih[idx];
    }
    for (int idx = tid; idx < GG * HH; idx += 256) {
        int g = idx >> 6, k = idx & 63;
        Wsm[(C + k) * GG + g] = Whh[idx];
    }
    for (int idx = tid; idx < HH * SPAD; idx += 256) Hsm[idx] = 0.0f;

    // combined bias per owned column (acc initializer)
    float bia[16];
    #pragma unroll
    for (int q = 0; q < 4; ++q)
        #pragma unroll
        for (int jj = 0; jj < 4; ++jj) {
            int col = q * 64 + gx * 4 + jj;
            bia[q * 4 + jj] = bih[col] + bhh[col];
        }

    float creg[8][4];
    #pragma unroll
    for (int s = 0; s < 8; ++s)
        #pragma unroll
        for (int jj = 0; jj < 4; ++jj) creg[s][jj] = 0.0f;

    // prefetch x tile for t = 0
    for (int idx = tid; idx < C * 32; idx += 256) {
        int c = idx >> 5, v = idx & 31;
        cp_async16(&Xsm[c * SPAD + v * 4], xt + ((size_t)c) * NS + n0 + v * 4);
    }
    cp_commit();

    for (int t = 0; t < TSTEPS; ++t) {
        const int cur = t & 1;
        cp_wait_all();
        __syncthreads();   // x[cur] ready; Hsm writes from t-1 visible

        if (t + 1 < TSTEPS) {
            float* xdst = Xsm + (cur ^ 1) * C * SPAD;
            for (int idx = tid; idx < C * 32; idx += 256) {
                int c = idx >> 5, v = idx & 31;
                cp_async16(xdst + c * SPAD + v * 4,
                           xt + ((size_t)(t + 1) * C + c) * NS + n0 + v * 4);
            }
            cp_commit();
        }

        float acc[8][16];
        #pragma unroll
        for (int s = 0; s < 8; ++s)
            #pragma unroll
            for (int j = 0; j < 16; ++j) acc[s][j] = bia[j];

        // ---- x-projection part: k over C channels ----
        const float* Xc = Xsm + cur * C * SPAD;
        #pragma unroll 2
        for (int k = 0; k < C; ++k) {
            float4 a0 = *(const float4*)(Xc + k * SPAD + sx * 8);
            float4 a1 = *(const float4*)(Xc + k * SPAD + sx * 8 + 4);
            const float* br = Wsm + k * GG + gx * 4;
            float4 b0 = *(const float4*)(br);
            float4 b1 = *(const float4*)(br + 64);
            float4 b2 = *(const float4*)(br + 128);
            float4 b3 = *(const float4*)(br + 192);
            float av[8]  = {a0.x, a0.y, a0.z, a0.w, a1.x, a1.y, a1.z, a1.w};
            float bv[16] = {b0.x, b0.y, b0.z, b0.w, b1.x, b1.y, b1.z, b1.w,
                            b2.x, b2.y, b2.z, b2.w, b3.x, b3.y, b3.z, b3.w};
            #pragma unroll
            for (int s = 0; s < 8; ++s)
                #pragma unroll
                for (int j = 0; j < 16; ++j)
                    acc[s][j] = fmaf(av[s], bv[j], acc[s][j]);
        }
        // ---- recurrent part: k over 64 h-dims ----
        #pragma unroll 2
        for (int k = 0; k < HH; ++k) {
            float4 a0 = *(const float4*)(Hsm + k * SPAD + sx * 8);
            float4 a1 = *(const float4*)(Hsm + k * SPAD + sx * 8 + 4);
            const float* br = Wsm + (C + k) * GG + gx * 4;
            float4 b0 = *(const float4*)(br);
            float4 b1 = *(const float4*)(br + 64);
            float4 b2 = *(const float4*)(br + 128);
            float4 b3 = *(const float4*)(br + 192);
            float av[8]  = {a0.x, a0.y, a0.z, a0.w, a1.x, a1.y, a1.z, a1.w};
            float bv[16] = {b0.x, b0.y, b0.z, b0.w, b1.x, b1.y, b1.z, b1.w,
                            b2.x, b2.y, b2.z, b2.w, b3.x, b3.y, b3.z, b3.w};
            #pragma unroll
            for (int s = 0; s < 8; ++s)
                #pragma unroll
                for (int j = 0; j < 16; ++j)
                    acc[s][j] = fmaf(av[s], bv[j], acc[s][j]);
        }

        __syncthreads();   // all reads of Hsm done before overwriting

        // gate nonlinearities + state update (PyTorch order i,f,g,o)
        #pragma unroll
        for (int jj = 0; jj < 4; ++jj) {
            float hv[8];
            #pragma unroll
            for (int s = 0; s < 8; ++s) {
                float gi = sigm_f(acc[s][jj]);
                float gf = sigm_f(acc[s][4 + jj]);
                float gg = tanh_f(acc[s][8 + jj]);
                float go = sigm_f(acc[s][12 + jj]);
                float c  = fmaf(gf, creg[s][jj], gi * gg);
                creg[s][jj] = c;
                hv[s] = go * tanh_f(c);
            }
            float* hrow = Hsm + (gx * 4 + jj) * SPAD + sx * 8;
            *(float4*)(hrow)     = make_float4(hv[0], hv[1], hv[2], hv[3]);
            *(float4*)(hrow + 4) = make_float4(hv[4], hv[5], hv[6], hv[7]);
        }
    }

    __syncthreads();
    const int off = wrf ? 64 : 0;
    for (int idx = tid; idx < HH * 128; idx += 256) {
        int j = idx >> 7, n = idx & 127;
        g_featT[(size_t)(off + j) * NS + n0 + n] = Hsm[j * SPAD + n];
    }
}

// ---------------- kernel 3: MLP heads --------------------------------------
template <int IN, int OUT, bool RELU>
__device__ __forceinline__ void athx_layer(const float* __restrict__ A,
                                           const float* __restrict__ wt,
                                           const float* __restrict__ bs,
                                           float* __restrict__ Bout,
                                           int gx, int sx) {
    constexpr int R = OUT / 16;
    float acc[8][R];
    #pragma unroll
    for (int s = 0; s < 8; ++s)
        #pragma unroll
        for (int r = 0; r < R; ++r) acc[s][r] = 0.0f;
    for (int k = 0; k < IN; ++k) {
        float4 a0 = *(const float4*)(A + k * SPAD + sx * 8);
        float4 a1 = *(const float4*)(A + k * SPAD + sx * 8 + 4);
        float av[8] = {a0.x, a0.y, a0.z, a0.w, a1.x, a1.y, a1.z, a1.w};
        #pragma unroll
        for (int r = 0; r < R; ++r) {
            float b = wt[k * OUT + gx + 16 * r];
            #pragma unroll
            for (int s = 0; s < 8; ++s) acc[s][r] = fmaf(av[s], b, acc[s][r]);
        }
    }
    #pragma unroll
    for (int r = 0; r < R; ++r) {
        int u = gx + 16 * r;
        float bb = bs[u];
        float hv[8];
        #pragma unroll
        for (int s = 0; s < 8; ++s) {
            float v = acc[s][r] + bb;
            hv[s] = RELU ? fmaxf(v, 0.0f) : v;
        }
        *(float4*)(Bout + u * SPAD + sx * 8)     = make_float4(hv[0], hv[1], hv[2], hv[3]);
        *(float4*)(Bout + u * SPAD + sx * 8 + 4) = make_float4(hv[4], hv[5], hv[6], hv[7]);
    }
}

__global__ __launch_bounds__(256, 1) void athx_head_kernel(
    const float* __restrict__ fW1, const float* __restrict__ fb1,
    const float* __restrict__ fW2, const float* __restrict__ fb2,
    const float* __restrict__ fW3, const float* __restrict__ fb3,
    const float* __restrict__ oW1, const float* __restrict__ ob1,
    const float* __restrict__ oW2, const float* __restrict__ ob2,
    const float* __restrict__ oW3, const float* __restrict__ ob3,
    float* __restrict__ out)
{
    extern __shared__ float sm[];
    float* A   = sm;                 // [128][SPAD] feat (reused as act2 [64][SPAD])
    float* B   = A + 128 * SPAD;     // [96][SPAD] act1
    float* w1t = B + 96 * SPAD;      // [128][96]
    float* w2t = w1t + 128 * 96;     // [96][64]
    float* w3t = w2t + 96 * 64;      // [64][48]
    float* bs1 = w3t + 64 * 48;      // 96
    float* bs2 = bs1 + 96;           // 64
    float* bs3 = bs2 + 64;           // 48

    const int head = blockIdx.y;
    const float* W1 = head ? oW1 : fW1; const float* b1 = head ? ob1 : fb1;
    const float* W2 = head ? oW2 : fW2; const float* b2 = head ? ob2 : fb2;
    const float* W3 = head ? oW3 : fW3; const float* b3 = head ? ob3 : fb3;
    const int n0  = blockIdx.x * 128;
    const int tid = threadIdx.x;
    const int gx  = tid & 15, sx = tid >> 4;

    for (int idx = tid; idx < 128 * 128; idx += 256) {
        int k = idx >> 7, s = idx & 127;
        A[k * SPAD + s] = g_featT[(size_t)k * NS + n0 + s];
    }
    for (int idx = tid; idx < 96 * 128; idx += 256) {
        int u = idx >> 7, k = idx & 127;
        w1t[k * 96 + u] = W1[idx];
    }
    for (int idx = tid; idx < 64 * 96; idx += 256) {
        int u = idx / 96, k = idx - u * 96;
        w2t[k * 64 + u] = W2[idx];
    }
    for (int idx = tid; idx < 48 * 64; idx += 256) {
        int u = idx >> 6, k = idx & 63;
        w3t[k * 48 + u] = W3[idx];
    }
    if (tid < 96) bs1[tid] = b1[tid];
    if (tid < 64) bs2[tid] = b2[tid];
    if (tid < 48) bs3[tid] = b3[tid];
    __syncthreads();

    athx_layer<128, 96, true>(A, w1t, bs1, B, gx, sx);
    __syncthreads();
    athx_layer<96, 64, true>(B, w2t, bs2, A, gx, sx);   // act2 overwrites feat
    __syncthreads();

    // layer 3: [64] -> 48, no relu, write global
    {
        float acc[8][3];
        #pragma unroll
        for (int s = 0; s < 8; ++s)
            #pragma unroll
            for (int r = 0; r < 3; ++r) acc[s][r] = 0.0f;
        for (int k = 0; k < 64; ++k) {
            float4 a0 = *(const float4*)(A + k * SPAD + sx * 8);
            float4 a1 = *(const float4*)(A + k * SPAD + sx * 8 + 4);
            float av[8] = {a0.x, a0.y, a0.z, a0.w, a1.x, a1.y, a1.z, a1.w};
            #pragma unroll
            for (int r = 0; r < 3; ++r) {
                float b = w3t[k * 48 + gx + 16 * r];
                #pragma unroll
                for (int s = 0; s < 8; ++s) acc[s][r] = fmaf(av[s], b, acc[s][r]);
            }
        }
        #pragma unroll
        for (int r = 0; r < 3; ++r) {
            int u = gx + 16 * r;
            float bb = bs3[u];
            #pragma unroll
            for (int s = 0; s < 8; ++s) {
                int n = n0 + sx * 8 + s;
                out[(size_t)n * 96 + head * 48 + u] = acc[s][r] + bb;
            }
        }
    }
}

// ---------------- launch ----------------------------------------------------
extern "C" void kernel_launch(void* const* d_in, const int* in_sizes, int n_in,
                              void* d_out, int out_size) {
    const float* X_obs  = (const float*)d_in[0];
    const float* X_wrf  = (const float*)d_in[1];
    const float* oWih   = (const float*)d_in[2];
    const float* oWhh   = (const float*)d_in[3];
    const float* obih   = (const float*)d_in[4];
    const float* obhh   = (const float*)d_in[5];
    const float* wWih   = (const float*)d_in[6];
    const float* wWhh   = (const float*)d_in[7];
    const float* wbih   = (const float*)d_in[8];
    const float* wbhh   = (const float*)d_in[9];
    const float* fW1 = (const float*)d_in[10]; const float* fb1 = (const float*)d_in[11];
    const float* fW2 = (const float*)d_in[12]; const float* fb2 = (const float*)d_in[13];
    const float* fW3 = (const float*)d_in[14]; const float* fb3 = (const float*)d_in[15];
    const float* oW1 = (const float*)d_in[16]; const float* ob1 = (const float*)d_in[17];
    const float* oW2 = (const float*)d_in[18]; const float* ob2 = (const float*)d_in[19];
    const float* oW3 = (const float*)d_in[20]; const float* ob3 = (const float*)d_in[21];
    float* out = (float*)d_out;

    const int LSTM_SMEM = (120 * GG + HH * SPAD + 2 * 56 * SPAD) * 4;   // 215808 B
    const int HEAD_SMEM = (128 * SPAD + 96 * SPAD + 128 * 96 + 96 * 64 + 64 * 48
                           + 96 + 64 + 48) * 4;                         // 205120 B
    cudaFuncSetAttribute(athx_lstm_kernel, cudaFuncAttributeMaxDynamicSharedMemorySize, LSTM_SMEM);
    cudaFuncSetAttribute(athx_head_kernel, cudaFuncAttributeMaxDynamicSharedMemorySize, HEAD_SMEM);

    // 1) transpose inputs to [T][C][N]
    athx_transpose_kernel<<<dim3(NS / 32, 3, 32), dim3(32, 8)>>>(X_obs, 32, 0);
    athx_transpose_kernel<<<dim3(NS / 32, 3, 56), dim3(32, 8)>>>(X_wrf, 56, 1);

    // 2) both LSTMs concurrently in one launch
    athx_lstm_kernel<<<128, 256, LSTM_SMEM>>>(oWih, oWhh, obih, obhh,
                                              wWih, wWhh, wbih, wbhh);

    // 3) heads
    athx_head_kernel<<<dim3(NS / 128, 2), 256, HEAD_SMEM>>>(
        fW1, fb1, fW2, fb2, fW3, fb3,
        oW1, ob1, oW2, ob2, oW3, ob3, out);
}

// round 2
// speedup vs baseline: 1.0064x; 1.0064x over previous
#include <cuda_runtime.h>
#include <cstdint>

#define NS   8192
#define TSTEPS 72
#define HH   64
#define GG   256      // 4*H gates
#define SPAD 132      // padded sample stride in smem

typedef unsigned long long u64;

// ---------------- scratch (device globals; no allocation allowed) ----------
__device__ float g_xt_obs[TSTEPS * 32 * NS];   // [T][C1][N]
__device__ float g_xt_wrf[TSTEPS * 56 * NS];   // [T][C2][N]
__device__ float g_featT[128 * NS];            // [128][N]

// ---------------- helpers --------------------------------------------------
__device__ __forceinline__ float sigm_f(float x) {
    return __fdividef(1.0f, 1.0f + __expf(-x));
}
__device__ __forceinline__ float tanh_f(float x) {
    return __fdividef(2.0f, 1.0f + __expf(-2.0f * x)) - 1.0f;
}
__device__ __forceinline__ u64 pack2(float x, float y) {
    u64 r; asm("mov.b64 %0, {%1,%2};" : "=l"(r) : "f"(x), "f"(y)); return r;
}
__device__ __forceinline__ u64 dup2(float x) {
    u64 r; asm("mov.b64 %0, {%1,%1};" : "=l"(r) : "f"(x)); return r;
}
__device__ __forceinline__ void unpack2(u64 v, float& x, float& y) {
    asm("mov.b64 {%0,%1}, %2;" : "=f"(x), "=f"(y) : "l"(v));
}
__device__ __forceinline__ u64 ffma2(u64 a, u64 b, u64 c) {
    u64 d; asm("fma.rn.f32x2 %0, %1, %2, %3;" : "=l"(d) : "l"(a), "l"(b), "l"(c)); return d;
}
__device__ __forceinline__ void cp_async16(float* dst, const float* src) {
    unsigned sa = (unsigned)__cvta_generic_to_shared(dst);
    asm volatile("cp.async.ca.shared.global [%0], [%1], 16;\n" :: "r"(sa), "l"(src));
}
__device__ __forceinline__ void cp_commit()   { asm volatile("cp.async.commit_group;\n"); }
__device__ __forceinline__ void cp_wait_all() { asm volatile("cp.async.wait_all;\n"); }

// ---------------- kernel 1: transpose [N][C][T] -> [T][C][N] ----------------
__global__ void athx_transpose_kernel(const float* __restrict__ in, int C, int which) {
    __shared__ float tile[32][33];
    float* out = which ? g_xt_wrf : g_xt_obs;
    const int c  = blockIdx.z;
    const int n0 = blockIdx.x * 32;
    const int t0 = blockIdx.y * 32;
    const int tx = threadIdx.x, ty = threadIdx.y;
    #pragma unroll
    for (int r = 0; r < 4; ++r) {
        int n = n0 + ty + r * 8;
        int t = t0 + tx;
        if (t < TSTEPS)
            tile[ty + r * 8][tx] = in[((size_t)n * C + c) * TSTEPS + t];
    }
    __syncthreads();
    #pragma unroll
    for (int r = 0; r < 4; ++r) {
        int t = t0 + ty + r * 8;
        int n = n0 + tx;
        if (t < TSTEPS)
            out[((size_t)t * C + c) * NS + n] = tile[tx][ty + r * 8];
    }
}

// ---------------- kernel 2: fused dual-LSTM, f32x2-packed GEMM --------------
// grid 128 CTAs: blocks 0..63 -> obs, 64..127 -> wrf, 128 samples each.
// Gate columns packed in pairs: acc2[s][jp] = gates (2jp, 2jp+1) of sample s.
__global__ __launch_bounds__(256, 1) void athx_lstm_kernel(
    const float* __restrict__ oWih, const float* __restrict__ oWhh,
    const float* __restrict__ obih, const float* __restrict__ obhh,
    const float* __restrict__ wWih, const float* __restrict__ wWhh,
    const float* __restrict__ wbih, const float* __restrict__ wbhh)
{
    extern __shared__ float sm[];
    const bool wrf = (blockIdx.x >= 64);
    const int  C   = wrf ? 56 : 32;
    const int  K   = C + HH;
    const float* xt  = wrf ? g_xt_wrf : g_xt_obs;
    const float* Wih = wrf ? wWih : oWih;
    const float* Whh = wrf ? wWhh : oWhh;
    const float* bih = wrf ? wbih : obih;
    const float* bhh = wrf ? wbhh : obhh;
    const int n0  = (blockIdx.x & 63) * 128;
    const int tid = threadIdx.x;
    const int gx  = tid & 15;      // gate-column group (4 cols per gate type)
    const int sx  = tid >> 4;      // sample group (8 samples)

    float* Wsm = sm;                   // [K][256]   fused [Wih|Whh]^T
    float* Hsm = sm + K * GG;          // [64][SPAD] h, k-major
    float* Xsm = Hsm + HH * SPAD;      // [2][C][SPAD] double-buffered x_t

    for (int idx = tid; idx < GG * C; idx += 256) {
        int g = idx / C, c = idx - g * C;
        Wsm[c * GG + g] = Wih[idx];
    }
    for (int idx = tid; idx < GG * HH; idx += 256) {
        int g = idx >> 6, k = idx & 63;
        Wsm[(C + k) * GG + g] = Whh[idx];
    }
    for (int idx = tid; idx < HH * SPAD; idx += 256) Hsm[idx] = 0.0f;

    // combined bias, packed in gate-column pairs (pairs never cross gate type)
    u64 bia2[8];
    #pragma unroll
    for (int jp = 0; jp < 8; ++jp) {
        int q  = jp >> 1;            // gate type
        int jj = (jp & 1) * 2;       // column-within-group (even)
        int col0 = q * 64 + gx * 4 + jj;
        bia2[jp] = pack2(bih[col0] + bhh[col0], bih[col0 + 1] + bhh[col0 + 1]);
    }

    float creg[8][4];
    #pragma unroll
    for (int s = 0; s < 8; ++s)
        #pragma unroll
        for (int jj = 0; jj < 4; ++jj) creg[s][jj] = 0.0f;

    // prefetch x tile for t = 0
    for (int idx = tid; idx < C * 32; idx += 256) {
        int c = idx >> 5, v = idx & 31;
        cp_async16(&Xsm[c * SPAD + v * 4], xt + ((size_t)c) * NS + n0 + v * 4);
    }
    cp_commit();

    for (int t = 0; t < TSTEPS; ++t) {
        const int cur = t & 1;
        cp_wait_all();
        __syncthreads();   // x[cur] ready; Hsm writes from t-1 visible

        if (t + 1 < TSTEPS) {
            float* xdst = Xsm + (cur ^ 1) * C * SPAD;
            for (int idx = tid; idx < C * 32; idx += 256) {
                int c = idx >> 5, v = idx & 31;
                cp_async16(xdst + c * SPAD + v * 4,
                           xt + ((size_t)(t + 1) * C + c) * NS + n0 + v * 4);
            }
            cp_commit();
        }

        u64 acc2[8][8];
        #pragma unroll
        for (int s = 0; s < 8; ++s)
            #pragma unroll
            for (int jp = 0; jp < 8; ++jp) acc2[s][jp] = bia2[jp];

        // ---- x-projection: k over C channels ----
        const float* Xc = Xsm + cur * C * SPAD;
        #pragma unroll 2
        for (int k = 0; k < C; ++k) {
            float4 a0 = *(const float4*)(Xc + k * SPAD + sx * 8);
            float4 a1 = *(const float4*)(Xc + k * SPAD + sx * 8 + 4);
            u64 ad[8] = {dup2(a0.x), dup2(a0.y), dup2(a0.z), dup2(a0.w),
                         dup2(a1.x), dup2(a1.y), dup2(a1.z), dup2(a1.w)};
            const ulonglong2* brp = (const ulonglong2*)(Wsm + k * GG + gx * 4);
            ulonglong2 q0 = brp[0];
            ulonglong2 q1 = brp[16];
            ulonglong2 q2 = brp[32];
            ulonglong2 q3 = brp[48];
            u64 bd[8] = {q0.x, q0.y, q1.x, q1.y, q2.x, q2.y, q3.x, q3.y};
            #pragma unroll
            for (int s = 0; s < 8; ++s)
                #pragma unroll
                for (int jp = 0; jp < 8; ++jp)
                    acc2[s][jp] = ffma2(ad[s], bd[jp], acc2[s][jp]);
        }
        // ---- recurrent part: k over 64 h-dims ----
        #pragma unroll 2
        for (int k = 0; k < HH; ++k) {
            float4 a0 = *(const float4*)(Hsm + k * SPAD + sx * 8);
            float4 a1 = *(const float4*)(Hsm + k * SPAD + sx * 8 + 4);
            u64 ad[8] = {dup2(a0.x), dup2(a0.y), dup2(a0.z), dup2(a0.w),
                         dup2(a1.x), dup2(a1.y), dup2(a1.z), dup2(a1.w)};
            const ulonglong2* brp = (const ulonglong2*)(Wsm + (C + k) * GG + gx * 4);
            ulonglong2 q0 = brp[0];
            ulonglong2 q1 = brp[16];
            ulonglong2 q2 = brp[32];
            ulonglong2 q3 = brp[48];
            u64 bd[8] = {q0.x, q0.y, q1.x, q1.y, q2.x, q2.y, q3.x, q3.y};
            #pragma unroll
            for (int s = 0; s < 8; ++s)
                #pragma unroll
                for (int jp = 0; jp < 8; ++jp)
                    acc2[s][jp] = ffma2(ad[s], bd[jp], acc2[s][jp]);
        }

        __syncthreads();   // all reads of Hsm done before overwriting

        // gate nonlinearities + state update, two gate-columns (one pair) at a time
        #pragma unroll
        for (int jjp = 0; jjp < 2; ++jjp) {      // covers jj = 2*jjp, 2*jjp+1
            float hv0[8], hv1[8];
            #pragma unroll
            for (int s = 0; s < 8; ++s) {
                float gi0, gi1, gf0, gf1, gg0, gg1, go0, go1;
                unpack2(acc2[s][0 * 2 + jjp], gi0, gi1);   // q=0 (i)
                unpack2(acc2[s][1 * 2 + jjp], gf0, gf1);   // q=1 (f)
                unpack2(acc2[s][2 * 2 + jjp], gg0, gg1);   // q=2 (g)
                unpack2(acc2[s][3 * 2 + jjp], go0, go1);   // q=3 (o)
                int jj0 = jjp * 2, jj1 = jjp * 2 + 1;
                float c0 = fmaf(sigm_f(gf0), creg[s][jj0], sigm_f(gi0) * tanh_f(gg0));
                float c1 = fmaf(sigm_f(gf1), creg[s][jj1], sigm_f(gi1) * tanh_f(gg1));
                creg[s][jj0] = c0;
                creg[s][jj1] = c1;
                hv0[s] = sigm_f(go0) * tanh_f(c0);
                hv1[s] = sigm_f(go1) * tanh_f(c1);
            }
            float* hrow0 = Hsm + (gx * 4 + jjp * 2) * SPAD + sx * 8;
            float* hrow1 = hrow0 + SPAD;
            *(float4*)(hrow0)     = make_float4(hv0[0], hv0[1], hv0[2], hv0[3]);
            *(float4*)(hrow0 + 4) = make_float4(hv0[4], hv0[5], hv0[6], hv0[7]);
            *(float4*)(hrow1)     = make_float4(hv1[0], hv1[1], hv1[2], hv1[3]);
            *(float4*)(hrow1 + 4) = make_float4(hv1[4], hv1[5], hv1[6], hv1[7]);
        }
    }

    __syncthreads();
    const int off = wrf ? 64 : 0;
    for (int idx = tid; idx < HH * 128; idx += 256) {
        int j = idx >> 7, n = idx & 127;
        g_featT[(size_t)(off + j) * NS + n0 + n] = Hsm[j * SPAD + n];
    }
}

// ---------------- kernel 3: MLP heads (f32x2-packed over sample pairs) ------
template <int IN, int OUT, bool RELU>
__device__ __forceinline__ void athx_layer(const float* __restrict__ A,
                                           const float* __restrict__ wt,
                                           const float* __restrict__ bs,
                                           float* __restrict__ Bout,
                                           int gx, int sx) {
    constexpr int R = OUT / 16;
    u64 acc2[4][R];
    #pragma unroll
    for (int sp = 0; sp < 4; ++sp)
        #pragma unroll
        for (int r = 0; r < R; ++r) acc2[sp][r] = 0ull;
    for (int k = 0; k < IN; ++k) {
        ulonglong2 p0 = *(const ulonglong2*)(A + k * SPAD + sx * 8);
        ulonglong2 p1 = *(const ulonglong2*)(A + k * SPAD + sx * 8 + 4);
        u64 a2[4] = {p0.x, p0.y, p1.x, p1.y};
        #pragma unroll
        for (int r = 0; r < R; ++r) {
            u64 b2 = dup2(wt[k * OUT + gx + 16 * r]);
            #pragma unroll
            for (int sp = 0; sp < 4; ++sp) acc2[sp][r] = ffma2(a2[sp], b2, acc2[sp][r]);
        }
    }
    #pragma unroll
    for (int r = 0; r < R; ++r) {
        int u = gx + 16 * r;
        float bb = bs[u];
        float hv[8];
        #pragma unroll
        for (int sp = 0; sp < 4; ++sp) {
            float v0, v1;
            unpack2(acc2[sp][r], v0, v1);
            v0 += bb; v1 += bb;
            hv[2 * sp]     = RELU ? fmaxf(v0, 0.0f) : v0;
            hv[2 * sp + 1] = RELU ? fmaxf(v1, 0.0f) : v1;
        }
        *(float4*)(Bout + u * SPAD + sx * 8)     = make_float4(hv[0], hv[1], hv[2], hv[3]);
        *(float4*)(Bout + u * SPAD + sx * 8 + 4) = make_float4(hv[4], hv[5], hv[6], hv[7]);
    }
}

__global__ __launch_bounds__(256, 1) void athx_head_kernel(
    const float* __restrict__ fW1, const float* __restrict__ fb1,
    const float* __restrict__ fW2, const float* __restrict__ fb2,
    const float* __restrict__ fW3, const float* __restrict__ fb3,
    const float* __restrict__ oW1, const float* __restrict__ ob1,
    const float* __restrict__ oW2, const float* __restrict__ ob2,
    const float* __restrict__ oW3, const float* __restrict__ ob3,
    float* __restrict__ out)
{
    extern __shared__ float sm[];
    float* A   = sm;                 // [128][SPAD] feat (reused as act2)
    float* B   = A + 128 * SPAD;     // [96][SPAD] act1
    float* w1t = B + 96 * SPAD;      // [128][96]
    float* w2t = w1t + 128 * 96;     // [96][64]
    float* w3t = w2t + 96 * 64;      // [64][48]
    float* bs1 = w3t + 64 * 48;      // 96
    float* bs2 = bs1 + 96;           // 64
    float* bs3 = bs2 + 64;           // 48

    const int head = blockIdx.y;
    const float* W1 = head ? oW1 : fW1; const float* b1 = head ? ob1 : fb1;
    const float* W2 = head ? oW2 : fW2; const float* b2 = head ? ob2 : fb2;
    const float* W3 = head ? oW3 : fW3; const float* b3 = head ? ob3 : fb3;
    const int n0  = blockIdx.x * 128;
    const int tid = threadIdx.x;
    const int gx  = tid & 15, sx = tid >> 4;

    for (int idx = tid; idx < 128 * 128; idx += 256) {
        int k = idx >> 7, s = idx & 127;
        A[k * SPAD + s] = g_featT[(size_t)k * NS + n0 + s];
    }
    for (int idx = tid; idx < 96 * 128; idx += 256) {
        int u = idx >> 7, k = idx & 127;
        w1t[k * 96 + u] = W1[idx];
    }
    for (int idx = tid; idx < 64 * 96; idx += 256) {
        int u = idx / 96, k = idx - u * 96;
        w2t[k * 64 + u] = W2[idx];
    }
    for (int idx = tid; idx < 48 * 64; idx += 256) {
        int u = idx >> 6, k = idx & 63;
        w3t[k * 48 + u] = W3[idx];
    }
    if (tid < 96) bs1[tid] = b1[tid];
    if (tid < 64) bs2[tid] = b2[tid];
    if (tid < 48) bs3[tid] = b3[tid];
    __syncthreads();

    athx_layer<128, 96, true>(A, w1t, bs1, B, gx, sx);
    __syncthreads();
    athx_layer<96, 64, true>(B, w2t, bs2, A, gx, sx);
    __syncthreads();

    // layer 3: [64] -> 48, no relu, write global
    {
        u64 acc2[4][3];
        #pragma unroll
        for (int sp = 0; sp < 4; ++sp)
            #pragma unroll
            for (int r = 0; r < 3; ++r) acc2[sp][r] = 0ull;
        for (int k = 0; k < 64; ++k) {
            ulonglong2 p0 = *(const ulonglong2*)(A + k * SPAD + sx * 8);
            ulonglong2 p1 = *(const ulonglong2*)(A + k * SPAD + sx * 8 + 4);
            u64 a2[4] = {p0.x, p0.y, p1.x, p1.y};
            #pragma unroll
            for (int r = 0; r < 3; ++r) {
                u64 b2 = dup2(w3t[k * 48 + gx + 16 * r]);
                #pragma unroll
                for (int sp = 0; sp < 4; ++sp) acc2[sp][r] = ffma2(a2[sp], b2, acc2[sp][r]);
            }
        }
        #pragma unroll
        for (int r = 0; r < 3; ++r) {
            int u = gx + 16 * r;
            float bb = bs3[u];
            #pragma unroll
            for (int sp = 0; sp < 4; ++sp) {
                float v0, v1;
                unpack2(acc2[sp][r], v0, v1);
                int n = n0 + sx * 8 + 2 * sp;
                out[(size_t)n * 96 + head * 48 + u]       = v0 + bb;
                out[(size_t)(n + 1) * 96 + head * 48 + u] = v1 + bb;
            }
        }
    }
}

// ---------------- launch ----------------------------------------------------
extern "C" void kernel_launch(void* const* d_in, const int* in_sizes, int n_in,
                              void* d_out, int out_size) {
    const float* X_obs  = (const float*)d_in[0];
    const float* X_wrf  = (const float*)d_in[1];
    const float* oWih   = (const float*)d_in[2];
    const float* oWhh   = (const float*)d_in[3];
    const float* obih   = (const float*)d_in[4];
    const float* obhh   = (const float*)d_in[5];
    const float* wWih   = (const float*)d_in[6];
    const float* wWhh   = (const float*)d_in[7];
    const float* wbih   = (const float*)d_in[8];
    const float* wbhh   = (const float*)d_in[9];
    const float* fW1 = (const float*)d_in[10]; const float* fb1 = (const float*)d_in[11];
    const float* fW2 = (const float*)d_in[12]; const float* fb2 = (const float*)d_in[13];
    const float* fW3 = (const float*)d_in[14]; const float* fb3 = (const float*)d_in[15];
    const float* oW1 = (const float*)d_in[16]; const float* ob1 = (const float*)d_in[17];
    const float* oW2 = (const float*)d_in[18]; const float* ob2 = (const float*)d_in[19];
    const float* oW3 = (const float*)d_in[20]; const float* ob3 = (const float*)d_in[21];
    float* out = (float*)d_out;

    const int LSTM_SMEM = (120 * GG + HH * SPAD + 2 * 56 * SPAD) * 4;
    const int HEAD_SMEM = (128 * SPAD + 96 * SPAD + 128 * 96 + 96 * 64 + 64 * 48
                           + 96 + 64 + 48) * 4;
    cudaFuncSetAttribute(athx_lstm_kernel, cudaFuncAttributeMaxDynamicSharedMemorySize, LSTM_SMEM);
    cudaFuncSetAttribute(athx_head_kernel, cudaFuncAttributeMaxDynamicSharedMemorySize, HEAD_SMEM);

    athx_transpose_kernel<<<dim3(NS / 32, 3, 32), dim3(32, 8)>>>(X_obs, 32, 0);
    athx_transpose_kernel<<<dim3(NS / 32, 3, 56), dim3(32, 8)>>>(X_wrf, 56, 1);

    athx_lstm_kernel<<<128, 256, LSTM_SMEM>>>(oWih, oWhh, obih, obhh,
                                              wWih, wWhh, wbih, wbhh);

    athx_head_kernel<<<dim3(NS / 128, 2), 256, HEAD_SMEM>>>(
        fW1, fb1, fW2, fb2, fW3, fb3,
        oW1, ob1, oW2, ob2, oW3, ob3, out);
}

// round 4
// speedup vs baseline: 1.4882x; 1.4788x over previous
#include <cuda_runtime.h>
#include <cuda_bf16.h>
#include <cstdint>

#define NS     8192
#define TSTEPS 72

typedef unsigned long long u64;
typedef unsigned int       u32;

// ---------------- scratch (device globals; no allocation allowed) ----------
__device__ u32   g_xt_obs[TSTEPS * 32 * NS];   // [T][C1][N] packed bf16 hi|lo
__device__ u32   g_xt_wrf[TSTEPS * 56 * NS];   // [T][C2][N] packed bf16 hi|lo
__device__ float g_featT[128 * NS];            // [128][N]

// ---------------- smem layout (bytes) for LSTM kernel ----------------------
// A: 128 rows x 128 bf16 cols (256B/row), hi + lo.  B: 256 rows x 128 cols.
#define SM_AHI    0
#define SM_ALO    32768
#define SM_BHI    65536
#define SM_BLO    131072
#define SM_STAGE  196608                      // u32 stage[C][128] (<=28672)
#define SM_TOTAL  225280

// ---------------- math helpers ---------------------------------------------
__device__ __forceinline__ float sigm_f(float x) {
    return __fdividef(1.0f, 1.0f + __expf(-x));
}
__device__ __forceinline__ float tanh_f(float x) {
    return __fdividef(2.0f, 1.0f + __expf(-2.0f * x)) - 1.0f;
}
__device__ __forceinline__ void split_bf16(float v, unsigned short& hi, unsigned short& lo) {
    u32 u = __float_as_uint(v);
    hi = (unsigned short)(u >> 16);
    float r = v - __uint_as_float(u & 0xFFFF0000u);
    __nv_bfloat16 b = __float2bfloat16_rn(r);
    lo = *reinterpret_cast<unsigned short*>(&b);
}
__device__ __forceinline__ u32 pack_split(float v) {
    unsigned short hi, lo; split_bf16(v, hi, lo);
    return ((u32)hi << 16) | (u32)lo;
}

// ---------------- PTX helpers -----------------------------------------------
__device__ __forceinline__ u32 smem_u32(const void* p) {
    u32 a;
    asm("{ .reg .u64 t; cvta.to.shared.u64 t, %1; cvt.u32.u64 %0, t; }" : "=r"(a) : "l"(p));
    return a;
}
__device__ __forceinline__ void cp_async16(char* smem_dst, const void* gsrc) {
    u32 sa = smem_u32(smem_dst);
    asm volatile("cp.async.ca.shared.global [%0], [%1], 16;\n" :: "r"(sa), "l"(gsrc));
}
__device__ __forceinline__ void cp_commit()   { asm volatile("cp.async.commit_group;\n"); }
__device__ __forceinline__ void cp_wait_all() { asm volatile("cp.async.wait_all;\n"); }

__device__ __forceinline__ void ldsm4(u32& r0, u32& r1, u32& r2, u32& r3, u32 addr) {
    asm volatile("ldmatrix.sync.aligned.m8n8.x4.shared.b16 {%0,%1,%2,%3}, [%4];"
                 : "=r"(r0), "=r"(r1), "=r"(r2), "=r"(r3) : "r"(addr));
}
__device__ __forceinline__ void mma_bf16(float& d0, float& d1, float& d2, float& d3,
                                         u32 a0, u32 a1, u32 a2, u32 a3,
                                         u32 b0, u32 b1) {
    asm volatile("mma.sync.aligned.m16n8k16.row.col.f32.bf16.bf16.f32 "
                 "{%0,%1,%2,%3}, {%4,%5,%6,%7}, {%8,%9}, {%0,%1,%2,%3};"
                 : "+f"(d0), "+f"(d1), "+f"(d2), "+f"(d3)
                 : "r"(a0), "r"(a1), "r"(a2), "r"(a3), "r"(b0), "r"(b1));
}

// XOR-swizzled byte offset: row stride 256B, 16B chunk index ^= (row&7)
__device__ __forceinline__ u32 swz(u32 row, u32 chunk) {
    return row * 256u + ((chunk ^ (row & 7u)) << 4);
}

// B row permutation: gate-quad-aligned fragment ownership
__device__ __forceinline__ int brow(int g) {
    int q = g >> 6, j = g & 63;
    int warpN = j >> 4, jl = j & 15;
    int hi = jl >> 3, a = (jl & 7) >> 1, e = jl & 1;
    return warpN * 64 + 8 * (q + 4 * hi) + 2 * a + e;
}

// ---------------- kernel 1: transpose+split [N][C][T] -> [T][C][N] u32 ------
__global__ void athx_transpose_kernel(const float* __restrict__ in, int C, int which) {
    __shared__ float tile[32][33];
    u32* out = which ? g_xt_wrf : g_xt_obs;
    const int c  = blockIdx.z;
    const int n0 = blockIdx.x * 32;
    const int t0 = blockIdx.y * 32;
    const int tx = threadIdx.x, ty = threadIdx.y;
    #pragma unroll
    for (int r = 0; r < 4; ++r) {
        int n = n0 + ty + r * 8;
        int t = t0 + tx;
        if (t < TSTEPS)
            tile[ty + r * 8][tx] = in[((size_t)n * C + c) * TSTEPS + t];
    }
    __syncthreads();
    #pragma unroll
    for (int r = 0; r < 4; ++r) {
        int t = t0 + ty + r * 8;
        int n = n0 + tx;
        if (t < TSTEPS)
            out[((size_t)t * C + c) * NS + n] = pack_split(tile[tx][ty + r * 8]);
    }
}

// ---------------- kernel 2: HMMA dual-LSTM ----------------------------------
// 128 CTAs x 512 thr: blocks 0..63 obs (C=32), 64..127 wrf (C=56); 128 samples.
// A[s][k]: [ h(0..63) | x(64..64+C-1) | 1.0 bias col | 0 pad ]  bf16 hi+lo
// B[p][k]: permuted gate rows, same k layout; D = 3-product bf16 split.
__global__ __launch_bounds__(512, 1)
void athx_lstm_mma(const float* __restrict__ oWih, const float* __restrict__ oWhh,
                   const float* __restrict__ obih, const float* __restrict__ obhh,
                   const float* __restrict__ wWih, const float* __restrict__ wWhh,
                   const float* __restrict__ wbih, const float* __restrict__ wbhh)
{
    extern __shared__ char smem[];
    const bool wrf = (blockIdx.x >= 64);
    const int  C      = wrf ? 56 : 32;
    const int  KSTEPS = wrf ? 8 : 7;
    const int  BCOL   = 64 + C;
    const u32* xt = wrf ? g_xt_wrf : g_xt_obs;
    const float* Wih = wrf ? wWih : oWih;
    const float* Whh = wrf ? wWhh : oWhh;
    const float* bih = wrf ? wbih : obih;
    const float* bhh = wrf ? wbhh : obhh;
    const int n0  = (blockIdx.x & 63) * 128;
    const int tid = threadIdx.x;
    const int wid = tid >> 5;
    const int lane = tid & 31;
    const int warpM = wid >> 2;
    const int warpN = wid & 3;

    const u32 smb = smem_u32(smem);
    u32* stage = (u32*)(smem + SM_STAGE);

    // ---- prefetch x_0 (staging region disjoint from zero region) ----
    const int NCHUNK = C * 32;
    for (int i = tid; i < NCHUNK; i += 512) {
        int ch = i >> 5, v = i & 31;
        cp_async16(smem + SM_STAGE + (ch * 128 + v * 4) * 4,
                   xt + (size_t)ch * NS + n0 + v * 4);
    }
    cp_commit();

    // ---- zero A+B (hi & lo), contiguous [0, 196608) ----
    for (int i = tid; i < 196608 / 16; i += 512)
        ((uint4*)smem)[i] = make_uint4(0, 0, 0, 0);
    __syncthreads();

    // ---- fill B (permuted rows) ----
    for (int i = tid; i < 256 * 64; i += 512) {      // Whh -> cols 0..63
        int g = i >> 6, k = i & 63;
        unsigned short hi, lo; split_bf16(Whh[i], hi, lo);
        u32 off = swz(brow(g), k >> 3) + (k & 7) * 2;
        *(unsigned short*)(smem + SM_BHI + off) = hi;
        *(unsigned short*)(smem + SM_BLO + off) = lo;
    }
    for (int i = tid; i < 256 * C; i += 512) {       // Wih -> cols 64..
        int g = i / C, ch = i - g * C, k = 64 + ch;
        unsigned short hi, lo; split_bf16(Wih[i], hi, lo);
        u32 off = swz(brow(g), k >> 3) + (k & 7) * 2;
        *(unsigned short*)(smem + SM_BHI + off) = hi;
        *(unsigned short*)(smem + SM_BLO + off) = lo;
    }
    if (tid < 256) {                                 // bias col
        unsigned short hi, lo; split_bf16(bih[tid] + bhh[tid], hi, lo);
        u32 off = swz(brow(tid), BCOL >> 3) + (BCOL & 7) * 2;
        *(unsigned short*)(smem + SM_BHI + off) = hi;
        *(unsigned short*)(smem + SM_BLO + off) = lo;
    }
    if (tid < 128) {                                 // A bias col = 1.0 (hi)
        u32 off = swz(tid, BCOL >> 3) + (BCOL & 7) * 2;
        *(unsigned short*)(smem + SM_AHI + off) = 0x3F80;
    }

    // ---- copy x_0 staging -> A (self-owned data only) ----
    cp_wait_all();
    for (int i = tid; i < NCHUNK; i += 512) {
        int ch = i >> 5, v = i & 31, k = 64 + ch;
        #pragma unroll
        for (int w = 0; w < 4; ++w) {
            u32 p = stage[ch * 128 + v * 4 + w];
            u32 row = v * 4 + w;
            u32 off = swz(row, k >> 3) + (k & 7) * 2;
            *(unsigned short*)(smem + SM_AHI + off) = (unsigned short)(p >> 16);
            *(unsigned short*)(smem + SM_ALO + off) = (unsigned short)(p & 0xFFFF);
        }
    }

    // ---- per-thread ldmatrix geometry ----
    const int g8 = lane >> 3, l = lane & 7;
    const u32 aRow = (u32)(warpM * 32 + (g8 & 1) * 8 + l);
    const u32 bRow = (u32)(warpN * 64 + ((g8 >> 1) & 1) * 8 + l);
    const u32 gAc = (u32)(g8 >> 1);     // A chunk offset
    const u32 gBc = (u32)(g8 & 1);      // B chunk offset
    const u32 aHiB = smb + SM_AHI + aRow * 256;
    const u32 aLoB = smb + SM_ALO + aRow * 256;
    const u32 bHiB = smb + SM_BHI + bRow * 256;
    const u32 bLoB = smb + SM_BLO + bRow * 256;
    const u32 lx = (u32)l;

    float cst[16];
    #pragma unroll
    for (int i = 0; i < 16; ++i) cst[i] = 0.0f;

    for (int t = 0; t < TSTEPS; ++t) {
        __syncthreads();   // A (h_{t-1}, x_t) visible to all warps

        // prefetch x_{t+1}
        if (t + 1 < TSTEPS) {
            const u32* src = xt + (size_t)(t + 1) * C * NS;
            for (int i = tid; i < NCHUNK; i += 512) {
                int ch = i >> 5, v = i & 31;
                cp_async16(smem + SM_STAGE + (ch * 128 + v * 4) * 4,
                           src + (size_t)ch * NS + n0 + v * 4);
            }
            cp_commit();
        }

        float acc[2][8][4];
        #pragma unroll
        for (int mt = 0; mt < 2; ++mt)
            #pragma unroll
            for (int nt = 0; nt < 8; ++nt)
                #pragma unroll
                for (int r = 0; r < 4; ++r) acc[mt][nt][r] = 0.0f;

        for (int ks = 0; ks < KSTEPS; ++ks) {
            u32 ah[8], al[8];
            u32 ca = ((2u * ks + gAc) ^ lx) << 4;
            ldsm4(ah[0], ah[1], ah[2], ah[3], aHiB + ca);
            ldsm4(ah[4], ah[5], ah[6], ah[7], aHiB + 4096 + ca);
            ldsm4(al[0], al[1], al[2], al[3], aLoB + ca);
            ldsm4(al[4], al[5], al[6], al[7], aLoB + 4096 + ca);
            u32 cb = ((2u * ks + gBc) ^ lx) << 4;
            #pragma unroll
            for (int ntp = 0; ntp < 4; ++ntp) {
                u32 b0, b1, b2, b3;
                ldsm4(b0, b1, b2, b3, bHiB + ntp * 4096 + cb);
                #pragma unroll
                for (int mt = 0; mt < 2; ++mt) {
                    mma_bf16(acc[mt][2*ntp][0],   acc[mt][2*ntp][1],   acc[mt][2*ntp][2],   acc[mt][2*ntp][3],
                             ah[4*mt], ah[4*mt+1], ah[4*mt+2], ah[4*mt+3], b0, b1);
                    mma_bf16(acc[mt][2*ntp+1][0], acc[mt][2*ntp+1][1], acc[mt][2*ntp+1][2], acc[mt][2*ntp+1][3],
                             ah[4*mt], ah[4*mt+1], ah[4*mt+2], ah[4*mt+3], b2, b3);
                    mma_bf16(acc[mt][2*ntp][0],   acc[mt][2*ntp][1],   acc[mt][2*ntp][2],   acc[mt][2*ntp][3],
                             al[4*mt], al[4*mt+1], al[4*mt+2], al[4*mt+3], b0, b1);
                    mma_bf16(acc[mt][2*ntp+1][0], acc[mt][2*ntp+1][1], acc[mt][2*ntp+1][2], acc[mt][2*ntp+1][3],
                             al[4*mt], al[4*mt+1], al[4*mt+2], al[4*mt+3], b2, b3);
                }
                ldsm4(b0, b1, b2, b3, bLoB + ntp * 4096 + cb);
                #pragma unroll
                for (int mt = 0; mt < 2; ++mt) {
                    mma_bf16(acc[mt][2*ntp][0],   acc[mt][2*ntp][1],   acc[mt][2*ntp][2],   acc[mt][2*ntp][3],
                             ah[4*mt], ah[4*mt+1], ah[4*mt+2], ah[4*mt+3], b0, b1);
                    mma_bf16(acc[mt][2*ntp+1][0], acc[mt][2*ntp+1][1], acc[mt][2*ntp+1][2], acc[mt][2*ntp+1][3],
                             ah[4*mt], ah[4*mt+1], ah[4*mt+2], ah[4*mt+3], b2, b3);
                }
            }
        }

        // ---- epilogue: gates in registers (i,f,g,o quads per thread) ----
        float hval[16];
        #pragma unroll
        for (int mt = 0; mt < 2; ++mt)
            #pragma unroll
            for (int d = 0; d < 2; ++d)
                #pragma unroll
                for (int h2 = 0; h2 < 2; ++h2)
                    #pragma unroll
                    for (int e = 0; e < 2; ++e) {
                        int r = 2 * d + e;
                        int ci = ((mt * 2 + d) * 2 + h2) * 2 + e;
                        float gi = sigm_f(acc[mt][4*h2 + 0][r]);
                        float gf = sigm_f(acc[mt][4*h2 + 1][r]);
                        float gg = tanh_f(acc[mt][4*h2 + 2][r]);
                        float go = sigm_f(acc[mt][4*h2 + 3][r]);
                        float cc = fmaf(gf, cst[ci], gi * gg);
                        cst[ci] = cc;
                        hval[ci] = go * tanh_f(cc);
                    }

        __syncthreads();   // all warps done reading A this step

        if (t == TSTEPS - 1) {
            const int off = wrf ? 64 : 0;
            #pragma unroll
            for (int mt = 0; mt < 2; ++mt)
                #pragma unroll
                for (int d = 0; d < 2; ++d)
                    #pragma unroll
                    for (int h2 = 0; h2 < 2; ++h2)
                        #pragma unroll
                        for (int e = 0; e < 2; ++e) {
                            int s = warpM * 32 + mt * 16 + (lane >> 2) + 8 * d;
                            int j = warpN * 16 + h2 * 8 + (lane & 3) * 2 + e;
                            int ci = ((mt * 2 + d) * 2 + h2) * 2 + e;
                            g_featT[(size_t)(off + j) * NS + n0 + s] = hval[ci];
                        }
        } else {
            // h -> A cols (bf16 hi/lo, packed j pairs)
            #pragma unroll
            for (int mt = 0; mt < 2; ++mt)
                #pragma unroll
                for (int d = 0; d < 2; ++d)
                    #pragma unroll
                    for (int h2 = 0; h2 < 2; ++h2) {
                        int ci = ((mt * 2 + d) * 2 + h2) * 2;
                        float h0 = hval[ci], h1 = hval[ci + 1];
                        u32 u0 = __float_as_uint(h0), u1 = __float_as_uint(h1);
                        u32 hi32 = (u0 >> 16) | (u1 & 0xFFFF0000u);
                        float r0 = h0 - __uint_as_float(u0 & 0xFFFF0000u);
                        float r1 = h1 - __uint_as_float(u1 & 0xFFFF0000u);
                        __nv_bfloat162 b2 = __floats2bfloat162_rn(r0, r1);
                        u32 lo32 = *reinterpret_cast<u32*>(&b2);
                        u32 s  = (u32)(warpM * 32 + mt * 16 + (lane >> 2) + 8 * d);
                        u32 jp = (u32)(warpN * 16 + h2 * 8 + (lane & 3) * 2);
                        u32 off = swz(s, jp >> 3) + (jp & 7) * 2;
                        *(u32*)(smem + SM_AHI + off) = hi32;
                        *(u32*)(smem + SM_ALO + off) = lo32;
                    }
            // staged x_{t+1} -> A (self-owned chunks)
            cp_wait_all();
            for (int i = tid; i < NCHUNK; i += 512) {
                int ch = i >> 5, v = i & 31, k = 64 + ch;
                #pragma unroll
                for (int w = 0; w < 4; ++w) {
                    u32 p = stage[ch * 128 + v * 4 + w];
                    u32 row = (u32)(v * 4 + w);
                    u32 off = swz(row, (u32)(k >> 3)) + (k & 7) * 2;
                    *(unsigned short*)(smem + SM_AHI + off) = (unsigned short)(p >> 16);
                    *(unsigned short*)(smem + SM_ALO + off) = (unsigned short)(p & 0xFFFF);
                }
            }
        }
    }
}

// ---------------- kernel 3: MLP heads (unchanged, passing since R1) ---------
#define SPAD 132
__device__ __forceinline__ u64 dup2(float x) {
    u64 r; asm("mov.b64 %0, {%1,%1};" : "=l"(r) : "f"(x)); return r;
}
__device__ __forceinline__ void unpack2(u64 v, float& x, float& y) {
    asm("mov.b64 {%0,%1}, %2;" : "=f"(x), "=f"(y) : "l"(v));
}
__device__ __forceinline__ u64 ffma2(u64 a, u64 b, u64 c) {
    u64 d; asm("fma.rn.f32x2 %0, %1, %2, %3;" : "=l"(d) : "l"(a), "l"(b), "l"(c)); return d;
}

template <int IN, int OUT, bool RELU>
__device__ __forceinline__ void athx_layer(const float* __restrict__ A,
                                           const float* __restrict__ wt,
                                           const float* __restrict__ bs,
                                           float* __restrict__ Bout,
                                           int gx, int sx) {
    constexpr int R = OUT / 16;
    u64 acc2[4][R];
    #pragma unroll
    for (int sp = 0; sp < 4; ++sp)
        #pragma unroll
        for (int r = 0; r < R; ++r) acc2[sp][r] = 0ull;
    for (int k = 0; k < IN; ++k) {
        ulonglong2 p0 = *(const ulonglong2*)(A + k * SPAD + sx * 8);
        ulonglong2 p1 = *(const ulonglong2*)(A + k * SPAD + sx * 8 + 4);
        u64 a2[4] = {p0.x, p0.y, p1.x, p1.y};
        #pragma unroll
        for (int r = 0; r < R; ++r) {
            u64 b2 = dup2(wt[k * OUT + gx + 16 * r]);
            #pragma unroll
            for (int sp = 0; sp < 4; ++sp) acc2[sp][r] = ffma2(a2[sp], b2, acc2[sp][r]);
        }
    }
    #pragma unroll
    for (int r = 0; r < R; ++r) {
        int u = gx + 16 * r;
        float bb = bs[u];
        float hv[8];
        #pragma unroll
        for (int sp = 0; sp < 4; ++sp) {
            float v0, v1;
            unpack2(acc2[sp][r], v0, v1);
            v0 += bb; v1 += bb;
            hv[2 * sp]     = RELU ? fmaxf(v0, 0.0f) : v0;
            hv[2 * sp + 1] = RELU ? fmaxf(v1, 0.0f) : v1;
        }
        *(float4*)(Bout + u * SPAD + sx * 8)     = make_float4(hv[0], hv[1], hv[2], hv[3]);
        *(float4*)(Bout + u * SPAD + sx * 8 + 4) = make_float4(hv[4], hv[5], hv[6], hv[7]);
    }
}

__global__ __launch_bounds__(256, 1) void athx_head_kernel(
    const float* __restrict__ fW1, const float* __restrict__ fb1,
    const float* __restrict__ fW2, const float* __restrict__ fb2,
    const float* __restrict__ fW3, const float* __restrict__ fb3,
    const float* __restrict__ oW1, const float* __restrict__ ob1,
    const float* __restrict__ oW2, const float* __restrict__ ob2,
    const float* __restrict__ oW3, const float* __restrict__ ob3,
    float* __restrict__ out)
{
    extern __shared__ float sm[];
    float* A   = sm;
    float* B   = A + 128 * SPAD;
    float* w1t = B + 96 * SPAD;
    float* w2t = w1t + 128 * 96;
    float* w3t = w2t + 96 * 64;
    float* bs1 = w3t + 64 * 48;
    float* bs2 = bs1 + 96;
    float* bs3 = bs2 + 64;

    const int head = blockIdx.y;
    const float* W1 = head ? oW1 : fW1; const float* b1 = head ? ob1 : fb1;
    const float* W2 = head ? oW2 : fW2; const float* b2 = head ? ob2 : fb2;
    const float* W3 = head ? oW3 : fW3; const float* b3 = head ? ob3 : fb3;
    const int n0  = blockIdx.x * 128;
    const int tid = threadIdx.x;
    const int gx  = tid & 15, sx = tid >> 4;

    for (int idx = tid; idx < 128 * 128; idx += 256) {
        int k = idx >> 7, s = idx & 127;
        A[k * SPAD + s] = g_featT[(size_t)k * NS + n0 + s];
    }
    for (int idx = tid; idx < 96 * 128; idx += 256) {
        int u = idx >> 7, k = idx & 127;
        w1t[k * 96 + u] = W1[idx];
    }
    for (int idx = tid; idx < 64 * 96; idx += 256) {
        int u = idx / 96, k = idx - u * 96;
        w2t[k * 64 + u] = W2[idx];
    }
    for (int idx = tid; idx < 48 * 64; idx += 256) {
        int u = idx >> 6, k = idx & 63;
        w3t[k * 48 + u] = W3[idx];
    }
    if (tid < 96) bs1[tid] = b1[tid];
    if (tid < 64) bs2[tid] = b2[tid];
    if (tid < 48) bs3[tid] = b3[tid];
    __syncthreads();

    athx_layer<128, 96, true>(A, w1t, bs1, B, gx, sx);
    __syncthreads();
    athx_layer<96, 64, true>(B, w2t, bs2, A, gx, sx);
    __syncthreads();

    {
        u64 acc2[4][3];
        #pragma unroll
        for (int sp = 0; sp < 4; ++sp)
            #pragma unroll
            for (int r = 0; r < 3; ++r) acc2[sp][r] = 0ull;
        for (int k = 0; k < 64; ++k) {
            ulonglong2 p0 = *(const ulonglong2*)(A + k * SPAD + sx * 8);
            ulonglong2 p1 = *(const ulonglong2*)(A + k * SPAD + sx * 8 + 4);
            u64 a2[4] = {p0.x, p0.y, p1.x, p1.y};
            #pragma unroll
            for (int r = 0; r < 3; ++r) {
                u64 b2 = dup2(w3t[k * 48 + gx + 16 * r]);
                #pragma unroll
                for (int sp = 0; sp < 4; ++sp) acc2[sp][r] = ffma2(a2[sp], b2, acc2[sp][r]);
            }
        }
        #pragma unroll
        for (int r = 0; r < 3; ++r) {
            int u = gx + 16 * r;
            float bb = bs3[u];
            #pragma unroll
            for (int sp = 0; sp < 4; ++sp) {
                float v0, v1;
                unpack2(acc2[sp][r], v0, v1);
                int n = n0 + sx * 8 + 2 * sp;
                out[(size_t)n * 96 + head * 48 + u]       = v0 + bb;
                out[(size_t)(n + 1) * 96 + head * 48 + u] = v1 + bb;
            }
        }
    }
}

// ---------------- launch ----------------------------------------------------
extern "C" void kernel_launch(void* const* d_in, const int* in_sizes, int n_in,
                              void* d_out, int out_size) {
    const float* X_obs  = (const float*)d_in[0];
    const float* X_wrf  = (const float*)d_in[1];
    const float* oWih   = (const float*)d_in[2];
    const float* oWhh   = (const float*)d_in[3];
    const float* obih   = (const float*)d_in[4];
    const float* obhh   = (const float*)d_in[5];
    const float* wWih   = (const float*)d_in[6];
    const float* wWhh   = (const float*)d_in[7];
    const float* wbih   = (const float*)d_in[8];
    const float* wbhh   = (const float*)d_in[9];
    const float* fW1 = (const float*)d_in[10]; const float* fb1 = (const float*)d_in[11];
    const float* fW2 = (const float*)d_in[12]; const float* fb2 = (const float*)d_in[13];
    const float* fW3 = (const float*)d_in[14]; const float* fb3 = (const float*)d_in[15];
    const float* oW1 = (const float*)d_in[16]; const float* ob1 = (const float*)d_in[17];
    const float* oW2 = (const float*)d_in[18]; const float* ob2 = (const float*)d_in[19];
    const float* oW3 = (const float*)d_in[20]; const float* ob3 = (const float*)d_in[21];
    float* out = (float*)d_out;

    const int HEAD_SMEM = (128 * SPAD + 96 * SPAD + 128 * 96 + 96 * 64 + 64 * 48
                           + 96 + 64 + 48) * 4;
    cudaFuncSetAttribute(athx_lstm_mma, cudaFuncAttributeMaxDynamicSharedMemorySize, SM_TOTAL);
    cudaFuncSetAttribute(athx_head_kernel, cudaFuncAttributeMaxDynamicSharedMemorySize, HEAD_SMEM);

    athx_transpose_kernel<<<dim3(NS / 32, 3, 32), dim3(32, 8)>>>(X_obs, 32, 0);
    athx_transpose_kernel<<<dim3(NS / 32, 3, 56), dim3(32, 8)>>>(X_wrf, 56, 1);

    athx_lstm_mma<<<128, 512, SM_TOTAL>>>(oWih, oWhh, obih, obhh,
                                          wWih, wWhh, wbih, wbhh);

    athx_head_kernel<<<dim3(NS / 128, 2), 256, HEAD_SMEM>>>(
        fW1, fb1, fW2, fb2, fW3, fb3,
        oW1, ob1, oW2, ob2, oW3, ob3, out);
}

// round 5
// speedup vs baseline: 1.9667x; 1.3215x over previous
#include <cuda_runtime.h>
#include <cuda_bf16.h>
#include <cstdint>

#define NS     8192
#define TSTEPS 72

typedef unsigned long long u64;
typedef unsigned int       u32;

// ---------------- scratch (device globals; no allocation allowed) ----------
__device__ u32   g_xt_obs[TSTEPS * 32 * NS];   // [T][C1][N] packed bf16 hi|lo
__device__ u32   g_xt_wrf[TSTEPS * 56 * NS];   // [T][C2][N] packed bf16 hi|lo
__device__ float g_featT[128 * NS];            // [128][N]

// ---------------- smem layout (bytes) for LSTM kernel ----------------------
// 16-bit tiles, 64 cols per row = 128B row stride, XOR swizzle on 8x16B chunks
#define SM_AHI    0          // h operand  [128 x 64]      16 KB
#define SM_ALO    16384
#define SM_XHI    32768      // x operand  [128 x 64]      16 KB
#define SM_XLO    49152
#define SM_BHHI   65536      // Whh gates  [256 x 64]      32 KB
#define SM_BHLO   98304
#define SM_BXHI   131072     // Wih gates  [256 x 64]      32 KB
#define SM_BXLO   163840
#define SM_STAGE  196608     // raw x u32 [C][128]        <=28 KB
#define SM_BIAS   225280     // fp32 bias[256]              1 KB
#define SM_TOTAL  226304

// ---------------- math helpers ---------------------------------------------
__device__ __forceinline__ float tanh_a(float x) {
    float y; asm("tanh.approx.f32 %0, %1;" : "=f"(y) : "f"(x)); return y;
}
__device__ __forceinline__ float sigm_a(float x) {
    return fmaf(0.5f, tanh_a(0.5f * x), 0.5f);
}
__device__ __forceinline__ void split_bf16(float v, unsigned short& hi, unsigned short& lo) {
    u32 u = __float_as_uint(v);
    hi = (unsigned short)(u >> 16);
    float r = v - __uint_as_float(u & 0xFFFF0000u);
    __nv_bfloat16 b = __float2bfloat16_rn(r);
    lo = *reinterpret_cast<unsigned short*>(&b);
}
__device__ __forceinline__ u32 pack_split(float v) {
    unsigned short hi, lo; split_bf16(v, hi, lo);
    return ((u32)hi << 16) | (u32)lo;
}

// ---------------- PTX helpers -----------------------------------------------
__device__ __forceinline__ u32 smem_u32(const void* p) {
    u32 a;
    asm("{ .reg .u64 t; cvta.to.shared.u64 t, %1; cvt.u32.u64 %0, t; }" : "=r"(a) : "l"(p));
    return a;
}
__device__ __forceinline__ void cp_async16(char* smem_dst, const void* gsrc) {
    u32 sa = smem_u32(smem_dst);
    asm volatile("cp.async.ca.shared.global [%0], [%1], 16;\n" :: "r"(sa), "l"(gsrc));
}
__device__ __forceinline__ void cp_commit()   { asm volatile("cp.async.commit_group;\n"); }
__device__ __forceinline__ void cp_wait_all() { asm volatile("cp.async.wait_all;\n"); }

__device__ __forceinline__ void ldsm4(u32& r0, u32& r1, u32& r2, u32& r3, u32 addr) {
    asm volatile("ldmatrix.sync.aligned.m8n8.x4.shared.b16 {%0,%1,%2,%3}, [%4];"
                 : "=r"(r0), "=r"(r1), "=r"(r2), "=r"(r3) : "r"(addr));
}
__device__ __forceinline__ void mma_bf16(float& d0, float& d1, float& d2, float& d3,
                                         u32 a0, u32 a1, u32 a2, u32 a3,
                                         u32 b0, u32 b1) {
    asm volatile("mma.sync.aligned.m16n8k16.row.col.f32.bf16.bf16.f32 "
                 "{%0,%1,%2,%3}, {%4,%5,%6,%7}, {%8,%9}, {%0,%1,%2,%3};"
                 : "+f"(d0), "+f"(d1), "+f"(d2), "+f"(d3)
                 : "r"(a0), "r"(a1), "r"(a2), "r"(a3), "r"(b0), "r"(b1));
}

// row stride 128B, 16B chunk index ^= (row&7)
__device__ __forceinline__ u32 swz(u32 row, u32 chunk) {
    return row * 128u + ((chunk ^ (row & 7u)) << 4);
}

// B row permutation: gate-quad-aligned fragment ownership (same as R4)
__device__ __forceinline__ int brow(int g) {
    int q = g >> 6, j = g & 63;
    int warpN = j >> 4, jl = j & 15;
    int hi = jl >> 3, a = (jl & 7) >> 1, e = jl & 1;
    return warpN * 64 + 8 * (q + 4 * hi) + 2 * a + e;
}

// ---------------- kernel 1: transpose+split [N][C][T] -> [T][C][N] u32 ------
__global__ void athx_transpose_kernel(const float* __restrict__ in, int C, int which) {
    __shared__ float tile[32][33];
    u32* out = which ? g_xt_wrf : g_xt_obs;
    const int c  = blockIdx.z;
    const int n0 = blockIdx.x * 32;
    const int t0 = blockIdx.y * 32;
    const int tx = threadIdx.x, ty = threadIdx.y;
    #pragma unroll
    for (int r = 0; r < 4; ++r) {
        int n = n0 + ty + r * 8;
        int t = t0 + tx;
        if (t < TSTEPS)
            tile[ty + r * 8][tx] = in[((size_t)n * C + c) * TSTEPS + t];
    }
    __syncthreads();
    #pragma unroll
    for (int r = 0; r < 4; ++r) {
        int t = t0 + ty + r * 8;
        int n = n0 + tx;
        if (t < TSTEPS)
            out[((size_t)t * C + c) * NS + n] = pack_split(tile[tx][ty + r * 8]);
    }
}

// ---------------- kernel 2: HMMA dual-LSTM, x-mma overlapped ----------------
__global__ __launch_bounds__(512, 1)
void athx_lstm_mma(const float* __restrict__ oWih, const float* __restrict__ oWhh,
                   const float* __restrict__ obih, const float* __restrict__ obhh,
                   const float* __restrict__ wWih, const float* __restrict__ wWhh,
                   const float* __restrict__ wbih, const float* __restrict__ wbhh)
{
    extern __shared__ char smem[];
    const bool wrf = (blockIdx.x >= 64);
    const int  C   = wrf ? 56 : 32;
    const int  KCX = wrf ? 4 : 2;         // x k-chunks (16 cols each)
    const u32* xt = wrf ? g_xt_wrf : g_xt_obs;
    const float* Wih = wrf ? wWih : oWih;
    const float* Whh = wrf ? wWhh : oWhh;
    const float* bih = wrf ? wbih : obih;
    const float* bhh = wrf ? wbhh : obhh;
    const int n0  = (blockIdx.x & 63) * 128;
    const int tid = threadIdx.x;
    const int wid = tid >> 5;
    const int lane = tid & 31;
    const int warpM = wid >> 2;
    const int warpN = wid & 3;

    const u32 smb = smem_u32(smem);
    u32* stage = (u32*)(smem + SM_STAGE);
    float* bsm = (float*)(smem + SM_BIAS);

    // ---- prefetch x_0 ----
    const int NCHUNK = C * 32;
    for (int i = tid; i < NCHUNK; i += 512) {
        int ch = i >> 5, v = i & 31;
        cp_async16(smem + SM_STAGE + (ch * 128 + v * 4) * 4,
                   xt + (size_t)ch * NS + n0 + v * 4);
    }
    cp_commit();

    // ---- zero all operand tiles [0, 196608) ----
    for (int i = tid; i < 196608 / 16; i += 512)
        ((uint4*)smem)[i] = make_uint4(0, 0, 0, 0);
    __syncthreads();

    // ---- fill B_h (Whh), B_x (Wih), bias ----
    for (int i = tid; i < 256 * 64; i += 512) {
        int g = i >> 6, k = i & 63;
        unsigned short hi, lo; split_bf16(Whh[i], hi, lo);
        u32 off = swz((u32)brow(g), (u32)(k >> 3)) + (k & 7) * 2;
        *(unsigned short*)(smem + SM_BHHI + off) = hi;
        *(unsigned short*)(smem + SM_BHLO + off) = lo;
    }
    for (int i = tid; i < 256 * C; i += 512) {
        int g = i / C, ch = i - g * C;
        unsigned short hi, lo; split_bf16(Wih[i], hi, lo);
        u32 off = swz((u32)brow(g), (u32)(ch >> 3)) + (ch & 7) * 2;
        *(unsigned short*)(smem + SM_BXHI + off) = hi;
        *(unsigned short*)(smem + SM_BXLO + off) = lo;
    }
    if (tid < 256) bsm[tid] = bih[tid] + bhh[tid];

    // ---- copy x_0 staging -> xbuf; prefetch x_1 ----
    cp_wait_all();
    __syncthreads();     // stage fully written (all threads) not needed but cheap
    for (int i = tid; i < C * 128; i += 512) {
        int ch = i >> 7, s = i & 127;
        u32 p = stage[ch * 128 + s];
        u32 off = swz((u32)s, (u32)(ch >> 3)) + (ch & 7) * 2;
        *(unsigned short*)(smem + SM_XHI + off) = (unsigned short)(p >> 16);
        *(unsigned short*)(smem + SM_XLO + off) = (unsigned short)(p & 0xFFFF);
    }
    __syncthreads();
    for (int i = tid; i < NCHUNK; i += 512) {
        int ch = i >> 5, v = i & 31;
        cp_async16(smem + SM_STAGE + (ch * 128 + v * 4) * 4,
                   xt + ((size_t)C + ch) * NS + n0 + v * 4);
    }
    cp_commit();

    // ---- per-thread ldmatrix geometry ----
    const int g8 = lane >> 3, l = lane & 7;
    const u32 aRow = (u32)(warpM * 32 + (g8 & 1) * 8 + l);
    const u32 bRow = (u32)(warpN * 64 + ((g8 >> 1) & 1) * 8 + l);
    const u32 gAc = (u32)(g8 >> 1);
    const u32 gBc = (u32)(g8 & 1);
    const u32 lx = (u32)l;
    const u32 aHiB = smb + SM_AHI + aRow * 128;
    const u32 aLoB = smb + SM_ALO + aRow * 128;
    const u32 xHiB = smb + SM_XHI + aRow * 128;
    const u32 xLoB = smb + SM_XLO + aRow * 128;
    const u32 bhHiB = smb + SM_BHHI + bRow * 128;
    const u32 bhLoB = smb + SM_BHLO + bRow * 128;
    const u32 bxHiB = smb + SM_BXHI + bRow * 128;
    const u32 bxLoB = smb + SM_BXLO + bRow * 128;

    // bias for this thread's 16 gates
    // gate g = q*64 + warpN*16 + h2*8 + (lane&3)*2 + e
    const int jbase = warpN * 16 + (lane & 3) * 2;

    float acc[2][8][4];
    float cst[16];
    #pragma unroll
    for (int i = 0; i < 16; ++i) cst[i] = 0.0f;

    // ---- mma part helper (macro to keep regs tight) ----
#define MMA_PART(AHI_B, ALO_B, BHI_B, BLO_B, KC)                                        \
    for (int ks = 0; ks < (KC); ++ks) {                                                 \
        u32 ah[8], al[8];                                                               \
        u32 ca = ((2u * ks + gAc) ^ lx) << 4;                                           \
        ldsm4(ah[0], ah[1], ah[2], ah[3], (AHI_B) + ca);                                \
        ldsm4(ah[4], ah[5], ah[6], ah[7], (AHI_B) + 2048 + ca);                         \
        ldsm4(al[0], al[1], al[2], al[3], (ALO_B) + ca);                                \
        ldsm4(al[4], al[5], al[6], al[7], (ALO_B) + 2048 + ca);                         \
        u32 cb = ((2u * ks + gBc) ^ lx) << 4;                                           \
        _Pragma("unroll")                                                               \
        for (int ntp = 0; ntp < 4; ++ntp) {                                             \
            u32 b0, b1, b2, b3;                                                         \
            ldsm4(b0, b1, b2, b3, (BHI_B) + ntp * 2048 + cb);                           \
            _Pragma("unroll")                                                           \
            for (int mt = 0; mt < 2; ++mt) {                                            \
                mma_bf16(acc[mt][2*ntp][0], acc[mt][2*ntp][1], acc[mt][2*ntp][2], acc[mt][2*ntp][3], \
                         ah[4*mt], ah[4*mt+1], ah[4*mt+2], ah[4*mt+3], b0, b1);         \
                mma_bf16(acc[mt][2*ntp+1][0], acc[mt][2*ntp+1][1], acc[mt][2*ntp+1][2], acc[mt][2*ntp+1][3], \
                         ah[4*mt], ah[4*mt+1], ah[4*mt+2], ah[4*mt+3], b2, b3);         \
                mma_bf16(acc[mt][2*ntp][0], acc[mt][2*ntp][1], acc[mt][2*ntp][2], acc[mt][2*ntp][3], \
                         al[4*mt], al[4*mt+1], al[4*mt+2], al[4*mt+3], b0, b1);         \
                mma_bf16(acc[mt][2*ntp+1][0], acc[mt][2*ntp+1][1], acc[mt][2*ntp+1][2], acc[mt][2*ntp+1][3], \
                         al[4*mt], al[4*mt+1], al[4*mt+2], al[4*mt+3], b2, b3);         \
            }                                                                           \
            ldsm4(b0, b1, b2, b3, (BLO_B) + ntp * 2048 + cb);                           \
            _Pragma("unroll")                                                           \
            for (int mt = 0; mt < 2; ++mt) {                                            \
                mma_bf16(acc[mt][2*ntp][0], acc[mt][2*ntp][1], acc[mt][2*ntp][2], acc[mt][2*ntp][3], \
                         ah[4*mt], ah[4*mt+1], ah[4*mt+2], ah[4*mt+3], b0, b1);         \
                mma_bf16(acc[mt][2*ntp+1][0], acc[mt][2*ntp+1][1], acc[mt][2*ntp+1][2], acc[mt][2*ntp+1][3], \
                         ah[4*mt], ah[4*mt+1], ah[4*mt+2], ah[4*mt+3], b2, b3);         \
            }                                                                           \
        }                                                                               \
    }

    // ---- prologue: acc = Xpart_0 ----
    #pragma unroll
    for (int mt = 0; mt < 2; ++mt)
        #pragma unroll
        for (int nt = 0; nt < 8; ++nt)
            #pragma unroll
            for (int r = 0; r < 4; ++r) acc[mt][nt][r] = 0.0f;
    __syncthreads();   // B_x, xbuf(x_0) visible
    MMA_PART(xHiB, xLoB, bxHiB, bxLoB, KCX)

    for (int t = 0; t < TSTEPS; ++t) {
        __syncthreads();   // sync1: h_{t-1} STS visible; prior x-mma reads done

        // copy staged x_{t+1} -> xbuf; issue cp.async x_{t+2}
        if (t + 1 < TSTEPS) {
            cp_wait_all();
            for (int i = tid; i < C * 128; i += 512) {
                int ch = i >> 7, s = i & 127;
                u32 p = stage[ch * 128 + s];
                u32 off = swz((u32)s, (u32)(ch >> 3)) + (ch & 7) * 2;
                *(unsigned short*)(smem + SM_XHI + off) = (unsigned short)(p >> 16);
                *(unsigned short*)(smem + SM_XLO + off) = (unsigned short)(p & 0xFFFF);
            }
            if (t + 2 < TSTEPS) {
                const u32* src = xt + (size_t)(t + 2) * C * NS;
                for (int i = tid; i < NCHUNK; i += 512) {
                    int ch = i >> 5, v = i & 31;
                    cp_async16(smem + SM_STAGE + (ch * 128 + v * 4) * 4,
                               src + (size_t)ch * NS + n0 + v * 4);
                }
                cp_commit();
            }
        }

        // ---- h-part mma: acc += h_{t-1} . Whh^T ----
        MMA_PART(aHiB, aLoB, bhHiB, bhLoB, 4)

        // ---- epilogue: bias + gates + state update ----
        float hval[16];
        #pragma unroll
        for (int mt = 0; mt < 2; ++mt)
            #pragma unroll
            for (int d = 0; d < 2; ++d)
                #pragma unroll
                for (int h2 = 0; h2 < 2; ++h2)
                    #pragma unroll
                    for (int e = 0; e < 2; ++e) {
                        int r = 2 * d + e;
                        int ci = ((mt * 2 + d) * 2 + h2) * 2 + e;
                        int j = jbase + h2 * 8 + e;
                        float gi = sigm_a(acc[mt][4*h2 + 0][r] + bsm[j]);
                        float gf = sigm_a(acc[mt][4*h2 + 1][r] + bsm[64 + j]);
                        float gg = tanh_a(acc[mt][4*h2 + 2][r] + bsm[128 + j]);
                        float go = sigm_a(acc[mt][4*h2 + 3][r] + bsm[192 + j]);
                        float cc = fmaf(gf, cst[ci], gi * gg);
                        cst[ci] = cc;
                        hval[ci] = go * tanh_a(cc);
                    }

        __syncthreads();   // sync2: h-mma reads of A done; xbuf copy visible

        if (t == TSTEPS - 1) {
            const int off = wrf ? 64 : 0;
            #pragma unroll
            for (int mt = 0; mt < 2; ++mt)
                #pragma unroll
                for (int d = 0; d < 2; ++d)
                    #pragma unroll
                    for (int h2 = 0; h2 < 2; ++h2)
                        #pragma unroll
                        for (int e = 0; e < 2; ++e) {
                            int s = warpM * 32 + mt * 16 + (lane >> 2) + 8 * d;
                            int j = warpN * 16 + h2 * 8 + (lane & 3) * 2 + e;
                            int ci = ((mt * 2 + d) * 2 + h2) * 2 + e;
                            g_featT[(size_t)(off + j) * NS + n0 + s] = hval[ci];
                        }
        } else {
            // STS h_t -> A (bf16 hi/lo)
            #pragma unroll
            for (int mt = 0; mt < 2; ++mt)
                #pragma unroll
                for (int d = 0; d < 2; ++d)
                    #pragma unroll
                    for (int h2 = 0; h2 < 2; ++h2) {
                        int ci = ((mt * 2 + d) * 2 + h2) * 2;
                        float h0 = hval[ci], h1 = hval[ci + 1];
                        u32 u0 = __float_as_uint(h0), u1 = __float_as_uint(h1);
                        u32 hi32 = (u0 >> 16) | (u1 & 0xFFFF0000u);
                        float r0 = h0 - __uint_as_float(u0 & 0xFFFF0000u);
                        float r1 = h1 - __uint_as_float(u1 & 0xFFFF0000u);
                        __nv_bfloat162 b2 = __floats2bfloat162_rn(r0, r1);
                        u32 lo32 = *reinterpret_cast<u32*>(&b2);
                        u32 s  = (u32)(warpM * 32 + mt * 16 + (lane >> 2) + 8 * d);
                        u32 jp = (u32)(warpN * 16 + h2 * 8 + (lane & 3) * 2);
                        u32 off = swz(s, jp >> 3) + (jp & 7) * 2;
                        *(u32*)(smem + SM_AHI + off) = hi32;
                        *(u32*)(smem + SM_ALO + off) = lo32;
                    }
            // ---- x-part mma for t+1 (overlaps other warps' epilogues) ----
            #pragma unroll
            for (int mt = 0; mt < 2; ++mt)
                #pragma unroll
                for (int nt = 0; nt < 8; ++nt)
                    #pragma unroll
                    for (int r = 0; r < 4; ++r) acc[mt][nt][r] = 0.0f;
            MMA_PART(xHiB, xLoB, bxHiB, bxLoB, KCX)
        }
    }
#undef MMA_PART
}

// ---------------- kernel 3: MLP heads (unchanged, passing since R1) ---------
#define SPAD 132
__device__ __forceinline__ u64 dup2(float x) {
    u64 r; asm("mov.b64 %0, {%1,%1};" : "=l"(r) : "f"(x)); return r;
}
__device__ __forceinline__ void unpack2(u64 v, float& x, float& y) {
    asm("mov.b64 {%0,%1}, %2;" : "=f"(x), "=f"(y) : "l"(v));
}
__device__ __forceinline__ u64 ffma2(u64 a, u64 b, u64 c) {
    u64 d; asm("fma.rn.f32x2 %0, %1, %2, %3;" : "=l"(d) : "l"(a), "l"(b), "l"(c)); return d;
}

template <int IN, int OUT, bool RELU>
__device__ __forceinline__ void athx_layer(const float* __restrict__ A,
                                           const float* __restrict__ wt,
                                           const float* __restrict__ bs,
                                           float* __restrict__ Bout,
                                           int gx, int sx) {
    constexpr int R = OUT / 16;
    u64 acc2[4][R];
    #pragma unroll
    for (int sp = 0; sp < 4; ++sp)
        #pragma unroll
        for (int r = 0; r < R; ++r) acc2[sp][r] = 0ull;
    for (int k = 0; k < IN; ++k) {
        ulonglong2 p0 = *(const ulonglong2*)(A + k * SPAD + sx * 8);
        ulonglong2 p1 = *(const ulonglong2*)(A + k * SPAD + sx * 8 + 4);
        u64 a2[4] = {p0.x, p0.y, p1.x, p1.y};
        #pragma unroll
        for (int r = 0; r < R; ++r) {
            u64 b2 = dup2(wt[k * OUT + gx + 16 * r]);
            #pragma unroll
            for (int sp = 0; sp < 4; ++sp) acc2[sp][r] = ffma2(a2[sp], b2, acc2[sp][r]);
        }
    }
    #pragma unroll
    for (int r = 0; r < R; ++r) {
        int u = gx + 16 * r;
        float bb = bs[u];
        float hv[8];
        #pragma unroll
        for (int sp = 0; sp < 4; ++sp) {
            float v0, v1;
            unpack2(acc2[sp][r], v0, v1);
            v0 += bb; v1 += bb;
            hv[2 * sp]     = RELU ? fmaxf(v0, 0.0f) : v0;
            hv[2 * sp + 1] = RELU ? fmaxf(v1, 0.0f) : v1;
        }
        *(float4*)(Bout + u * SPAD + sx * 8)     = make_float4(hv[0], hv[1], hv[2], hv[3]);
        *(float4*)(Bout + u * SPAD + sx * 8 + 4) = make_float4(hv[4], hv[5], hv[6], hv[7]);
    }
}

__global__ __launch_bounds__(256, 1) void athx_head_kernel(
    const float* __restrict__ fW1, const float* __restrict__ fb1,
    const float* __restrict__ fW2, const float* __restrict__ fb2,
    const float* __restrict__ fW3, const float* __restrict__ fb3,
    const float* __restrict__ oW1, const float* __restrict__ ob1,
    const float* __restrict__ oW2, const float* __restrict__ ob2,
    const float* __restrict__ oW3, const float* __restrict__ ob3,
    float* __restrict__ out)
{
    extern __shared__ float sm[];
    float* A   = sm;
    float* B   = A + 128 * SPAD;
    float* w1t = B + 96 * SPAD;
    float* w2t = w1t + 128 * 96;
    float* w3t = w2t + 96 * 64;
    float* bs1 = w3t + 64 * 48;
    float* bs2 = bs1 + 96;
    float* bs3 = bs2 + 64;

    const int head = blockIdx.y;
    const float* W1 = head ? oW1 : fW1; const float* b1 = head ? ob1 : fb1;
    const float* W2 = head ? oW2 : fW2; const float* b2 = head ? ob2 : fb2;
    const float* W3 = head ? oW3 : fW3; const float* b3 = head ? ob3 : fb3;
    const int n0  = blockIdx.x * 128;
    const int tid = threadIdx.x;
    const int gx  = tid & 15, sx = tid >> 4;

    for (int idx = tid; idx < 128 * 128; idx += 256) {
        int k = idx >> 7, s = idx & 127;
        A[k * SPAD + s] = g_featT[(size_t)k * NS + n0 + s];
    }
    for (int idx = tid; idx < 96 * 128; idx += 256) {
        int u = idx >> 7, k = idx & 127;
        w1t[k * 96 + u] = W1[idx];
    }
    for (int idx = tid; idx < 64 * 96; idx += 256) {
        int u = idx / 96, k = idx - u * 96;
        w2t[k * 64 + u] = W2[idx];
    }
    for (int idx = tid; idx < 48 * 64; idx += 256) {
        int u = idx >> 6, k = idx & 63;
        w3t[k * 48 + u] = W3[idx];
    }
    if (tid < 96) bs1[tid] = b1[tid];
    if (tid < 64) bs2[tid] = b2[tid];
    if (tid < 48) bs3[tid] = b3[tid];
    __syncthreads();

    athx_layer<128, 96, true>(A, w1t, bs1, B, gx, sx);
    __syncthreads();
    athx_layer<96, 64, true>(B, w2t, bs2, A, gx, sx);
    __syncthreads();

    {
        u64 acc2[4][3];
        #pragma unroll
        for (int sp = 0; sp < 4; ++sp)
            #pragma unroll
            for (int r = 0; r < 3; ++r) acc2[sp][r] = 0ull;
        for (int k = 0; k < 64; ++k) {
            ulonglong2 p0 = *(const ulonglong2*)(A + k * SPAD + sx * 8);
            ulonglong2 p1 = *(const ulonglong2*)(A + k * SPAD + sx * 8 + 4);
            u64 a2[4] = {p0.x, p0.y, p1.x, p1.y};
            #pragma unroll
            for (int r = 0; r < 3; ++r) {
                u64 b2 = dup2(w3t[k * 48 + gx + 16 * r]);
                #pragma unroll
                for (int sp = 0; sp < 4; ++sp) acc2[sp][r] = ffma2(a2[sp], b2, acc2[sp][r]);
            }
        }
        #pragma unroll
        for (int r = 0; r < 3; ++r) {
            int u = gx + 16 * r;
            float bb = bs3[u];
            #pragma unroll
            for (int sp = 0; sp < 4; ++sp) {
                float v0, v1;
                unpack2(acc2[sp][r], v0, v1);
                int n = n0 + sx * 8 + 2 * sp;
                out[(size_t)n * 96 + head * 48 + u]       = v0 + bb;
                out[(size_t)(n + 1) * 96 + head * 48 + u] = v1 + bb;
            }
        }
    }
}

// ---------------- launch ----------------------------------------------------
extern "C" void kernel_launch(void* const* d_in, const int* in_sizes, int n_in,
                              void* d_out, int out_size) {
    const float* X_obs  = (const float*)d_in[0];
    const float* X_wrf  = (const float*)d_in[1];
    const float* oWih   = (const float*)d_in[2];
    const float* oWhh   = (const float*)d_in[3];
    const float* obih   = (const float*)d_in[4];
    const float* obhh   = (const float*)d_in[5];
    const float* wWih   = (const float*)d_in[6];
    const float* wWhh   = (const float*)d_in[7];
    const float* wbih   = (const float*)d_in[8];
    const float* wbhh   = (const float*)d_in[9];
    const float* fW1 = (const float*)d_in[10]; const float* fb1 = (const float*)d_in[11];
    const float* fW2 = (const float*)d_in[12]; const float* fb2 = (const float*)d_in[13];
    const float* fW3 = (const float*)d_in[14]; const float* fb3 = (const float*)d_in[15];
    const float* oW1 = (const float*)d_in[16]; const float* ob1 = (const float*)d_in[17];
    const float* oW2 = (const float*)d_in[18]; const float* ob2 = (const float*)d_in[19];
    const float* oW3 = (const float*)d_in[20]; const float* ob3 = (const float*)d_in[21];
    float* out = (float*)d_out;

    const int HEAD_SMEM = (128 * SPAD + 96 * SPAD + 128 * 96 + 96 * 64 + 64 * 48
                           + 96 + 64 + 48) * 4;
    cudaFuncSetAttribute(athx_lstm_mma, cudaFuncAttributeMaxDynamicSharedMemorySize, SM_TOTAL);
    cudaFuncSetAttribute(athx_head_kernel, cudaFuncAttributeMaxDynamicSharedMemorySize, HEAD_SMEM);

    athx_transpose_kernel<<<dim3(NS / 32, 3, 32), dim3(32, 8)>>>(X_obs, 32, 0);
    athx_transpose_kernel<<<dim3(NS / 32, 3, 56), dim3(32, 8)>>>(X_wrf, 56, 1);

    athx_lstm_mma<<<128, 512, SM_TOTAL>>>(oWih, oWhh, obih, obhh,
                                          wWih, wWhh, wbih, wbhh);

    athx_head_kernel<<<dim3(NS / 128, 2), 256, HEAD_SMEM>>>(
        fW1, fb1, fW2, fb2, fW3, fb3,
        oW1, ob1, oW2, ob2, oW3, ob3, out);
}

// round 6
// speedup vs baseline: 2.2292x; 1.1335x over previous
#include <cuda_runtime.h>
#include <cuda_fp16.h>
#include <cstdint>

#define NS     8192
#define TSTEPS 72

typedef unsigned long long u64;
typedef unsigned int       u32;

// ---------------- scratch (device globals; no allocation allowed) ----------
__device__ u32   g_xt_obs[TSTEPS * 32 * NS];   // [T][C1][N] packed fp16 hi|lo
__device__ u32   g_xt_wrf[TSTEPS * 56 * NS];   // [T][C2][N] packed fp16 hi|lo
__device__ float g_featT[128 * NS];            // [128][N]

// ---------------- smem layout (bytes) for LSTM kernel ----------------------
// fp16 tiles, 64 cols per row = 128B row stride, XOR swizzle on 8x16B chunks
#define SM_AH0   0          // h hi buf0 [128x64] 16 KB
#define SM_AL0   16384
#define SM_AH1   32768
#define SM_AL1   49152
#define SM_XHI   65536      // x hi (single buffer)
#define SM_XLO   81920
#define SM_BH    98304      // Whh fp16 [256x64] 32 KB
#define SM_BX    131072     // Wih fp16 [256x64] 32 KB
#define SM_ST0   163840     // stage buf0: u32 [C][128] <=28 KB
#define SM_ST1   192512     // stage buf1
#define SM_TOTAL 221184

// ---------------- math helpers ---------------------------------------------
__device__ __forceinline__ float tanh_a(float x) {
    float y; asm("tanh.approx.f32 %0, %1;" : "=f"(y) : "f"(x)); return y;
}
__device__ __forceinline__ float sigm_a(float x) {
    return fmaf(0.5f, tanh_a(0.5f * x), 0.5f);
}
// fp16 split: v = hi + lo (hi = rn(v), lo = rn(v - hi))
__device__ __forceinline__ u32 pack_split(float v) {
    __half h = __float2half_rn(v);
    float r = v - __half2float(h);
    __half l = __float2half_rn(r);
    u32 hb = (u32)__half_as_ushort(h);
    u32 lb = (u32)__half_as_ushort(l);
    return (hb << 16) | lb;
}

// ---------------- PTX helpers -----------------------------------------------
__device__ __forceinline__ u32 smem_u32(const void* p) {
    u32 a;
    asm("{ .reg .u64 t; cvta.to.shared.u64 t, %1; cvt.u32.u64 %0, t; }" : "=r"(a) : "l"(p));
    return a;
}
__device__ __forceinline__ void cp_async16(char* smem_dst, const void* gsrc) {
    u32 sa = smem_u32(smem_dst);
    asm volatile("cp.async.ca.shared.global [%0], [%1], 16;\n" :: "r"(sa), "l"(gsrc));
}
__device__ __forceinline__ void cp_commit()   { asm volatile("cp.async.commit_group;\n"); }
__device__ __forceinline__ void cp_wait_all() { asm volatile("cp.async.wait_all;\n"); }

__device__ __forceinline__ void ldsm4(u32& r0, u32& r1, u32& r2, u32& r3, u32 addr) {
    asm volatile("ldmatrix.sync.aligned.m8n8.x4.shared.b16 {%0,%1,%2,%3}, [%4];"
                 : "=r"(r0), "=r"(r1), "=r"(r2), "=r"(r3) : "r"(addr));
}
__device__ __forceinline__ void mma_fp16(float& d0, float& d1, float& d2, float& d3,
                                         u32 a0, u32 a1, u32 a2, u32 a3,
                                         u32 b0, u32 b1) {
    asm volatile("mma.sync.aligned.m16n8k16.row.col.f32.f16.f16.f32 "
                 "{%0,%1,%2,%3}, {%4,%5,%6,%7}, {%8,%9}, {%0,%1,%2,%3};"
                 : "+f"(d0), "+f"(d1), "+f"(d2), "+f"(d3)
                 : "r"(a0), "r"(a1), "r"(a2), "r"(a3), "r"(b0), "r"(b1));
}

// row stride 128B, 16B chunk index ^= (row&7)
__device__ __forceinline__ u32 swz(u32 row, u32 chunk) {
    return row * 128u + ((chunk ^ (row & 7u)) << 4);
}

// B row permutation: gate-quad-aligned fragment ownership
__device__ __forceinline__ int brow(int g) {
    int q = g >> 6, j = g & 63;
    int warpN = j >> 4, jl = j & 15;
    int hi = jl >> 3, a = (jl & 7) >> 1, e = jl & 1;
    return warpN * 64 + 8 * (q + 4 * hi) + 2 * a + e;
}

// ---------------- kernel 1: transpose+split [N][C][T] -> [T][C][N] u32 ------
__global__ void athx_transpose_kernel(const float* __restrict__ in, int C, int which) {
    __shared__ float tile[32][33];
    u32* out = which ? g_xt_wrf : g_xt_obs;
    const int c  = blockIdx.z;
    const int n0 = blockIdx.x * 32;
    const int t0 = blockIdx.y * 32;
    const int tx = threadIdx.x, ty = threadIdx.y;
    #pragma unroll
    for (int r = 0; r < 4; ++r) {
        int n = n0 + ty + r * 8;
        int t = t0 + tx;
        if (t < TSTEPS)
            tile[ty + r * 8][tx] = in[((size_t)n * C + c) * TSTEPS + t];
    }
    __syncthreads();
    #pragma unroll
    for (int r = 0; r < 4; ++r) {
        int t = t0 + ty + r * 8;
        int n = n0 + tx;
        if (t < TSTEPS)
            out[((size_t)t * C + c) * NS + n] = pack_split(tile[tx][ty + r * 8]);
    }
}

// ---------------- kernel 2: HMMA dual-LSTM, fp16 2-product ------------------
// 128 CTAs x 512 thr: blocks 0..63 obs (C=32), 64..127 wrf (C=56); 128 samples.
// D = (a_hi + a_lo) . fp16(W)^T  — exact activations x fp16 weights.
__global__ __launch_bounds__(512, 1)
void athx_lstm_mma(const float* __restrict__ oWih, const float* __restrict__ oWhh,
                   const float* __restrict__ obih, const float* __restrict__ obhh,
                   const float* __restrict__ wWih, const float* __restrict__ wWhh,
                   const float* __restrict__ wbih, const float* __restrict__ wbhh)
{
    extern __shared__ char smem[];
    const bool wrf = (blockIdx.x >= 64);
    const int  C   = wrf ? 56 : 32;
    const int  KCX = wrf ? 4 : 2;         // x k-chunks (16 cols each)
    const u32* xt = wrf ? g_xt_wrf : g_xt_obs;
    const float* Wih = wrf ? wWih : oWih;
    const float* Whh = wrf ? wWhh : oWhh;
    const float* bih = wrf ? wbih : obih;
    const float* bhh = wrf ? wbhh : obhh;
    const int n0  = (blockIdx.x & 63) * 128;
    const int tid = threadIdx.x;
    const int wid = tid >> 5;
    const int lane = tid & 31;
    const int warpM = wid >> 2;
    const int warpN = wid & 3;

    const u32 smb = smem_u32(smem);
    const int NCHUNK = C * 32;           // 16B chunks per x tile

    // ---- prefetch x_0 into stage0 ----
    for (int i = tid; i < NCHUNK; i += 512) {
        int ch = i >> 5, v = i & 31;
        cp_async16(smem + SM_ST0 + (ch * 128 + v * 4) * 4,
                   xt + (size_t)ch * NS + n0 + v * 4);
    }
    cp_commit();

    // ---- zero all fp16 operand tiles [0, 163840) ----
    for (int i = tid; i < 163840 / 16; i += 512)
        ((uint4*)smem)[i] = make_uint4(0, 0, 0, 0);
    __syncthreads();

    // ---- fill B_h (Whh fp16), B_x (Wih fp16) ----
    for (int i = tid; i < 256 * 64; i += 512) {
        int g = i >> 6, k = i & 63;
        u32 off = swz((u32)brow(g), (u32)(k >> 3)) + (k & 7) * 2;
        *(__half*)(smem + SM_BH + off) = __float2half_rn(Whh[i]);
    }
    for (int i = tid; i < 256 * C; i += 512) {
        int g = i / C, ch = i - g * C;
        u32 off = swz((u32)brow(g), (u32)(ch >> 3)) + (ch & 7) * 2;
        *(__half*)(smem + SM_BX + off) = __float2half_rn(Wih[i]);
    }

    // ---- bias into registers (per-thread 16 gates) ----
    const int jbase = warpN * 16 + (lane & 3) * 2;
    float breg[16];
    #pragma unroll
    for (int q = 0; q < 4; ++q)
        #pragma unroll
        for (int h2 = 0; h2 < 2; ++h2)
            #pragma unroll
            for (int e = 0; e < 2; ++e) {
                int g = q * 64 + jbase + h2 * 8 + e;
                breg[q * 4 + h2 * 2 + e] = bih[g] + bhh[g];
            }

    // ---- x_0 stage -> xbuf; prefetch x_1 into stage1 ----
    cp_wait_all();
    __syncthreads();    // stage0 chunks from ALL threads landed; B visible
    {
        const u32* stg = (const u32*)(smem + SM_ST0);
        for (int i = tid; i < C * 128; i += 512) {
            int ch = i >> 7, s = i & 127;
            u32 p = stg[ch * 128 + s];
            u32 off = swz((u32)s, (u32)(ch >> 3)) + (ch & 7) * 2;
            *(unsigned short*)(smem + SM_XHI + off) = (unsigned short)(p >> 16);
            *(unsigned short*)(smem + SM_XLO + off) = (unsigned short)(p & 0xFFFF);
        }
    }
    for (int i = tid; i < NCHUNK; i += 512) {
        int ch = i >> 5, v = i & 31;
        cp_async16(smem + SM_ST1 + (ch * 128 + v * 4) * 4,
                   xt + ((size_t)C + ch) * NS + n0 + v * 4);
    }
    cp_commit();
    __syncthreads();    // xbuf(x_0) visible; hbuf0 zeros already visible

    // ---- per-thread ldmatrix geometry ----
    const int g8 = lane >> 3, l = lane & 7;
    const u32 aRow = (u32)(warpM * 32 + (g8 & 1) * 8 + l);
    const u32 bRow = (u32)(warpN * 64 + ((g8 >> 1) & 1) * 8 + l);
    const u32 gAc = (u32)(g8 >> 1);
    const u32 gBc = (u32)(g8 & 1);
    const u32 lx = (u32)l;
    const u32 aH0 = smb + SM_AH0 + aRow * 128;
    const u32 aL0 = smb + SM_AL0 + aRow * 128;
    const u32 aH1 = smb + SM_AH1 + aRow * 128;
    const u32 aL1 = smb + SM_AL1 + aRow * 128;
    const u32 xHiB = smb + SM_XHI + aRow * 128;
    const u32 xLoB = smb + SM_XLO + aRow * 128;
    const u32 bhB  = smb + SM_BH + bRow * 128;
    const u32 bxB  = smb + SM_BX + bRow * 128;

    float acc[2][8][4];
    float cst[16];
    #pragma unroll
    for (int i = 0; i < 16; ++i) cst[i] = 0.0f;

    // 2-product mma pass: (ahi + alo) . B
#define MMA2(AHI_B, ALO_B, B_B, KC)                                                     \
    for (int ks = 0; ks < (KC); ++ks) {                                                 \
        u32 ah[8], al[8];                                                               \
        u32 ca = ((2u * ks + gAc) ^ lx) << 4;                                           \
        ldsm4(ah[0], ah[1], ah[2], ah[3], (AHI_B) + ca);                                \
        ldsm4(ah[4], ah[5], ah[6], ah[7], (AHI_B) + 2048 + ca);                         \
        ldsm4(al[0], al[1], al[2], al[3], (ALO_B) + ca);                                \
        ldsm4(al[4], al[5], al[6], al[7], (ALO_B) + 2048 + ca);                         \
        u32 cb = ((2u * ks + gBc) ^ lx) << 4;                                           \
        _Pragma("unroll")                                                               \
        for (int ntp = 0; ntp < 4; ++ntp) {                                             \
            u32 b0, b1, b2, b3;                                                         \
            ldsm4(b0, b1, b2, b3, (B_B) + ntp * 2048 + cb);                             \
            _Pragma("unroll")                                                           \
            for (int mt = 0; mt < 2; ++mt) {                                            \
                mma_fp16(acc[mt][2*ntp][0], acc[mt][2*ntp][1], acc[mt][2*ntp][2], acc[mt][2*ntp][3], \
                         ah[4*mt], ah[4*mt+1], ah[4*mt+2], ah[4*mt+3], b0, b1);         \
                mma_fp16(acc[mt][2*ntp+1][0], acc[mt][2*ntp+1][1], acc[mt][2*ntp+1][2], acc[mt][2*ntp+1][3], \
                         ah[4*mt], ah[4*mt+1], ah[4*mt+2], ah[4*mt+3], b2, b3);         \
                mma_fp16(acc[mt][2*ntp][0], acc[mt][2*ntp][1], acc[mt][2*ntp][2], acc[mt][2*ntp][3], \
                         al[4*mt], al[4*mt+1], al[4*mt+2], al[4*mt+3], b0, b1);         \
                mma_fp16(acc[mt][2*ntp+1][0], acc[mt][2*ntp+1][1], acc[mt][2*ntp+1][2], acc[mt][2*ntp+1][3], \
                         al[4*mt], al[4*mt+1], al[4*mt+2], al[4*mt+3], b2, b3);         \
            }                                                                           \
        }                                                                               \
    }

    for (int t = 0; t < TSTEPS; ++t) {
        const int cur = t & 1;

        #pragma unroll
        for (int mt = 0; mt < 2; ++mt)
            #pragma unroll
            for (int nt = 0; nt < 8; ++nt)
                #pragma unroll
                for (int r = 0; r < 4; ++r) acc[mt][nt][r] = 0.0f;

        // x-part then h-part
        MMA2(xHiB, xLoB, bxB, KCX)
        if (cur == 0) { MMA2(aH0, aL0, bhB, 4) } else { MMA2(aH1, aL1, bhB, 4) }

        // ---- epilogue ----
        float hval[16];
        #pragma unroll
        for (int mt = 0; mt < 2; ++mt)
            #pragma unroll
            for (int d = 0; d < 2; ++d)
                #pragma unroll
                for (int h2 = 0; h2 < 2; ++h2)
                    #pragma unroll
                    for (int e = 0; e < 2; ++e) {
                        int r = 2 * d + e;
                        int ci = ((mt * 2 + d) * 2 + h2) * 2 + e;
                        int bi = h2 * 2 + e;
                        float gi = sigm_a(acc[mt][4*h2 + 0][r] + breg[bi]);
                        float gf = sigm_a(acc[mt][4*h2 + 1][r] + breg[4 + bi]);
                        float gg = tanh_a(acc[mt][4*h2 + 2][r] + breg[8 + bi]);
                        float go = sigm_a(acc[mt][4*h2 + 3][r] + breg[12 + bi]);
                        float cc = fmaf(gf, cst[ci], gi * gg);
                        cst[ci] = cc;
                        hval[ci] = go * tanh_a(cc);
                    }

        cp_wait_all();       // own stage chunks for x_{t+1} landed
        __syncthreads();     // S2: everyone waited; mma reads of xbuf/h done

        if (t == TSTEPS - 1) {
            const int off = wrf ? 64 : 0;
            #pragma unroll
            for (int mt = 0; mt < 2; ++mt)
                #pragma unroll
                for (int d = 0; d < 2; ++d)
                    #pragma unroll
                    for (int h2 = 0; h2 < 2; ++h2)
                        #pragma unroll
                        for (int e = 0; e < 2; ++e) {
                            int s = warpM * 32 + mt * 16 + (lane >> 2) + 8 * d;
                            int j = warpN * 16 + h2 * 8 + (lane & 3) * 2 + e;
                            int ci = ((mt * 2 + d) * 2 + h2) * 2 + e;
                            g_featT[(size_t)(off + j) * NS + n0 + s] = hval[ci];
                        }
        } else {
            // copy staged x_{t+1} -> xbuf
            {
                const u32* stg = (const u32*)(smem + ((t & 1) ? SM_ST0 : SM_ST1));
                for (int i = tid; i < C * 128; i += 512) {
                    int ch = i >> 7, s = i & 127;
                    u32 p = stg[ch * 128 + s];
                    u32 off = swz((u32)s, (u32)(ch >> 3)) + (ch & 7) * 2;
                    *(unsigned short*)(smem + SM_XHI + off) = (unsigned short)(p >> 16);
                    *(unsigned short*)(smem + SM_XLO + off) = (unsigned short)(p & 0xFFFF);
                }
            }
            // STS h_t -> hbuf[nxt] (fp16 hi/lo)
            {
                const u32 dstH = (cur ? SM_AH0 : SM_AH1);
                const u32 dstL = (cur ? SM_AL0 : SM_AL1);
                #pragma unroll
                for (int mt = 0; mt < 2; ++mt)
                    #pragma unroll
                    for (int d = 0; d < 2; ++d)
                        #pragma unroll
                        for (int h2 = 0; h2 < 2; ++h2) {
                            int ci = ((mt * 2 + d) * 2 + h2) * 2;
                            float h0 = hval[ci], h1 = hval[ci + 1];
                            __half hh0 = __float2half_rn(h0);
                            __half hh1 = __float2half_rn(h1);
                            __half hl0 = __float2half_rn(h0 - __half2float(hh0));
                            __half hl1 = __float2half_rn(h1 - __half2float(hh1));
                            u32 hi32 = (u32)__half_as_ushort(hh0) | ((u32)__half_as_ushort(hh1) << 16);
                            u32 lo32 = (u32)__half_as_ushort(hl0) | ((u32)__half_as_ushort(hl1) << 16);
                            u32 s  = (u32)(warpM * 32 + mt * 16 + (lane >> 2) + 8 * d);
                            u32 jp = (u32)(warpN * 16 + h2 * 8 + (lane & 3) * 2);
                            u32 off = swz(s, jp >> 3) + (jp & 7) * 2;
                            *(u32*)(smem + dstH + off) = hi32;
                            *(u32*)(smem + dstL + off) = lo32;
                        }
            }
            // cp.async x_{t+2} -> stage[t&1] (its readers finished in window t-1)
            if (t + 2 < TSTEPS) {
                const u32* src = xt + (size_t)(t + 2) * C * NS;
                char* dst = smem + ((t & 1) ? SM_ST1 : SM_ST0);
                for (int i = tid; i < NCHUNK; i += 512) {
                    int ch = i >> 5, v = i & 31;
                    cp_async16(dst + (ch * 128 + v * 4) * 4,
                               src + (size_t)ch * NS + n0 + v * 4);
                }
                cp_commit();
            }
            __syncthreads();   // S1: xbuf + h STS visible for next window
        }
    }
#undef MMA2
}

// ---------------- kernel 3: MLP heads (unchanged, passing since R1) ---------
#define SPAD 132
__device__ __forceinline__ u64 dup2(float x) {
    u64 r; asm("mov.b64 %0, {%1,%1};" : "=l"(r) : "f"(x)); return r;
}
__device__ __forceinline__ void unpack2(u64 v, float& x, float& y) {
    asm("mov.b64 {%0,%1}, %2;" : "=f"(x), "=f"(y) : "l"(v));
}
__device__ __forceinline__ u64 ffma2(u64 a, u64 b, u64 c) {
    u64 d; asm("fma.rn.f32x2 %0, %1, %2, %3;" : "=l"(d) : "l"(a), "l"(b), "l"(c)); return d;
}

template <int IN, int OUT, bool RELU>
__device__ __forceinline__ void athx_layer(const float* __restrict__ A,
                                           const float* __restrict__ wt,
                                           const float* __restrict__ bs,
                                           float* __restrict__ Bout,
                                           int gx, int sx) {
    constexpr int R = OUT / 16;
    u64 acc2[4][R];
    #pragma unroll
    for (int sp = 0; sp < 4; ++sp)
        #pragma unroll
        for (int r = 0; r < R; ++r) acc2[sp][r] = 0ull;
    for (int k = 0; k < IN; ++k) {
        ulonglong2 p0 = *(const ulonglong2*)(A + k * SPAD + sx * 8);
        ulonglong2 p1 = *(const ulonglong2*)(A + k * SPAD + sx * 8 + 4);
        u64 a2[4] = {p0.x, p0.y, p1.x, p1.y};
        #pragma unroll
        for (int r = 0; r < R; ++r) {
            u64 b2 = dup2(wt[k * OUT + gx + 16 * r]);
            #pragma unroll
            for (int sp = 0; sp < 4; ++sp) acc2[sp][r] = ffma2(a2[sp], b2, acc2[sp][r]);
        }
    }
    #pragma unroll
    for (int r = 0; r < R; ++r) {
        int u = gx + 16 * r;
        float bb = bs[u];
        float hv[8];
        #pragma unroll
        for (int sp = 0; sp < 4; ++sp) {
            float v0, v1;
            unpack2(acc2[sp][r], v0, v1);
            v0 += bb; v1 += bb;
            hv[2 * sp]     = RELU ? fmaxf(v0, 0.0f) : v0;
            hv[2 * sp + 1] = RELU ? fmaxf(v1, 0.0f) : v1;
        }
        *(float4*)(Bout + u * SPAD + sx * 8)     = make_float4(hv[0], hv[1], hv[2], hv[3]);
        *(float4*)(Bout + u * SPAD + sx * 8 + 4) = make_float4(hv[4], hv[5], hv[6], hv[7]);
    }
}

__global__ __launch_bounds__(256, 1) void athx_head_kernel(
    const float* __restrict__ fW1, const float* __restrict__ fb1,
    const float* __restrict__ fW2, const float* __restrict__ fb2,
    const float* __restrict__ fW3, const float* __restrict__ fb3,
    const float* __restrict__ oW1, const float* __restrict__ ob1,
    const float* __restrict__ oW2, const float* __restrict__ ob2,
    const float* __restrict__ oW3, const float* __restrict__ ob3,
    float* __restrict__ out)
{
    extern __shared__ float sm[];
    float* A   = sm;
    float* B   = A + 128 * SPAD;
    float* w1t = B + 96 * SPAD;
    float* w2t = w1t + 128 * 96;
    float* w3t = w2t + 96 * 64;
    float* bs1 = w3t + 64 * 48;
    float* bs2 = bs1 + 96;
    float* bs3 = bs2 + 64;

    const int head = blockIdx.y;
    const float* W1 = head ? oW1 : fW1; const float* b1 = head ? ob1 : fb1;
    const float* W2 = head ? oW2 : fW2; const float* b2 = head ? ob2 : fb2;
    const float* W3 = head ? oW3 : fW3; const float* b3 = head ? ob3 : fb3;
    const int n0  = blockIdx.x * 128;
    const int tid = threadIdx.x;
    const int gx  = tid & 15, sx = tid >> 4;

    for (int idx = tid; idx < 128 * 128; idx += 256) {
        int k = idx >> 7, s = idx & 127;
        A[k * SPAD + s] = g_featT[(size_t)k * NS + n0 + s];
    }
    for (int idx = tid; idx < 96 * 128; idx += 256) {
        int u = idx >> 7, k = idx & 127;
        w1t[k * 96 + u] = W1[idx];
    }
    for (int idx = tid; idx < 64 * 96; idx += 256) {
        int u = idx / 96, k = idx - u * 96;
        w2t[k * 64 + u] = W2[idx];
    }
    for (int idx = tid; idx < 48 * 64; idx += 256) {
        int u = idx >> 6, k = idx & 63;
        w3t[k * 48 + u] = W3[idx];
    }
    if (tid < 96) bs1[tid] = b1[tid];
    if (tid < 64) bs2[tid] = b2[tid];
    if (tid < 48) bs3[tid] = b3[tid];
    __syncthreads();

    athx_layer<128, 96, true>(A, w1t, bs1, B, gx, sx);
    __syncthreads();
    athx_layer<96, 64, true>(B, w2t, bs2, A, gx, sx);
    __syncthreads();

    {
        u64 acc2[4][3];
        #pragma unroll
        for (int sp = 0; sp < 4; ++sp)
            #pragma unroll
            for (int r = 0; r < 3; ++r) acc2[sp][r] = 0ull;
        for (int k = 0; k < 64; ++k) {
            ulonglong2 p0 = *(const ulonglong2*)(A + k * SPAD + sx * 8);
            ulonglong2 p1 = *(const ulonglong2*)(A + k * SPAD + sx * 8 + 4);
            u64 a2[4] = {p0.x, p0.y, p1.x, p1.y};
            #pragma unroll
            for (int r = 0; r < 3; ++r) {
                u64 b2 = dup2(w3t[k * 48 + gx + 16 * r]);
                #pragma unroll
                for (int sp = 0; sp < 4; ++sp) acc2[sp][r] = ffma2(a2[sp], b2, acc2[sp][r]);
            }
        }
        #pragma unroll
        for (int r = 0; r < 3; ++r) {
            int u = gx + 16 * r;
            float bb = bs3[u];
            #pragma unroll
            for (int sp = 0; sp < 4; ++sp) {
                float v0, v1;
                unpack2(acc2[sp][r], v0, v1);
                int n = n0 + sx * 8 + 2 * sp;
                out[(size_t)n * 96 + head * 48 + u]       = v0 + bb;
                out[(size_t)(n + 1) * 96 + head * 48 + u] = v1 + bb;
            }
        }
    }
}

// ---------------- launch ----------------------------------------------------
extern "C" void kernel_launch(void* const* d_in, const int* in_sizes, int n_in,
                              void* d_out, int out_size) {
    const float* X_obs  = (const float*)d_in[0];
    const float* X_wrf  = (const float*)d_in[1];
    const float* oWih   = (const float*)d_in[2];
    const float* oWhh   = (const float*)d_in[3];
    const float* obih   = (const float*)d_in[4];
    const float* obhh   = (const float*)d_in[5];
    const float* wWih   = (const float*)d_in[6];
    const float* wWhh   = (const float*)d_in[7];
    const float* wbih   = (const float*)d_in[8];
    const float* wbhh   = (const float*)d_in[9];
    const float* fW1 = (const float*)d_in[10]; const float* fb1 = (const float*)d_in[11];
    const float* fW2 = (const float*)d_in[12]; const float* fb2 = (const float*)d_in[13];
    const float* fW3 = (const float*)d_in[14]; const float* fb3 = (const float*)d_in[15];
    const float* oW1 = (const float*)d_in[16]; const float* ob1 = (const float*)d_in[17];
    const float* oW2 = (const float*)d_in[18]; const float* ob2 = (const float*)d_in[19];
    const float* oW3 = (const float*)d_in[20]; const float* ob3 = (const float*)d_in[21];
    float* out = (float*)d_out;

    const int HEAD_SMEM = (128 * SPAD + 96 * SPAD + 128 * 96 + 96 * 64 + 64 * 48
                           + 96 + 64 + 48) * 4;
    cudaFuncSetAttribute(athx_lstm_mma, cudaFuncAttributeMaxDynamicSharedMemorySize, SM_TOTAL);
    cudaFuncSetAttribute(athx_head_kernel, cudaFuncAttributeMaxDynamicSharedMemorySize, HEAD_SMEM);

    athx_transpose_kernel<<<dim3(NS / 32, 3, 32), dim3(32, 8)>>>(X_obs, 32, 0);
    athx_transpose_kernel<<<dim3(NS / 32, 3, 56), dim3(32, 8)>>>(X_wrf, 56, 1);

    athx_lstm_mma<<<128, 512, SM_TOTAL>>>(oWih, oWhh, obih, obhh,
                                          wWih, wWhh, wbih, wbhh);

    athx_head_kernel<<<dim3(NS / 128, 2), 256, HEAD_SMEM>>>(
        fW1, fb1, fW2, fb2, fW3, fb3,
        oW1, ob1, oW2, ob2, oW3, ob3, out);
}

// round 7
// speedup vs baseline: 2.4716x; 1.1087x over previous
#include <cuda_runtime.h>
#include <cuda_fp16.h>
#include <cstdint>

#define NS     8192
#define TSTEPS 72

typedef unsigned long long u64;
typedef unsigned int       u32;

// ---------------- scratch (device globals; no allocation allowed) ----------
__device__ u32   g_xt_obs[TSTEPS * 32 * NS];   // [T][C1][N] packed fp16 hi|lo
__device__ u32   g_xt_wrf[TSTEPS * 56 * NS];   // [T][C2][N] packed fp16 hi|lo
__device__ float g_featT[128 * NS];            // [128][N]

// ---------------- smem layout (bytes) for LSTM kernel ----------------------
// fp16 tiles, 64 cols per row = 128B row stride, XOR swizzle on 8x16B chunks
#define SM_AH    0          // h hi [128x64] 16 KB (single buffer, barrier-sep)
#define SM_AL    16384
#define SM_XHI   32768      // x operand
#define SM_XLO   49152
#define SM_BH    65536      // Whh fp16 [256x64] 32 KB
#define SM_BX    98304      // Wih fp16 [256x64] 32 KB
#define SM_ST0   131072     // stage buf0: u32 [C][128] <=28 KB
#define SM_ST1   160256     // stage buf1
#define SM_TOTAL 189440

// ---------------- math helpers ---------------------------------------------
__device__ __forceinline__ float tanh_a(float x) {
    float y; asm("tanh.approx.f32 %0, %1;" : "=f"(y) : "f"(x)); return y;
}
__device__ __forceinline__ float sigm_a(float x) {
    return fmaf(0.5f, tanh_a(0.5f * x), 0.5f);
}
// fp16 split: v = hi + lo (hi = rn(v), lo = rn(v - hi))
__device__ __forceinline__ u32 pack_split(float v) {
    __half h = __float2half_rn(v);
    float r = v - __half2float(h);
    __half l = __float2half_rn(r);
    u32 hb = (u32)__half_as_ushort(h);
    u32 lb = (u32)__half_as_ushort(l);
    return (hb << 16) | lb;
}

// ---------------- PTX helpers -----------------------------------------------
__device__ __forceinline__ u32 smem_u32(const void* p) {
    u32 a;
    asm("{ .reg .u64 t; cvta.to.shared.u64 t, %1; cvt.u32.u64 %0, t; }" : "=r"(a) : "l"(p));
    return a;
}
__device__ __forceinline__ void cp_async16(char* smem_dst, const void* gsrc) {
    u32 sa = smem_u32(smem_dst);
    asm volatile("cp.async.ca.shared.global [%0], [%1], 16;\n" :: "r"(sa), "l"(gsrc));
}
__device__ __forceinline__ void cp_commit()   { asm volatile("cp.async.commit_group;\n"); }
__device__ __forceinline__ void cp_wait_all() { asm volatile("cp.async.wait_all;\n"); }

__device__ __forceinline__ void ldsm4(u32& r0, u32& r1, u32& r2, u32& r3, u32 addr) {
    asm volatile("ldmatrix.sync.aligned.m8n8.x4.shared.b16 {%0,%1,%2,%3}, [%4];"
                 : "=r"(r0), "=r"(r1), "=r"(r2), "=r"(r3) : "r"(addr));
}
__device__ __forceinline__ void mma_fp16(float& d0, float& d1, float& d2, float& d3,
                                         u32 a0, u32 a1, u32 a2, u32 a3,
                                         u32 b0, u32 b1) {
    asm volatile("mma.sync.aligned.m16n8k16.row.col.f32.f16.f16.f32 "
                 "{%0,%1,%2,%3}, {%4,%5,%6,%7}, {%8,%9}, {%0,%1,%2,%3};"
                 : "+f"(d0), "+f"(d1), "+f"(d2), "+f"(d3)
                 : "r"(a0), "r"(a1), "r"(a2), "r"(a3), "r"(b0), "r"(b1));
}

// row stride 128B, 16B chunk index ^= (row&7)
__device__ __forceinline__ u32 swz(u32 row, u32 chunk) {
    return row * 128u + ((chunk ^ (row & 7u)) << 4);
}

// B row permutation: gate-quad-aligned fragment ownership
__device__ __forceinline__ int brow(int g) {
    int q = g >> 6, j = g & 63;
    int warpN = j >> 4, jl = j & 15;
    int hi = jl >> 3, a = (jl & 7) >> 1, e = jl & 1;
    return warpN * 64 + 8 * (q + 4 * hi) + 2 * a + e;
}

// ---------------- kernel 1: transpose+split [N][C][T] -> [T][C][N] u32 ------
__global__ void athx_transpose_kernel(const float* __restrict__ in, int C, int which) {
    __shared__ float tile[32][33];
    u32* out = which ? g_xt_wrf : g_xt_obs;
    const int c  = blockIdx.z;
    const int n0 = blockIdx.x * 32;
    const int t0 = blockIdx.y * 32;
    const int tx = threadIdx.x, ty = threadIdx.y;
    #pragma unroll
    for (int r = 0; r < 4; ++r) {
        int n = n0 + ty + r * 8;
        int t = t0 + tx;
        if (t < TSTEPS)
            tile[ty + r * 8][tx] = in[((size_t)n * C + c) * TSTEPS + t];
    }
    __syncthreads();
    #pragma unroll
    for (int r = 0; r < 4; ++r) {
        int t = t0 + ty + r * 8;
        int n = n0 + tx;
        if (t < TSTEPS)
            out[((size_t)t * C + c) * NS + n] = pack_split(tile[tx][ty + r * 8]);
    }
}

// ---------------- kernel 2: HMMA dual-LSTM, fp16 2-product, tail-x overlap --
__global__ __launch_bounds__(512, 1)
void athx_lstm_mma(const float* __restrict__ oWih, const float* __restrict__ oWhh,
                   const float* __restrict__ obih, const float* __restrict__ obhh,
                   const float* __restrict__ wWih, const float* __restrict__ wWhh,
                   const float* __restrict__ wbih, const float* __restrict__ wbhh)
{
    extern __shared__ char smem[];
    const bool wrf = (blockIdx.x >= 64);
    const int  C   = wrf ? 56 : 32;
    const int  CP  = C >> 1;              // channel pairs
    const int  KCX = wrf ? 4 : 2;         // x k-chunks (16 cols each)
    const u32* xt = wrf ? g_xt_wrf : g_xt_obs;
    const float* Wih = wrf ? wWih : oWih;
    const float* Whh = wrf ? wWhh : oWhh;
    const float* bih = wrf ? wbih : obih;
    const float* bhh = wrf ? wbhh : obhh;
    const int n0  = (blockIdx.x & 63) * 128;
    const int tid = threadIdx.x;
    const int wid = tid >> 5;
    const int lane = tid & 31;
    const int warpM = wid >> 2;
    const int warpN = wid & 3;

    const u32 smb = smem_u32(smem);
    const int NCHUNK = C * 32;           // 16B chunks per x tile

    // conflict-aware stage -> xbuf copy: lanes over samples, u32 channel pairs
#define XCOPY(STG_OFF)                                                           \
    {                                                                            \
        const u32* stg = (const u32*)(smem + (STG_OFF));                         \
        for (int i = tid; i < CP * 128; i += 512) {                              \
            int s = i & 127, cp = i >> 7;                                        \
            u32 p0 = stg[(2 * cp) * 128 + s];                                    \
            u32 p1 = stg[(2 * cp + 1) * 128 + s];                                \
            u32 hi = (p0 >> 16) | (p1 & 0xFFFF0000u);                            \
            u32 lo = (p0 & 0xFFFFu) | (p1 << 16);                                \
            u32 off = swz((u32)s, (u32)(cp >> 2)) + (cp & 3) * 4;                \
            *(u32*)(smem + SM_XHI + off) = hi;                                   \
            *(u32*)(smem + SM_XLO + off) = lo;                                   \
        }                                                                        \
    }

#define XFETCH(TIDX, STG_OFF)                                                    \
    {                                                                            \
        const u32* src = xt + (size_t)(TIDX) * C * NS;                           \
        char* dst = smem + (STG_OFF);                                            \
        for (int i = tid; i < NCHUNK; i += 512) {                                \
            int ch = i >> 5, v = i & 31;                                         \
            cp_async16(dst + (ch * 128 + v * 4) * 4,                             \
                       src + (size_t)ch * NS + n0 + v * 4);                      \
        }                                                                        \
        cp_commit();                                                             \
    }

    // ---- prefetch x_0 into stage0 ----
    XFETCH(0, SM_ST0)

    // ---- zero h/x/B tiles [0, 131072) ----
    for (int i = tid; i < 131072 / 16; i += 512)
        ((uint4*)smem)[i] = make_uint4(0, 0, 0, 0);
    __syncthreads();

    // ---- fill B_h (Whh fp16), B_x (Wih fp16) ----
    for (int i = tid; i < 256 * 64; i += 512) {
        int g = i >> 6, k = i & 63;
        u32 off = swz((u32)brow(g), (u32)(k >> 3)) + (k & 7) * 2;
        *(__half*)(smem + SM_BH + off) = __float2half_rn(Whh[i]);
    }
    for (int i = tid; i < 256 * C; i += 512) {
        int g = i / C, ch = i - g * C;
        u32 off = swz((u32)brow(g), (u32)(ch >> 3)) + (ch & 7) * 2;
        *(__half*)(smem + SM_BX + off) = __float2half_rn(Wih[i]);
    }

    // ---- bias into registers (per-thread 16 gates) ----
    const int jbase = warpN * 16 + (lane & 3) * 2;
    float breg[16];
    #pragma unroll
    for (int q = 0; q < 4; ++q)
        #pragma unroll
        for (int h2 = 0; h2 < 2; ++h2)
            #pragma unroll
            for (int e = 0; e < 2; ++e) {
                int g = q * 64 + jbase + h2 * 8 + e;
                breg[q * 4 + h2 * 2 + e] = bih[g] + bhh[g];
            }

    // ---- x_0 stage -> xbuf; prefetch x_1 into stage1 ----
    cp_wait_all();
    __syncthreads();    // stage0 from all threads + B fills + zeros visible
    XCOPY(SM_ST0)
    __syncthreads();    // xbuf(x_0) visible everywhere
    XFETCH(1, SM_ST1)

    // ---- per-thread ldmatrix geometry ----
    const int g8 = lane >> 3, l = lane & 7;
    const u32 aRow = (u32)(warpM * 32 + (g8 & 1) * 8 + l);
    const u32 bRow = (u32)(warpN * 64 + ((g8 >> 1) & 1) * 8 + l);
    const u32 gAc = (u32)(g8 >> 1);
    const u32 gBc = (u32)(g8 & 1);
    const u32 lx = (u32)l;
    const u32 aHiB = smb + SM_AH + aRow * 128;
    const u32 aLoB = smb + SM_AL + aRow * 128;
    const u32 xHiB = smb + SM_XHI + aRow * 128;
    const u32 xLoB = smb + SM_XLO + aRow * 128;
    const u32 bhB  = smb + SM_BH + bRow * 128;
    const u32 bxB  = smb + SM_BX + bRow * 128;

    float acc[2][8][4];
    float cst[16];
    #pragma unroll
    for (int i = 0; i < 16; ++i) cst[i] = 0.0f;

    // 2-product mma pass: (ahi + alo) . B, accumulating into acc
#define MMA2(AHI_B, ALO_B, B_B, KC)                                                     \
    for (int ks = 0; ks < (KC); ++ks) {                                                 \
        u32 ah[8], al[8];                                                               \
        u32 ca = ((2u * ks + gAc) ^ lx) << 4;                                           \
        ldsm4(ah[0], ah[1], ah[2], ah[3], (AHI_B) + ca);                                \
        ldsm4(ah[4], ah[5], ah[6], ah[7], (AHI_B) + 2048 + ca);                         \
        ldsm4(al[0], al[1], al[2], al[3], (ALO_B) + ca);                                \
        ldsm4(al[4], al[5], al[6], al[7], (ALO_B) + 2048 + ca);                         \
        u32 cb = ((2u * ks + gBc) ^ lx) << 4;                                           \
        _Pragma("unroll")                                                               \
        for (int ntp = 0; ntp < 4; ++ntp) {                                             \
            u32 b0, b1, b2, b3;                                                         \
            ldsm4(b0, b1, b2, b3, (B_B) + ntp * 2048 + cb);                             \
            _Pragma("unroll")                                                           \
            for (int mt = 0; mt < 2; ++mt) {                                            \
                mma_fp16(acc[mt][2*ntp][0], acc[mt][2*ntp][1], acc[mt][2*ntp][2], acc[mt][2*ntp][3], \
                         ah[4*mt], ah[4*mt+1], ah[4*mt+2], ah[4*mt+3], b0, b1);         \
                mma_fp16(acc[mt][2*ntp+1][0], acc[mt][2*ntp+1][1], acc[mt][2*ntp+1][2], acc[mt][2*ntp+1][3], \
                         ah[4*mt], ah[4*mt+1], ah[4*mt+2], ah[4*mt+3], b2, b3);         \
                mma_fp16(acc[mt][2*ntp][0], acc[mt][2*ntp][1], acc[mt][2*ntp][2], acc[mt][2*ntp][3], \
                         al[4*mt], al[4*mt+1], al[4*mt+2], al[4*mt+3], b0, b1);         \
                mma_fp16(acc[mt][2*ntp+1][0], acc[mt][2*ntp+1][1], acc[mt][2*ntp+1][2], acc[mt][2*ntp+1][3], \
                         al[4*mt], al[4*mt+1], al[4*mt+2], al[4*mt+3], b2, b3);         \
            }                                                                           \
        }                                                                               \
    }

#define ZERO_ACC()                                                                      \
    _Pragma("unroll")                                                                   \
    for (int mt = 0; mt < 2; ++mt)                                                      \
        _Pragma("unroll")                                                               \
        for (int nt = 0; nt < 8; ++nt)                                                  \
            _Pragma("unroll")                                                           \
            for (int r = 0; r < 4; ++r) acc[mt][nt][r] = 0.0f;

    // ---- prologue x-mma: acc = Xpart_0 ----
    ZERO_ACC()
    MMA2(xHiB, xLoB, bxB, KCX)

    for (int t = 0; t < TSTEPS; ++t) {
        __syncthreads();   // sync1: h STS from t-1 visible; stage slot free

        // h-part: acc += h_{t-1} . Whh^T
        MMA2(aHiB, aLoB, bhB, 4)

        // epilogue
        float hval[16];
        #pragma unroll
        for (int mt = 0; mt < 2; ++mt)
            #pragma unroll
            for (int d = 0; d < 2; ++d)
                #pragma unroll
                for (int h2 = 0; h2 < 2; ++h2)
                    #pragma unroll
                    for (int e = 0; e < 2; ++e) {
                        int r = 2 * d + e;
                        int ci = ((mt * 2 + d) * 2 + h2) * 2 + e;
                        int bi = h2 * 2 + e;
                        float gi = sigm_a(acc[mt][4*h2 + 0][r] + breg[bi]);
                        float gf = sigm_a(acc[mt][4*h2 + 1][r] + breg[4 + bi]);
                        float gg = tanh_a(acc[mt][4*h2 + 2][r] + breg[8 + bi]);
                        float go = sigm_a(acc[mt][4*h2 + 3][r] + breg[12 + bi]);
                        float cc = fmaf(gf, cst[ci], gi * gg);
                        cst[ci] = cc;
                        hval[ci] = go * tanh_a(cc);
                    }

        cp_wait_all();     // own x_{t+1} chunks landed (issued last window)
        __syncthreads();   // sync2: all x_{t+1} staged; h-mma reads done

        if (t == TSTEPS - 1) {
            const int off = wrf ? 64 : 0;
            #pragma unroll
            for (int mt = 0; mt < 2; ++mt)
                #pragma unroll
                for (int d = 0; d < 2; ++d)
                    #pragma unroll
                    for (int h2 = 0; h2 < 2; ++h2)
                        #pragma unroll
                        for (int e = 0; e < 2; ++e) {
                            int s = warpM * 32 + mt * 16 + (lane >> 2) + 8 * d;
                            int j = warpN * 16 + h2 * 8 + (lane & 3) * 2 + e;
                            int ci = ((mt * 2 + d) * 2 + h2) * 2 + e;
                            g_featT[(size_t)(off + j) * NS + n0 + s] = hval[ci];
                        }
        } else {
            // copy staged x_{t+1} -> xbuf  (slot (t+1)&1)
            XCOPY(((t + 1) & 1) ? SM_ST1 : SM_ST0)
            // STS h_t -> hbuf (fp16 hi/lo)
            #pragma unroll
            for (int mt = 0; mt < 2; ++mt)
                #pragma unroll
                for (int d = 0; d < 2; ++d)
                    #pragma unroll
                    for (int h2 = 0; h2 < 2; ++h2) {
                        int ci = ((mt * 2 + d) * 2 + h2) * 2;
                        float h0 = hval[ci], h1 = hval[ci + 1];
                        __half hh0 = __float2half_rn(h0);
                        __half hh1 = __float2half_rn(h1);
                        __half hl0 = __float2half_rn(h0 - __half2float(hh0));
                        __half hl1 = __float2half_rn(h1 - __half2float(hh1));
                        u32 hi32 = (u32)__half_as_ushort(hh0) | ((u32)__half_as_ushort(hh1) << 16);
                        u32 lo32 = (u32)__half_as_ushort(hl0) | ((u32)__half_as_ushort(hl1) << 16);
                        u32 s  = (u32)(warpM * 32 + mt * 16 + (lane >> 2) + 8 * d);
                        u32 jp = (u32)(warpN * 16 + h2 * 8 + (lane & 3) * 2);
                        u32 off = swz(s, jp >> 3) + (jp & 7) * 2;
                        *(u32*)(smem + SM_AH + off) = hi32;
                        *(u32*)(smem + SM_AL + off) = lo32;
                    }
            // prefetch x_{t+2} into slot (t)&1 (freed: its x_t copied last window)
            if (t + 2 < TSTEPS) {
                XFETCH(t + 2, (t & 1) ? SM_ST1 : SM_ST0)
            }
            __syncthreads();   // sync3: xbuf(x_{t+1}) visible
            // tail x-mma for t+1 — overlaps other warps' epilogue/copy phases
            ZERO_ACC()
            MMA2(xHiB, xLoB, bxB, KCX)
        }
    }
#undef MMA2
#undef ZERO_ACC
#undef XCOPY
#undef XFETCH
}

// ---------------- kernel 3: MLP heads (unchanged, passing since R1) ---------
#define SPAD 132
__device__ __forceinline__ u64 dup2(float x) {
    u64 r; asm("mov.b64 %0, {%1,%1};" : "=l"(r) : "f"(x)); return r;
}
__device__ __forceinline__ void unpack2(u64 v, float& x, float& y) {
    asm("mov.b64 {%0,%1}, %2;" : "=f"(x), "=f"(y) : "l"(v));
}
__device__ __forceinline__ u64 ffma2(u64 a, u64 b, u64 c) {
    u64 d; asm("fma.rn.f32x2 %0, %1, %2, %3;" : "=l"(d) : "l"(a), "l"(b), "l"(c)); return d;
}

template <int IN, int OUT, bool RELU>
__device__ __forceinline__ void athx_layer(const float* __restrict__ A,
                                           const float* __restrict__ wt,
                                           const float* __restrict__ bs,
                                           float* __restrict__ Bout,
                                           int gx, int sx) {
    constexpr int R = OUT / 16;
    u64 acc2[4][R];
    #pragma unroll
    for (int sp = 0; sp < 4; ++sp)
        #pragma unroll
        for (int r = 0; r < R; ++r) acc2[sp][r] = 0ull;
    for (int k = 0; k < IN; ++k) {
        ulonglong2 p0 = *(const ulonglong2*)(A + k * SPAD + sx * 8);
        ulonglong2 p1 = *(const ulonglong2*)(A + k * SPAD + sx * 8 + 4);
        u64 a2[4] = {p0.x, p0.y, p1.x, p1.y};
        #pragma unroll
        for (int r = 0; r < R; ++r) {
            u64 b2 = dup2(wt[k * OUT + gx + 16 * r]);
            #pragma unroll
            for (int sp = 0; sp < 4; ++sp) acc2[sp][r] = ffma2(a2[sp], b2, acc2[sp][r]);
        }
    }
    #pragma unroll
    for (int r = 0; r < R; ++r) {
        int u = gx + 16 * r;
        float bb = bs[u];
        float hv[8];
        #pragma unroll
        for (int sp = 0; sp < 4; ++sp) {
            float v0, v1;
            unpack2(acc2[sp][r], v0, v1);
            v0 += bb; v1 += bb;
            hv[2 * sp]     = RELU ? fmaxf(v0, 0.0f) : v0;
            hv[2 * sp + 1] = RELU ? fmaxf(v1, 0.0f) : v1;
        }
        *(float4*)(Bout + u * SPAD + sx * 8)     = make_float4(hv[0], hv[1], hv[2], hv[3]);
        *(float4*)(Bout + u * SPAD + sx * 8 + 4) = make_float4(hv[4], hv[5], hv[6], hv[7]);
    }
}

__global__ __launch_bounds__(256, 1) void athx_head_kernel(
    const float* __restrict__ fW1, const float* __restrict__ fb1,
    const float* __restrict__ fW2, const float* __restrict__ fb2,
    const float* __restrict__ fW3, const float* __restrict__ fb3,
    const float* __restrict__ oW1, const float* __restrict__ ob1,
    const float* __restrict__ oW2, const float* __restrict__ ob2,
    const float* __restrict__ oW3, const float* __restrict__ ob3,
    float* __restrict__ out)
{
    extern __shared__ float sm[];
    float* A   = sm;
    float* B   = A + 128 * SPAD;
    float* w1t = B + 96 * SPAD;
    float* w2t = w1t + 128 * 96;
    float* w3t = w2t + 96 * 64;
    float* bs1 = w3t + 64 * 48;
    float* bs2 = bs1 + 96;
    float* bs3 = bs2 + 64;

    const int head = blockIdx.y;
    const float* W1 = head ? oW1 : fW1; const float* b1 = head ? ob1 : fb1;
    const float* W2 = head ? oW2 : fW2; const float* b2 = head ? ob2 : fb2;
    const float* W3 = head ? oW3 : fW3; const float* b3 = head ? ob3 : fb3;
    const int n0  = blockIdx.x * 128;
    const int tid = threadIdx.x;
    const int gx  = tid & 15, sx = tid >> 4;

    for (int idx = tid; idx < 128 * 128; idx += 256) {
        int k = idx >> 7, s = idx & 127;
        A[k * SPAD + s] = g_featT[(size_t)k * NS + n0 + s];
    }
    for (int idx = tid; idx < 96 * 128; idx += 256) {
        int u = idx >> 7, k = idx & 127;
        w1t[k * 96 + u] = W1[idx];
    }
    for (int idx = tid; idx < 64 * 96; idx += 256) {
        int u = idx / 96, k = idx - u * 96;
        w2t[k * 64 + u] = W2[idx];
    }
    for (int idx = tid; idx < 48 * 64; idx += 256) {
        int u = idx >> 6, k = idx & 63;
        w3t[k * 48 + u] = W3[idx];
    }
    if (tid < 96) bs1[tid] = b1[tid];
    if (tid < 64) bs2[tid] = b2[tid];
    if (tid < 48) bs3[tid] = b3[tid];
    __syncthreads();

    athx_layer<128, 96, true>(A, w1t, bs1, B, gx, sx);
    __syncthreads();
    athx_layer<96, 64, true>(B, w2t, bs2, A, gx, sx);
    __syncthreads();

    {
        u64 acc2[4][3];
        #pragma unroll
        for (int sp = 0; sp < 4; ++sp)
            #pragma unroll
            for (int r = 0; r < 3; ++r) acc2[sp][r] = 0ull;
        for (int k = 0; k < 64; ++k) {
            ulonglong2 p0 = *(const ulonglong2*)(A + k * SPAD + sx * 8);
            ulonglong2 p1 = *(const ulonglong2*)(A + k * SPAD + sx * 8 + 4);
            u64 a2[4] = {p0.x, p0.y, p1.x, p1.y};
            #pragma unroll
            for (int r = 0; r < 3; ++r) {
                u64 b2 = dup2(w3t[k * 48 + gx + 16 * r]);
                #pragma unroll
                for (int sp = 0; sp < 4; ++sp) acc2[sp][r] = ffma2(a2[sp], b2, acc2[sp][r]);
            }
        }
        #pragma unroll
        for (int r = 0; r < 3; ++r) {
            int u = gx + 16 * r;
            float bb = bs3[u];
            #pragma unroll
            for (int sp = 0; sp < 4; ++sp) {
                float v0, v1;
                unpack2(acc2[sp][r], v0, v1);
                int n = n0 + sx * 8 + 2 * sp;
                out[(size_t)n * 96 + head * 48 + u]       = v0 + bb;
                out[(size_t)(n + 1) * 96 + head * 48 + u] = v1 + bb;
            }
        }
    }
}

// ---------------- launch ----------------------------------------------------
extern "C" void kernel_launch(void* const* d_in, const int* in_sizes, int n_in,
                              void* d_out, int out_size) {
    const float* X_obs  = (const float*)d_in[0];
    const float* X_wrf  = (const float*)d_in[1];
    const float* oWih   = (const float*)d_in[2];
    const float* oWhh   = (const float*)d_in[3];
    const float* obih   = (const float*)d_in[4];
    const float* obhh   = (const float*)d_in[5];
    const float* wWih   = (const float*)d_in[6];
    const float* wWhh   = (const float*)d_in[7];
    const float* wbih   = (const float*)d_in[8];
    const float* wbhh   = (const float*)d_in[9];
    const float* fW1 = (const float*)d_in[10]; const float* fb1 = (const float*)d_in[11];
    const float* fW2 = (const float*)d_in[12]; const float* fb2 = (const float*)d_in[13];
    const float* fW3 = (const float*)d_in[14]; const float* fb3 = (const float*)d_in[15];
    const float* oW1 = (const float*)d_in[16]; const float* ob1 = (const float*)d_in[17];
    const float* oW2 = (const float*)d_in[18]; const float* ob2 = (const float*)d_in[19];
    const float* oW3 = (const float*)d_in[20]; const float* ob3 = (const float*)d_in[21];
    float* out = (float*)d_out;

    const int HEAD_SMEM = (128 * SPAD + 96 * SPAD + 128 * 96 + 96 * 64 + 64 * 48
                           + 96 + 64 + 48) * 4;
    cudaFuncSetAttribute(athx_lstm_mma, cudaFuncAttributeMaxDynamicSharedMemorySize, SM_TOTAL);
    cudaFuncSetAttribute(athx_head_kernel, cudaFuncAttributeMaxDynamicSharedMemorySize, HEAD_SMEM);

    athx_transpose_kernel<<<dim3(NS / 32, 3, 32), dim3(32, 8)>>>(X_obs, 32, 0);
    athx_transpose_kernel<<<dim3(NS / 32, 3, 56), dim3(32, 8)>>>(X_wrf, 56, 1);

    athx_lstm_mma<<<128, 512, SM_TOTAL>>>(oWih, oWhh, obih, obhh,
                                          wWih, wWhh, wbih, wbhh);

    athx_head_kernel<<<dim3(NS / 128, 2), 256, HEAD_SMEM>>>(
        fW1, fb1, fW2, fb2, fW3, fb3,
        oW1, ob1, oW2, ob2, oW3, ob3, out);
}

// round 8
// speedup vs baseline: 3.4910x; 1.4125x over previous
#include <cuda_runtime.h>
#include <cuda_fp16.h>
#include <cstdint>

#define NS     8192
#define TSTEPS 72

typedef unsigned long long u64;
typedef unsigned int       u32;
typedef unsigned short     u16;

// ---------------- scratch (device globals; no allocation allowed) ----------
__device__ u16   g_xt_obs[TSTEPS * 32 * NS];   // [T][C1][N] fp16
__device__ u16   g_xt_wrf[TSTEPS * 56 * NS];   // [T][C2][N] fp16
__device__ float g_featT[128 * NS];            // [128][N]

// ---------------- smem layout (bytes) for LSTM kernel ----------------------
// fp16 tiles, 64 cols per row = 128B row stride, XOR swizzle on 8x16B chunks
#define SM_AH    0          // h [128x64] fp16, 16 KB
#define SM_XH    16384      // x [128x64] fp16, 16 KB
#define SM_BH    32768      // Whh [256x64] fp16, 32 KB
#define SM_BX    65536      // Wih [256x64] fp16, 32 KB
#define SM_ST0   98304      // stage buf0: half [C][128] <=14 KB
#define SM_ST1   112640     // stage buf1
#define SM_TOTAL 126976

// ---------------- math helpers ---------------------------------------------
__device__ __forceinline__ float tanh_a(float x) {
    float y; asm("tanh.approx.f32 %0, %1;" : "=f"(y) : "f"(x)); return y;
}
__device__ __forceinline__ float sigm_a(float x) {
    return fmaf(0.5f, tanh_a(0.5f * x), 0.5f);
}

// ---------------- PTX helpers -----------------------------------------------
__device__ __forceinline__ u32 smem_u32(const void* p) {
    u32 a;
    asm("{ .reg .u64 t; cvta.to.shared.u64 t, %1; cvt.u32.u64 %0, t; }" : "=r"(a) : "l"(p));
    return a;
}
__device__ __forceinline__ void cp_async16(char* smem_dst, const void* gsrc) {
    u32 sa = smem_u32(smem_dst);
    asm volatile("cp.async.ca.shared.global [%0], [%1], 16;\n" :: "r"(sa), "l"(gsrc));
}
__device__ __forceinline__ void cp_commit()   { asm volatile("cp.async.commit_group;\n"); }
__device__ __forceinline__ void cp_wait_all() { asm volatile("cp.async.wait_all;\n"); }

__device__ __forceinline__ void ldsm4(u32& r0, u32& r1, u32& r2, u32& r3, u32 addr) {
    asm volatile("ldmatrix.sync.aligned.m8n8.x4.shared.b16 {%0,%1,%2,%3}, [%4];"
                 : "=r"(r0), "=r"(r1), "=r"(r2), "=r"(r3) : "r"(addr));
}
__device__ __forceinline__ void mma_fp16(float& d0, float& d1, float& d2, float& d3,
                                         u32 a0, u32 a1, u32 a2, u32 a3,
                                         u32 b0, u32 b1) {
    asm volatile("mma.sync.aligned.m16n8k16.row.col.f32.f16.f16.f32 "
                 "{%0,%1,%2,%3}, {%4,%5,%6,%7}, {%8,%9}, {%0,%1,%2,%3};"
                 : "+f"(d0), "+f"(d1), "+f"(d2), "+f"(d3)
                 : "r"(a0), "r"(a1), "r"(a2), "r"(a3), "r"(b0), "r"(b1));
}

// row stride 128B, 16B chunk index ^= (row&7)
__device__ __forceinline__ u32 swz(u32 row, u32 chunk) {
    return row * 128u + ((chunk ^ (row & 7u)) << 4);
}

// B row permutation: gate-quad-aligned fragment ownership
__device__ __forceinline__ int brow(int g) {
    int q = g >> 6, j = g & 63;
    int warpN = j >> 4, jl = j & 15;
    int hi = jl >> 3, a = (jl & 7) >> 1, e = jl & 1;
    return warpN * 64 + 8 * (q + 4 * hi) + 2 * a + e;
}

// ---------------- kernel 1: transpose [N][C][T] -> [T][C][N] fp16 -----------
__global__ void athx_transpose_kernel(const float* __restrict__ in, int C, int which) {
    __shared__ float tile[32][33];
    u16* out = which ? g_xt_wrf : g_xt_obs;
    const int c  = blockIdx.z;
    const int n0 = blockIdx.x * 32;
    const int t0 = blockIdx.y * 32;
    const int tx = threadIdx.x, ty = threadIdx.y;
    #pragma unroll
    for (int r = 0; r < 4; ++r) {
        int n = n0 + ty + r * 8;
        int t = t0 + tx;
        if (t < TSTEPS)
            tile[ty + r * 8][tx] = in[((size_t)n * C + c) * TSTEPS + t];
    }
    __syncthreads();
    #pragma unroll
    for (int r = 0; r < 4; ++r) {
        int t = t0 + ty + r * 8;
        int n = n0 + tx;
        if (t < TSTEPS)
            out[((size_t)t * C + c) * NS + n] =
                __half_as_ushort(__float2half_rn(tile[tx][ty + r * 8]));
    }
}

// ---------------- kernel 2: HMMA dual-LSTM, pure fp16, tail-x overlap -------
__global__ __launch_bounds__(512, 1)
void athx_lstm_mma(const float* __restrict__ oWih, const float* __restrict__ oWhh,
                   const float* __restrict__ obih, const float* __restrict__ obhh,
                   const float* __restrict__ wWih, const float* __restrict__ wWhh,
                   const float* __restrict__ wbih, const float* __restrict__ wbhh)
{
    extern __shared__ char smem[];
    const bool wrf = (blockIdx.x >= 64);
    const int  C   = wrf ? 56 : 32;
    const int  CP  = C >> 1;              // channel pairs
    const int  KCX = wrf ? 4 : 2;         // x k-chunks (16 cols each)
    const u16* xt = wrf ? g_xt_wrf : g_xt_obs;
    const float* Wih = wrf ? wWih : oWih;
    const float* Whh = wrf ? wWhh : oWhh;
    const float* bih = wrf ? wbih : obih;
    const float* bhh = wrf ? wbhh : obhh;
    const int n0  = (blockIdx.x & 63) * 128;
    const int tid = threadIdx.x;
    const int wid = tid >> 5;
    const int lane = tid & 31;
    const int warpM = wid >> 2;
    const int warpN = wid & 3;

    const u32 smb = smem_u32(smem);
    const int NCHUNK = C * 16;           // 16B chunks per x tile (8 halves each)

    // conflict-aware stage -> xbuf copy: lanes over samples, u32 channel pairs
#define XCOPY(STG_OFF)                                                           \
    {                                                                            \
        const u16* stg = (const u16*)(smem + (STG_OFF));                         \
        for (int i = tid; i < CP * 128; i += 512) {                              \
            int s = i & 127, cp = i >> 7;                                        \
            u32 h0 = (u32)stg[(2 * cp) * 128 + s];                               \
            u32 h1 = (u32)stg[(2 * cp + 1) * 128 + s];                           \
            u32 off = swz((u32)s, (u32)(cp >> 2)) + (cp & 3) * 4;                \
            *(u32*)(smem + SM_XH + off) = h0 | (h1 << 16);                       \
        }                                                                        \
    }

#define XFETCH(TIDX, STG_OFF)                                                    \
    {                                                                            \
        const u16* src = xt + (size_t)(TIDX) * C * NS;                           \
        char* dst = smem + (STG_OFF);                                            \
        for (int i = tid; i < NCHUNK; i += 512) {                                \
            int ch = i >> 4, v = i & 15;                                         \
            cp_async16(dst + (ch * 128 + v * 8) * 2,                             \
                       src + (size_t)ch * NS + n0 + v * 8);                      \
        }                                                                        \
        cp_commit();                                                             \
    }

    // ---- prefetch x_0 into stage0 ----
    XFETCH(0, SM_ST0)

    // ---- zero h/x/B tiles [0, 98304) ----
    for (int i = tid; i < 98304 / 16; i += 512)
        ((uint4*)smem)[i] = make_uint4(0, 0, 0, 0);
    __syncthreads();

    // ---- fill B_h (Whh fp16), B_x (Wih fp16) ----
    for (int i = tid; i < 256 * 64; i += 512) {
        int g = i >> 6, k = i & 63;
        u32 off = swz((u32)brow(g), (u32)(k >> 3)) + (k & 7) * 2;
        *(__half*)(smem + SM_BH + off) = __float2half_rn(Whh[i]);
    }
    for (int i = tid; i < 256 * C; i += 512) {
        int g = i / C, ch = i - g * C;
        u32 off = swz((u32)brow(g), (u32)(ch >> 3)) + (ch & 7) * 2;
        *(__half*)(smem + SM_BX + off) = __float2half_rn(Wih[i]);
    }

    // ---- bias into registers (per-thread 16 gates) ----
    const int jbase = warpN * 16 + (lane & 3) * 2;
    float breg[16];
    #pragma unroll
    for (int q = 0; q < 4; ++q)
        #pragma unroll
        for (int h2 = 0; h2 < 2; ++h2)
            #pragma unroll
            for (int e = 0; e < 2; ++e) {
                int g = q * 64 + jbase + h2 * 8 + e;
                breg[q * 4 + h2 * 2 + e] = bih[g] + bhh[g];
            }

    // ---- x_0 stage -> xbuf; prefetch x_1 into stage1 ----
    cp_wait_all();
    __syncthreads();    // stage0 from all threads + B fills + zeros visible
    XCOPY(SM_ST0)
    __syncthreads();    // xbuf(x_0) visible everywhere
    XFETCH(1, SM_ST1)

    // ---- per-thread ldmatrix geometry ----
    const int g8 = lane >> 3, l = lane & 7;
    const u32 aRow = (u32)(warpM * 32 + (g8 & 1) * 8 + l);
    const u32 bRow = (u32)(warpN * 64 + ((g8 >> 1) & 1) * 8 + l);
    const u32 gAc = (u32)(g8 >> 1);
    const u32 gBc = (u32)(g8 & 1);
    const u32 lx = (u32)l;
    const u32 aB  = smb + SM_AH + aRow * 128;
    const u32 xB  = smb + SM_XH + aRow * 128;
    const u32 bhB = smb + SM_BH + bRow * 128;
    const u32 bxB = smb + SM_BX + bRow * 128;

    float acc[2][8][4];
    float cst[16];
    #pragma unroll
    for (int i = 0; i < 16; ++i) cst[i] = 0.0f;

    // single-product fp16 mma pass: A . B
#define MMA1(A_B, B_B, KC)                                                              \
    for (int ks = 0; ks < (KC); ++ks) {                                                 \
        u32 a[8];                                                                       \
        u32 ca = ((2u * ks + gAc) ^ lx) << 4;                                           \
        ldsm4(a[0], a[1], a[2], a[3], (A_B) + ca);                                      \
        ldsm4(a[4], a[5], a[6], a[7], (A_B) + 2048 + ca);                               \
        u32 cb = ((2u * ks + gBc) ^ lx) << 4;                                           \
        _Pragma("unroll")                                                               \
        for (int ntp = 0; ntp < 4; ++ntp) {                                             \
            u32 b0, b1, b2, b3;                                                         \
            ldsm4(b0, b1, b2, b3, (B_B) + ntp * 2048 + cb);                             \
            _Pragma("unroll")                                                           \
            for (int mt = 0; mt < 2; ++mt) {                                            \
                mma_fp16(acc[mt][2*ntp][0], acc[mt][2*ntp][1], acc[mt][2*ntp][2], acc[mt][2*ntp][3], \
                         a[4*mt], a[4*mt+1], a[4*mt+2], a[4*mt+3], b0, b1);             \
                mma_fp16(acc[mt][2*ntp+1][0], acc[mt][2*ntp+1][1], acc[mt][2*ntp+1][2], acc[mt][2*ntp+1][3], \
                         a[4*mt], a[4*mt+1], a[4*mt+2], a[4*mt+3], b2, b3);             \
            }                                                                           \
        }                                                                               \
    }

#define ZERO_ACC()                                                                      \
    _Pragma("unroll")                                                                   \
    for (int mt = 0; mt < 2; ++mt)                                                      \
        _Pragma("unroll")                                                               \
        for (int nt = 0; nt < 8; ++nt)                                                  \
            _Pragma("unroll")                                                           \
            for (int r = 0; r < 4; ++r) acc[mt][nt][r] = 0.0f;

    // ---- prologue x-mma: acc = Xpart_0 ----
    ZERO_ACC()
    MMA1(xB, bxB, KCX)

    for (int t = 0; t < TSTEPS; ++t) {
        __syncthreads();   // sync1: h STS from t-1 visible; stage slot free

        // h-part: acc += h_{t-1} . Whh^T
        MMA1(aB, bhB, 4)

        // epilogue
        float hval[16];
        #pragma unroll
        for (int mt = 0; mt < 2; ++mt)
            #pragma unroll
            for (int d = 0; d < 2; ++d)
                #pragma unroll
                for (int h2 = 0; h2 < 2; ++h2)
                    #pragma unroll
                    for (int e = 0; e < 2; ++e) {
                        int r = 2 * d + e;
                        int ci = ((mt * 2 + d) * 2 + h2) * 2 + e;
                        int bi = h2 * 2 + e;
                        float gi = sigm_a(acc[mt][4*h2 + 0][r] + breg[bi]);
                        float gf = sigm_a(acc[mt][4*h2 + 1][r] + breg[4 + bi]);
                        float gg = tanh_a(acc[mt][4*h2 + 2][r] + breg[8 + bi]);
                        float go = sigm_a(acc[mt][4*h2 + 3][r] + breg[12 + bi]);
                        float cc = fmaf(gf, cst[ci], gi * gg);
                        cst[ci] = cc;
                        hval[ci] = go * tanh_a(cc);
                    }

        cp_wait_all();     // own x_{t+1} chunks landed (issued last window)
        __syncthreads();   // sync2: all x_{t+1} staged; h-mma reads done

        if (t == TSTEPS - 1) {
            const int off = wrf ? 64 : 0;
            #pragma unroll
            for (int mt = 0; mt < 2; ++mt)
                #pragma unroll
                for (int d = 0; d < 2; ++d)
                    #pragma unroll
                    for (int h2 = 0; h2 < 2; ++h2)
                        #pragma unroll
                        for (int e = 0; e < 2; ++e) {
                            int s = warpM * 32 + mt * 16 + (lane >> 2) + 8 * d;
                            int j = warpN * 16 + h2 * 8 + (lane & 3) * 2 + e;
                            int ci = ((mt * 2 + d) * 2 + h2) * 2 + e;
                            g_featT[(size_t)(off + j) * NS + n0 + s] = hval[ci];
                        }
        } else {
            // copy staged x_{t+1} -> xbuf  (slot (t+1)&1)
            XCOPY(((t + 1) & 1) ? SM_ST1 : SM_ST0)
            // STS h_t -> hbuf (fp16)
            #pragma unroll
            for (int mt = 0; mt < 2; ++mt)
                #pragma unroll
                for (int d = 0; d < 2; ++d)
                    #pragma unroll
                    for (int h2 = 0; h2 < 2; ++h2) {
                        int ci = ((mt * 2 + d) * 2 + h2) * 2;
                        __half hh0 = __float2half_rn(hval[ci]);
                        __half hh1 = __float2half_rn(hval[ci + 1]);
                        u32 hi32 = (u32)__half_as_ushort(hh0) | ((u32)__half_as_ushort(hh1) << 16);
                        u32 s  = (u32)(warpM * 32 + mt * 16 + (lane >> 2) + 8 * d);
                        u32 jp = (u32)(warpN * 16 + h2 * 8 + (lane & 3) * 2);
                        u32 off = swz(s, jp >> 3) + (jp & 7) * 2;
                        *(u32*)(smem + SM_AH + off) = hi32;
                    }
            // prefetch x_{t+2} into slot (t)&1 (freed: its x_t copied last window)
            if (t + 2 < TSTEPS) {
                XFETCH(t + 2, (t & 1) ? SM_ST1 : SM_ST0)
            }
            __syncthreads();   // sync3: xbuf(x_{t+1}) visible
            // tail x-mma for t+1 — overlaps other warps' epilogue/copy phases
            ZERO_ACC()
            MMA1(xB, bxB, KCX)
        }
    }
#undef MMA1
#undef ZERO_ACC
#undef XCOPY
#undef XFETCH
}

// ---------------- kernel 3: MLP heads (unchanged, passing since R1) ---------
#define SPAD 132
__device__ __forceinline__ u64 dup2(float x) {
    u64 r; asm("mov.b64 %0, {%1,%1};" : "=l"(r) : "f"(x)); return r;
}
__device__ __forceinline__ void unpack2(u64 v, float& x, float& y) {
    asm("mov.b64 {%0,%1}, %2;" : "=f"(x), "=f"(y) : "l"(v));
}
__device__ __forceinline__ u64 ffma2(u64 a, u64 b, u64 c) {
    u64 d; asm("fma.rn.f32x2 %0, %1, %2, %3;" : "=l"(d) : "l"(a), "l"(b), "l"(c)); return d;
}

template <int IN, int OUT, bool RELU>
__device__ __forceinline__ void athx_layer(const float* __restrict__ A,
                                           const float* __restrict__ wt,
                                           const float* __restrict__ bs,
                                           float* __restrict__ Bout,
                                           int gx, int sx) {
    constexpr int R = OUT / 16;
    u64 acc2[4][R];
    #pragma unroll
    for (int sp = 0; sp < 4; ++sp)
        #pragma unroll
        for (int r = 0; r < R; ++r) acc2[sp][r] = 0ull;
    for (int k = 0; k < IN; ++k) {
        ulonglong2 p0 = *(const ulonglong2*)(A + k * SPAD + sx * 8);
        ulonglong2 p1 = *(const ulonglong2*)(A + k * SPAD + sx * 8 + 4);
        u64 a2[4] = {p0.x, p0.y, p1.x, p1.y};
        #pragma unroll
        for (int r = 0; r < R; ++r) {
            u64 b2 = dup2(wt[k * OUT + gx + 16 * r]);
            #pragma unroll
            for (int sp = 0; sp < 4; ++sp) acc2[sp][r] = ffma2(a2[sp], b2, acc2[sp][r]);
        }
    }
    #pragma unroll
    for (int r = 0; r < R; ++r) {
        int u = gx + 16 * r;
        float bb = bs[u];
        float hv[8];
        #pragma unroll
        for (int sp = 0; sp < 4; ++sp) {
            float v0, v1;
            unpack2(acc2[sp][r], v0, v1);
            v0 += bb; v1 += bb;
            hv[2 * sp]     = RELU ? fmaxf(v0, 0.0f) : v0;
            hv[2 * sp + 1] = RELU ? fmaxf(v1, 0.0f) : v1;
        }
        *(float4*)(Bout + u * SPAD + sx * 8)     = make_float4(hv[0], hv[1], hv[2], hv[3]);
        *(float4*)(Bout + u * SPAD + sx * 8 + 4) = make_float4(hv[4], hv[5], hv[6], hv[7]);
    }
}

__global__ __launch_bounds__(256, 1) void athx_head_kernel(
    const float* __restrict__ fW1, const float* __restrict__ fb1,
    const float* __restrict__ fW2, const float* __restrict__ fb2,
    const float* __restrict__ fW3, const float* __restrict__ fb3,
    const float* __restrict__ oW1, const float* __restrict__ ob1,
    const float* __restrict__ oW2, const float* __restrict__ ob2,
    const float* __restrict__ oW3, const float* __restrict__ ob3,
    float* __restrict__ out)
{
    extern __shared__ float sm[];
    float* A   = sm;
    float* B   = A + 128 * SPAD;
    float* w1t = B + 96 * SPAD;
    float* w2t = w1t + 128 * 96;
    float* w3t = w2t + 96 * 64;
    float* bs1 = w3t + 64 * 48;
    float* bs2 = bs1 + 96;
    float* bs3 = bs2 + 64;

    const int head = blockIdx.y;
    const float* W1 = head ? oW1 : fW1; const float* b1 = head ? ob1 : fb1;
    const float* W2 = head ? oW2 : fW2; const float* b2 = head ? ob2 : fb2;
    const float* W3 = head ? oW3 : fW3; const float* b3 = head ? ob3 : fb3;
    const int n0  = blockIdx.x * 128;
    const int tid = threadIdx.x;
    const int gx  = tid & 15, sx = tid >> 4;

    for (int idx = tid; idx < 128 * 128; idx += 256) {
        int k = idx >> 7, s = idx & 127;
        A[k * SPAD + s] = g_featT[(size_t)k * NS + n0 + s];
    }
    for (int idx = tid; idx < 96 * 128; idx += 256) {
        int u = idx >> 7, k = idx & 127;
        w1t[k * 96 + u] = W1[idx];
    }
    for (int idx = tid; idx < 64 * 96; idx += 256) {
        int u = idx / 96, k = idx - u * 96;
        w2t[k * 64 + u] = W2[idx];
    }
    for (int idx = tid; idx < 48 * 64; idx += 256) {
        int u = idx >> 6, k = idx & 63;
        w3t[k * 48 + u] = W3[idx];
    }
    if (tid < 96) bs1[tid] = b1[tid];
    if (tid < 64) bs2[tid] = b2[tid];
    if (tid < 48) bs3[tid] = b3[tid];
    __syncthreads();

    athx_layer<128, 96, true>(A, w1t, bs1, B, gx, sx);
    __syncthreads();
    athx_layer<96, 64, true>(B, w2t, bs2, A, gx, sx);
    __syncthreads();

    {
        u64 acc2[4][3];
        #pragma unroll
        for (int sp = 0; sp < 4; ++sp)
            #pragma unroll
            for (int r = 0; r < 3; ++r) acc2[sp][r] = 0ull;
        for (int k = 0; k < 64; ++k) {
            ulonglong2 p0 = *(const ulonglong2*)(A + k * SPAD + sx * 8);
            ulonglong2 p1 = *(const ulonglong2*)(A + k * SPAD + sx * 8 + 4);
            u64 a2[4] = {p0.x, p0.y, p1.x, p1.y};
            #pragma unroll
            for (int r = 0; r < 3; ++r) {
                u64 b2 = dup2(w3t[k * 48 + gx + 16 * r]);
                #pragma unroll
                for (int sp = 0; sp < 4; ++sp) acc2[sp][r] = ffma2(a2[sp], b2, acc2[sp][r]);
            }
        }
        #pragma unroll
        for (int r = 0; r < 3; ++r) {
            int u = gx + 16 * r;
            float bb = bs3[u];
            #pragma unroll
            for (int sp = 0; sp < 4; ++sp) {
                float v0, v1;
                unpack2(acc2[sp][r], v0, v1);
                int n = n0 + sx * 8 + 2 * sp;
                out[(size_t)n * 96 + head * 48 + u]       = v0 + bb;
                out[(size_t)(n + 1) * 96 + head * 48 + u] = v1 + bb;
            }
        }
    }
}

// ---------------- launch ----------------------------------------------------
extern "C" void kernel_launch(void* const* d_in, const int* in_sizes, int n_in,
                              void* d_out, int out_size) {
    const float* X_obs  = (const float*)d_in[0];
    const float* X_wrf  = (const float*)d_in[1];
    const float* oWih   = (const float*)d_in[2];
    const float* oWhh   = (const float*)d_in[3];
    const float* obih   = (const float*)d_in[4];
    const float* obhh   = (const float*)d_in[5];
    const float* wWih   = (const float*)d_in[6];
    const float* wWhh   = (const float*)d_in[7];
    const float* wbih   = (const float*)d_in[8];
    const float* wbhh   = (const float*)d_in[9];
    const float* fW1 = (const float*)d_in[10]; const float* fb1 = (const float*)d_in[11];
    const float* fW2 = (const float*)d_in[12]; const float* fb2 = (const float*)d_in[13];
    const float* fW3 = (const float*)d_in[14]; const float* fb3 = (const float*)d_in[15];
    const float* oW1 = (const float*)d_in[16]; const float* ob1 = (const float*)d_in[17];
    const float* oW2 = (const float*)d_in[18]; const float* ob2 = (const float*)d_in[19];
    const float* oW3 = (const float*)d_in[20]; const float* ob3 = (const float*)d_in[21];
    float* out = (float*)d_out;

    const int HEAD_SMEM = (128 * SPAD + 96 * SPAD + 128 * 96 + 96 * 64 + 64 * 48
                           + 96 + 64 + 48) * 4;
    cudaFuncSetAttribute(athx_lstm_mma, cudaFuncAttributeMaxDynamicSharedMemorySize, SM_TOTAL);
    cudaFuncSetAttribute(athx_head_kernel, cudaFuncAttributeMaxDynamicSharedMemorySize, HEAD_SMEM);

    athx_transpose_kernel<<<dim3(NS / 32, 3, 32), dim3(32, 8)>>>(X_obs, 32, 0);
    athx_transpose_kernel<<<dim3(NS / 32, 3, 56), dim3(32, 8)>>>(X_wrf, 56, 1);

    athx_lstm_mma<<<128, 512, SM_TOTAL>>>(oWih, oWhh, obih, obhh,
                                          wWih, wWhh, wbih, wbhh);

    athx_head_kernel<<<dim3(NS / 128, 2), 256, HEAD_SMEM>>>(
        fW1, fb1, fW2, fb2, fW3, fb3,
        oW1, ob1, oW2, ob2, oW3, ob3, out);
}

// round 9
// speedup vs baseline: 3.6026x; 1.0320x over previous
#include <cuda_runtime.h>
#include <cuda_fp16.h>
#include <cstdint>

#define NS     8192
#define TSTEPS 72

typedef unsigned long long u64;
typedef unsigned int       u32;
typedef unsigned short     u16;

// ---------------- scratch (device globals; no allocation allowed) ----------
__device__ u16   g_xt_obs[TSTEPS * 32 * NS];   // [T][C1][N] fp16
__device__ u16   g_xt_wrf[TSTEPS * 56 * NS];   // [T][C2][N] fp16
__device__ float g_featT[128 * NS];            // [128][N]

// ---------------- smem layout (bytes) for LSTM kernel ----------------------
#define SM_AH    0          // h [128x64] fp16, 16 KB
#define SM_XH    16384      // x [128x64] fp16, 16 KB
#define SM_BH    32768      // Whh [256x64] fp16, 32 KB
#define SM_BX    65536      // Wih [256x64] fp16, 32 KB
#define SM_ST0   98304      // stage buf0: half [C][128] <=14 KB
#define SM_ST1   112640     // stage buf1
#define SM_TOTAL 126976

// ---------------- math helpers ---------------------------------------------
__device__ __forceinline__ u32 tanh2(u32 x) {
    u32 y; asm("tanh.approx.f16x2 %0, %1;" : "=r"(y) : "r"(x)); return y;
}
__device__ __forceinline__ u32 f2h2(float lo, float hi) {
    __half2 v = __floats2half2_rn(lo, hi);
    return *reinterpret_cast<u32*>(&v);
}
__device__ __forceinline__ float2 h22f2(u32 a) {
    __half2 v = *reinterpret_cast<__half2*>(&a);
    return __half22float2(v);
}
__device__ __forceinline__ u32 hmul2_u(u32 a, u32 b) {
    __half2 x = *reinterpret_cast<__half2*>(&a);
    __half2 y = *reinterpret_cast<__half2*>(&b);
    __half2 z = __hmul2(x, y);
    return *reinterpret_cast<u32*>(&z);
}
__device__ __forceinline__ u32 sigm2(u32 x) {
    const __half2 half05 = __half2half2(__ushort_as_half(0x3800));  // 0.5
    __half2 v = *reinterpret_cast<__half2*>(&x);
    v = __hmul2(v, half05);
    u32 t = tanh2(*reinterpret_cast<u32*>(&v));
    __half2 tv = *reinterpret_cast<__half2*>(&t);
    __half2 r = __hfma2(tv, half05, half05);
    return *reinterpret_cast<u32*>(&r);
}

// ---------------- PTX helpers -----------------------------------------------
__device__ __forceinline__ u32 smem_u32(const void* p) {
    u32 a;
    asm("{ .reg .u64 t; cvta.to.shared.u64 t, %1; cvt.u32.u64 %0, t; }" : "=r"(a) : "l"(p));
    return a;
}
__device__ __forceinline__ void cp_async16(char* smem_dst, const void* gsrc) {
    u32 sa = smem_u32(smem_dst);
    asm volatile("cp.async.ca.shared.global [%0], [%1], 16;\n" :: "r"(sa), "l"(gsrc));
}
__device__ __forceinline__ void cp_commit()   { asm volatile("cp.async.commit_group;\n"); }
__device__ __forceinline__ void cp_wait_all() { asm volatile("cp.async.wait_all;\n"); }

__device__ __forceinline__ void ldsm4(u32& r0, u32& r1, u32& r2, u32& r3, u32 addr) {
    asm volatile("ldmatrix.sync.aligned.m8n8.x4.shared.b16 {%0,%1,%2,%3}, [%4];"
                 : "=r"(r0), "=r"(r1), "=r"(r2), "=r"(r3) : "r"(addr));
}
__device__ __forceinline__ void mma_fp16(float& d0, float& d1, float& d2, float& d3,
                                         u32 a0, u32 a1, u32 a2, u32 a3,
                                         u32 b0, u32 b1) {
    asm volatile("mma.sync.aligned.m16n8k16.row.col.f32.f16.f16.f32 "
                 "{%0,%1,%2,%3}, {%4,%5,%6,%7}, {%8,%9}, {%0,%1,%2,%3};"
                 : "+f"(d0), "+f"(d1), "+f"(d2), "+f"(d3)
                 : "r"(a0), "r"(a1), "r"(a2), "r"(a3), "r"(b0), "r"(b1));
}

// row stride 128B, 16B chunk index ^= (row&7)
__device__ __forceinline__ u32 swz(u32 row, u32 chunk) {
    return row * 128u + ((chunk ^ (row & 7u)) << 4);
}

// B row permutation: gate-quad-aligned fragment ownership
__device__ __forceinline__ int brow(int g) {
    int q = g >> 6, j = g & 63;
    int warpN = j >> 4, jl = j & 15;
    int hi = jl >> 3, a = (jl & 7) >> 1, e = jl & 1;
    return warpN * 64 + 8 * (q + 4 * hi) + 2 * a + e;
}

// ---------------- kernel 1: transpose [N][C][T] -> [T][C][N] fp16 -----------
__global__ void athx_transpose_kernel(const float* __restrict__ in, int C, int which) {
    __shared__ float tile[32][33];
    u16* out = which ? g_xt_wrf : g_xt_obs;
    const int c  = blockIdx.z;
    const int n0 = blockIdx.x * 32;
    const int t0 = blockIdx.y * 32;
    const int tx = threadIdx.x, ty = threadIdx.y;
    #pragma unroll
    for (int r = 0; r < 4; ++r) {
        int n = n0 + ty + r * 8;
        int t = t0 + tx;
        if (t < TSTEPS)
            tile[ty + r * 8][tx] = in[((size_t)n * C + c) * TSTEPS + t];
    }
    __syncthreads();
    #pragma unroll
    for (int r = 0; r < 4; ++r) {
        int t = t0 + ty + r * 8;
        int n = n0 + tx;
        if (t < TSTEPS)
            out[((size_t)t * C + c) * NS + n] =
                __half_as_ushort(__float2half_rn(tile[tx][ty + r * 8]));
    }
}

// ---------------- kernel 2: HMMA dual-LSTM, pure fp16, f16x2 epilogue -------
__global__ __launch_bounds__(512, 1)
void athx_lstm_mma(const float* __restrict__ oWih, const float* __restrict__ oWhh,
                   const float* __restrict__ obih, const float* __restrict__ obhh,
                   const float* __restrict__ wWih, const float* __restrict__ wWhh,
                   const float* __restrict__ wbih, const float* __restrict__ wbhh)
{
    extern __shared__ char smem[];
    const bool wrf = (blockIdx.x >= 64);
    const int  C   = wrf ? 56 : 32;
    const int  CP  = C >> 1;              // channel pairs
    const int  KCX = wrf ? 4 : 2;         // x k-chunks (16 cols each)
    const u16* xt = wrf ? g_xt_wrf : g_xt_obs;
    const float* Wih = wrf ? wWih : oWih;
    const float* Whh = wrf ? wWhh : oWhh;
    const float* bih = wrf ? wbih : obih;
    const float* bhh = wrf ? wbhh : obhh;
    const int n0  = (blockIdx.x & 63) * 128;
    const int tid = threadIdx.x;
    const int wid = tid >> 5;
    const int lane = tid & 31;
    const int warpM = wid >> 2;
    const int warpN = wid & 3;

    const u32 smb = smem_u32(smem);
    const int NCHUNK = C * 16;           // 16B chunks per x tile

#define XCOPY(STG_OFF)                                                           \
    {                                                                            \
        const u16* stg = (const u16*)(smem + (STG_OFF));                         \
        for (int i = tid; i < CP * 128; i += 512) {                              \
            int s = i & 127, cp = i >> 7;                                        \
            u32 h0 = (u32)stg[(2 * cp) * 128 + s];                               \
            u32 h1 = (u32)stg[(2 * cp + 1) * 128 + s];                           \
            u32 off = swz((u32)s, (u32)(cp >> 2)) + (cp & 3) * 4;                \
            *(u32*)(smem + SM_XH + off) = h0 | (h1 << 16);                       \
        }                                                                        \
    }

#define XFETCH(TIDX, STG_OFF)                                                    \
    {                                                                            \
        const u16* src = xt + (size_t)(TIDX) * C * NS;                           \
        char* dst = smem + (STG_OFF);                                            \
        for (int i = tid; i < NCHUNK; i += 512) {                                \
            int ch = i >> 4, v = i & 15;                                         \
            cp_async16(dst + (ch * 128 + v * 8) * 2,                             \
                       src + (size_t)ch * NS + n0 + v * 8);                      \
        }                                                                        \
        cp_commit();                                                             \
    }

    // ---- prefetch x_0 into stage0 ----
    XFETCH(0, SM_ST0)

    // ---- zero h/x/B tiles ----
    for (int i = tid; i < 98304 / 16; i += 512)
        ((uint4*)smem)[i] = make_uint4(0, 0, 0, 0);
    __syncthreads();

    // ---- fill B_h (Whh fp16), B_x (Wih fp16) ----
    for (int i = tid; i < 256 * 64; i += 512) {
        int g = i >> 6, k = i & 63;
        u32 off = swz((u32)brow(g), (u32)(k >> 3)) + (k & 7) * 2;
        *(__half*)(smem + SM_BH + off) = __float2half_rn(Whh[i]);
    }
    for (int i = tid; i < 256 * C; i += 512) {
        int g = i / C, ch = i - g * C;
        u32 off = swz((u32)brow(g), (u32)(ch >> 3)) + (ch & 7) * 2;
        *(__half*)(smem + SM_BX + off) = __float2half_rn(Wih[i]);
    }

    // ---- bias into registers (per-thread 16 gates, fp32) ----
    const int jbase = warpN * 16 + (lane & 3) * 2;
    float breg[16];
    #pragma unroll
    for (int q = 0; q < 4; ++q)
        #pragma unroll
        for (int h2i = 0; h2i < 2; ++h2i)
            #pragma unroll
            for (int e = 0; e < 2; ++e) {
                int g = q * 64 + jbase + h2i * 8 + e;
                breg[q * 4 + h2i * 2 + e] = bih[g] + bhh[g];
            }

    // ---- x_0 stage -> xbuf; prefetch x_1 into stage1 ----
    cp_wait_all();
    __syncthreads();
    XCOPY(SM_ST0)
    __syncthreads();
    XFETCH(1, SM_ST1)

    // ---- per-thread ldmatrix geometry ----
    const int g8 = lane >> 3, l = lane & 7;
    const u32 aRow = (u32)(warpM * 32 + (g8 & 1) * 8 + l);
    const u32 bRow = (u32)(warpN * 64 + ((g8 >> 1) & 1) * 8 + l);
    const u32 gAc = (u32)(g8 >> 1);
    const u32 gBc = (u32)(g8 & 1);
    const u32 lx = (u32)l;
    const u32 aB  = smb + SM_AH + aRow * 128;
    const u32 xB  = smb + SM_XH + aRow * 128;
    const u32 bhB = smb + SM_BH + bRow * 128;
    const u32 bxB = smb + SM_BX + bRow * 128;

    float acc[2][8][4];
    float cst[16];
    #pragma unroll
    for (int i = 0; i < 16; ++i) cst[i] = 0.0f;

#define MMA1(A_B, B_B, KC)                                                              \
    for (int ks = 0; ks < (KC); ++ks) {                                                 \
        u32 a[8];                                                                       \
        u32 ca = ((2u * ks + gAc) ^ lx) << 4;                                           \
        ldsm4(a[0], a[1], a[2], a[3], (A_B) + ca);                                      \
        ldsm4(a[4], a[5], a[6], a[7], (A_B) + 2048 + ca);                               \
        u32 cb = ((2u * ks + gBc) ^ lx) << 4;                                           \
        _Pragma("unroll")                                                               \
        for (int ntp = 0; ntp < 4; ++ntp) {                                             \
            u32 b0, b1, b2, b3;                                                         \
            ldsm4(b0, b1, b2, b3, (B_B) + ntp * 2048 + cb);                             \
            _Pragma("unroll")                                                           \
            for (int mt = 0; mt < 2; ++mt) {                                            \
                mma_fp16(acc[mt][2*ntp][0], acc[mt][2*ntp][1], acc[mt][2*ntp][2], acc[mt][2*ntp][3], \
                         a[4*mt], a[4*mt+1], a[4*mt+2], a[4*mt+3], b0, b1);             \
                mma_fp16(acc[mt][2*ntp+1][0], acc[mt][2*ntp+1][1], acc[mt][2*ntp+1][2], acc[mt][2*ntp+1][3], \
                         a[4*mt], a[4*mt+1], a[4*mt+2], a[4*mt+3], b2, b3);             \
            }                                                                           \
        }                                                                               \
    }

#define ZERO_ACC()                                                                      \
    _Pragma("unroll")                                                                   \
    for (int mt = 0; mt < 2; ++mt)                                                      \
        _Pragma("unroll")                                                               \
        for (int nt = 0; nt < 8; ++nt)                                                  \
            _Pragma("unroll")                                                           \
            for (int r = 0; r < 4; ++r) acc[mt][nt][r] = 0.0f;

    // ---- prologue x-mma: acc = Xpart_0 ----
    ZERO_ACC()
    MMA1(xB, bxB, KCX)

    for (int t = 0; t < TSTEPS; ++t) {
        __syncthreads();   // sync1: h STS from t-1 visible; stage slot free

        // h-part: acc += h_{t-1} . Whh^T
        MMA1(aB, bhB, 4)

        // ---- epilogue: packed f16x2 gates, fp32 cell state ----
        u32 hv2[8];    // packed h pairs; index ph = ((mt*2+d)*2+h2i)
        #pragma unroll
        for (int mt = 0; mt < 2; ++mt)
            #pragma unroll
            for (int d = 0; d < 2; ++d)
                #pragma unroll
                for (int h2i = 0; h2i < 2; ++h2i) {
                    int r0 = 2 * d, r1 = 2 * d + 1;
                    int bi0 = h2i * 2, bi1 = h2i * 2 + 1;
                    int ci0 = ((mt * 2 + d) * 2 + h2i) * 2;
                    int ph  = (mt * 2 + d) * 2 + h2i;
                    u32 gi2 = sigm2(f2h2(acc[mt][4*h2i + 0][r0] + breg[bi0],
                                         acc[mt][4*h2i + 0][r1] + breg[bi1]));
                    u32 gf2 = sigm2(f2h2(acc[mt][4*h2i + 1][r0] + breg[4 + bi0],
                                         acc[mt][4*h2i + 1][r1] + breg[4 + bi1]));
                    u32 gg2 = tanh2(f2h2(acc[mt][4*h2i + 2][r0] + breg[8 + bi0],
                                         acc[mt][4*h2i + 2][r1] + breg[8 + bi1]));
                    u32 go2 = sigm2(f2h2(acc[mt][4*h2i + 3][r0] + breg[12 + bi0],
                                         acc[mt][4*h2i + 3][r1] + breg[12 + bi1]));
                    float2 fi = h22f2(gi2);
                    float2 ff = h22f2(gf2);
                    float2 fg = h22f2(gg2);
                    float c0 = fmaf(ff.x, cst[ci0],     fi.x * fg.x);
                    float c1 = fmaf(ff.y, cst[ci0 + 1], fi.y * fg.y);
                    cst[ci0] = c0; cst[ci0 + 1] = c1;
                    u32 th2 = tanh2(f2h2(c0, c1));
                    hv2[ph] = hmul2_u(go2, th2);
                }

        cp_wait_all();     // own x_{t+1} chunks landed
        __syncthreads();   // sync2: all x_{t+1} staged; h-mma reads done

        if (t == TSTEPS - 1) {
            const int off = wrf ? 64 : 0;
            #pragma unroll
            for (int mt = 0; mt < 2; ++mt)
                #pragma unroll
                for (int d = 0; d < 2; ++d)
                    #pragma unroll
                    for (int h2i = 0; h2i < 2; ++h2i) {
                        int ph = (mt * 2 + d) * 2 + h2i;
                        float2 hf = h22f2(hv2[ph]);
                        int s  = warpM * 32 + mt * 16 + (lane >> 2) + 8 * d;
                        int j0 = warpN * 16 + h2i * 8 + (lane & 3) * 2;
                        g_featT[(size_t)(off + j0)     * NS + n0 + s] = hf.x;
                        g_featT[(size_t)(off + j0 + 1) * NS + n0 + s] = hf.y;
                    }
        } else {
            // copy staged x_{t+1} -> xbuf  (slot (t+1)&1)
            XCOPY(((t + 1) & 1) ? SM_ST1 : SM_ST0)
            // STS h_t -> hbuf (already packed fp16 pairs)
            #pragma unroll
            for (int mt = 0; mt < 2; ++mt)
                #pragma unroll
                for (int d = 0; d < 2; ++d)
                    #pragma unroll
                    for (int h2i = 0; h2i < 2; ++h2i) {
                        int ph = (mt * 2 + d) * 2 + h2i;
                        u32 s  = (u32)(warpM * 32 + mt * 16 + (lane >> 2) + 8 * d);
                        u32 jp = (u32)(warpN * 16 + h2i * 8 + (lane & 3) * 2);
                        u32 off = swz(s, jp >> 3) + (jp & 7) * 2;
                        *(u32*)(smem + SM_AH + off) = hv2[ph];
                    }
            // prefetch x_{t+2} into freed slot
            if (t + 2 < TSTEPS) {
                XFETCH(t + 2, (t & 1) ? SM_ST1 : SM_ST0)
            }
            __syncthreads();   // sync3: xbuf(x_{t+1}) visible
            // tail x-mma for t+1 — overlaps other warps' epilogue/copy phases
            ZERO_ACC()
            MMA1(xB, bxB, KCX)
        }
    }
#undef MMA1
#undef ZERO_ACC
#undef XCOPY
#undef XFETCH
}

// ---------------- kernel 3: MLP heads (512 threads, 4 samples/thread) -------
#define SPAD 132
__device__ __forceinline__ u64 dup2(float x) {
    u64 r; asm("mov.b64 %0, {%1,%1};" : "=l"(r) : "f"(x)); return r;
}
__device__ __forceinline__ void unpack2(u64 v, float& x, float& y) {
    asm("mov.b64 {%0,%1}, %2;" : "=f"(x), "=f"(y) : "l"(v));
}
__device__ __forceinline__ u64 ffma2(u64 a, u64 b, u64 c) {
    u64 d; asm("fma.rn.f32x2 %0, %1, %2, %3;" : "=l"(d) : "l"(a), "l"(b), "l"(c)); return d;
}

template <int IN, int OUT, bool RELU>
__device__ __forceinline__ void athx_layer4(const float* __restrict__ A,
                                            const float* __restrict__ wt,
                                            const float* __restrict__ bs,
                                            float* __restrict__ Bout,
                                            int gx, int sx) {
    constexpr int R = OUT / 16;
    u64 acc2[2][R];
    #pragma unroll
    for (int sp = 0; sp < 2; ++sp)
        #pragma unroll
        for (int r = 0; r < R; ++r) acc2[sp][r] = 0ull;
    for (int k = 0; k < IN; ++k) {
        ulonglong2 p = *(const ulonglong2*)(A + k * SPAD + sx * 4);
        u64 a2[2] = {p.x, p.y};
        #pragma unroll
        for (int r = 0; r < R; ++r) {
            u64 b2 = dup2(wt[k * OUT + gx + 16 * r]);
            #pragma unroll
            for (int sp = 0; sp < 2; ++sp) acc2[sp][r] = ffma2(a2[sp], b2, acc2[sp][r]);
        }
    }
    #pragma unroll
    for (int r = 0; r < R; ++r) {
        int u = gx + 16 * r;
        float bb = bs[u];
        float hv[4];
        #pragma unroll
        for (int sp = 0; sp < 2; ++sp) {
            float v0, v1;
            unpack2(acc2[sp][r], v0, v1);
            v0 += bb; v1 += bb;
            hv[2 * sp]     = RELU ? fmaxf(v0, 0.0f) : v0;
            hv[2 * sp + 1] = RELU ? fmaxf(v1, 0.0f) : v1;
        }
        *(float4*)(Bout + u * SPAD + sx * 4) = make_float4(hv[0], hv[1], hv[2], hv[3]);
    }
}

__global__ __launch_bounds__(512, 1) void athx_head_kernel(
    const float* __restrict__ fW1, const float* __restrict__ fb1,
    const float* __restrict__ fW2, const float* __restrict__ fb2,
    const float* __restrict__ fW3, const float* __restrict__ fb3,
    const float* __restrict__ oW1, const float* __restrict__ ob1,
    const float* __restrict__ oW2, const float* __restrict__ ob2,
    const float* __restrict__ oW3, const float* __restrict__ ob3,
    float* __restrict__ out)
{
    extern __shared__ float sm[];
    float* A   = sm;
    float* B   = A + 128 * SPAD;
    float* w1t = B + 96 * SPAD;
    float* w2t = w1t + 128 * 96;
    float* w3t = w2t + 96 * 64;
    float* bs1 = w3t + 64 * 48;
    float* bs2 = bs1 + 96;
    float* bs3 = bs2 + 64;

    const int head = blockIdx.y;
    const float* W1 = head ? oW1 : fW1; const float* b1 = head ? ob1 : fb1;
    const float* W2 = head ? oW2 : fW2; const float* b2 = head ? ob2 : fb2;
    const float* W3 = head ? oW3 : fW3; const float* b3 = head ? ob3 : fb3;
    const int n0  = blockIdx.x * 128;
    const int tid = threadIdx.x;
    const int gx  = tid & 15, sx = tid >> 4;   // sx 0..31, 4 samples each

    for (int idx = tid; idx < 128 * 128; idx += 512) {
        int k = idx >> 7, s = idx & 127;
        A[k * SPAD + s] = g_featT[(size_t)k * NS + n0 + s];
    }
    for (int idx = tid; idx < 96 * 128; idx += 512) {
        int u = idx >> 7, k = idx & 127;
        w1t[k * 96 + u] = W1[idx];
    }
    for (int idx = tid; idx < 64 * 96; idx += 512) {
        int u = idx / 96, k = idx - u * 96;
        w2t[k * 64 + u] = W2[idx];
    }
    for (int idx = tid; idx < 48 * 64; idx += 512) {
        int u = idx >> 6, k = idx & 63;
        w3t[k * 48 + u] = W3[idx];
    }
    if (tid < 96) bs1[tid] = b1[tid];
    if (tid < 64) bs2[tid] = b2[tid];
    if (tid < 48) bs3[tid] = b3[tid];
    __syncthreads();

    athx_layer4<128, 96, true>(A, w1t, bs1, B, gx, sx);
    __syncthreads();
    athx_layer4<96, 64, true>(B, w2t, bs2, A, gx, sx);
    __syncthreads();

    {
        u64 acc2[2][3];
        #pragma unroll
        for (int sp = 0; sp < 2; ++sp)
            #pragma unroll
            for (int r = 0; r < 3; ++r) acc2[sp][r] = 0ull;
        for (int k = 0; k < 64; ++k) {
            ulonglong2 p = *(const ulonglong2*)(A + k * SPAD + sx * 4);
            u64 a2[2] = {p.x, p.y};
            #pragma unroll
            for (int r = 0; r < 3; ++r) {
                u64 b2 = dup2(w3t[k * 48 + gx + 16 * r]);
                #pragma unroll
                for (int sp = 0; sp < 2; ++sp) acc2[sp][r] = ffma2(a2[sp], b2, acc2[sp][r]);
            }
        }
        #pragma unroll
        for (int r = 0; r < 3; ++r) {
            int u = gx + 16 * r;
            float bb = bs3[u];
            #pragma unroll
            for (int sp = 0; sp < 2; ++sp) {
                float v0, v1;
                unpack2(acc2[sp][r], v0, v1);
                int n = n0 + sx * 4 + 2 * sp;
                out[(size_t)n * 96 + head * 48 + u]       = v0 + bb;
                out[(size_t)(n + 1) * 96 + head * 48 + u] = v1 + bb;
            }
        }
    }
}

// ---------------- launch ----------------------------------------------------
extern "C" void kernel_launch(void* const* d_in, const int* in_sizes, int n_in,
                              void* d_out, int out_size) {
    const float* X_obs  = (const float*)d_in[0];
    const float* X_wrf  = (const float*)d_in[1];
    const float* oWih   = (const float*)d_in[2];
    const float* oWhh   = (const float*)d_in[3];
    const float* obih   = (const float*)d_in[4];
    const float* obhh   = (const float*)d_in[5];
    const float* wWih   = (const float*)d_in[6];
    const float* wWhh   = (const float*)d_in[7];
    const float* wbih   = (const float*)d_in[8];
    const float* wbhh   = (const float*)d_in[9];
    const float* fW1 = (const float*)d_in[10]; const float* fb1 = (const float*)d_in[11];
    const float* fW2 = (const float*)d_in[12]; const float* fb2 = (const float*)d_in[13];
    const float* fW3 = (const float*)d_in[14]; const float* fb3 = (const float*)d_in[15];
    const float* oW1 = (const float*)d_in[16]; const float* ob1 = (const float*)d_in[17];
    const float* oW2 = (const float*)d_in[18]; const float* ob2 = (const float*)d_in[19];
    const float* oW3 = (const float*)d_in[20]; const float* ob3 = (const float*)d_in[21];
    float* out = (float*)d_out;

    const int HEAD_SMEM = (128 * SPAD + 96 * SPAD + 128 * 96 + 96 * 64 + 64 * 48
                           + 96 + 64 + 48) * 4;
    cudaFuncSetAttribute(athx_lstm_mma, cudaFuncAttributeMaxDynamicSharedMemorySize, SM_TOTAL);
    cudaFuncSetAttribute(athx_head_kernel, cudaFuncAttributeMaxDynamicSharedMemorySize, HEAD_SMEM);

    athx_transpose_kernel<<<dim3(NS / 32, 3, 32), dim3(32, 8)>>>(X_obs, 32, 0);
    athx_transpose_kernel<<<dim3(NS / 32, 3, 56), dim3(32, 8)>>>(X_wrf, 56, 1);

    athx_lstm_mma<<<128, 512, SM_TOTAL>>>(oWih, oWhh, obih, obhh,
                                          wWih, wWhh, wbih, wbhh);

    athx_head_kernel<<<dim3(NS / 128, 2), 512, HEAD_SMEM>>>(
        fW1, fb1, fW2, fb2, fW3, fb3,
        oW1, ob1, oW2, ob2, oW3, ob3, out);
}

// round 10
// speedup vs baseline: 3.7459x; 1.0398x over previous
#include <cuda_runtime.h>
#include <cuda_fp16.h>
#include <cstdint>

#define NS     8192
#define TSTEPS 72

typedef unsigned long long u64;
typedef unsigned int       u32;
typedef unsigned short     u16;

// ---------------- scratch (device globals; no allocation allowed) ----------
__device__ u16   g_xt_obs[TSTEPS * 32 * NS];   // [T][C1][N] fp16
__device__ u16   g_xt_wrf[TSTEPS * 56 * NS];   // [T][C2][N] fp16
__device__ float g_featT[128 * NS];            // [128][N]

// ---------------- smem layout (bytes) for LSTM kernel ----------------------
#define SM_AH    0          // h [128x64] fp16 sample-major, 16 KB
#define SM_BH    16384      // Whh [256x64] fp16, 32 KB
#define SM_BX    49152      // Wih [256x64] fp16, 32 KB
#define SM_ST0   81920      // stage buf0: half [64 ch rows][128 samples] 16 KB
#define SM_ST1   98304      // stage buf1
#define SM_TOTAL 114688

// ---------------- math helpers ---------------------------------------------
__device__ __forceinline__ float tanh_a(float x) {
    float y; asm("tanh.approx.f32 %0, %1;" : "=f"(y) : "f"(x)); return y;
}
__device__ __forceinline__ float sigm_a(float x) {
    return fmaf(0.5f, tanh_a(0.5f * x), 0.5f);
}

// ---------------- PTX helpers -----------------------------------------------
__device__ __forceinline__ u32 smem_u32(const void* p) {
    u32 a;
    asm("{ .reg .u64 t; cvta.to.shared.u64 t, %1; cvt.u32.u64 %0, t; }" : "=r"(a) : "l"(p));
    return a;
}
__device__ __forceinline__ void cp_async16(char* smem_dst, const void* gsrc) {
    u32 sa = smem_u32(smem_dst);
    asm volatile("cp.async.ca.shared.global [%0], [%1], 16;\n" :: "r"(sa), "l"(gsrc));
}
__device__ __forceinline__ void cp_commit()   { asm volatile("cp.async.commit_group;\n"); }
__device__ __forceinline__ void cp_wait_all() { asm volatile("cp.async.wait_all;\n"); }

__device__ __forceinline__ void ldsm4(u32& r0, u32& r1, u32& r2, u32& r3, u32 addr) {
    asm volatile("ldmatrix.sync.aligned.m8n8.x4.shared.b16 {%0,%1,%2,%3}, [%4];"
                 : "=r"(r0), "=r"(r1), "=r"(r2), "=r"(r3) : "r"(addr));
}
__device__ __forceinline__ void ldsm4t(u32& r0, u32& r1, u32& r2, u32& r3, u32 addr) {
    asm volatile("ldmatrix.sync.aligned.m8n8.x4.trans.shared.b16 {%0,%1,%2,%3}, [%4];"
                 : "=r"(r0), "=r"(r1), "=r"(r2), "=r"(r3) : "r"(addr));
}
__device__ __forceinline__ void mma_fp16(float& d0, float& d1, float& d2, float& d3,
                                         u32 a0, u32 a1, u32 a2, u32 a3,
                                         u32 b0, u32 b1) {
    asm volatile("mma.sync.aligned.m16n8k16.row.col.f32.f16.f16.f32 "
                 "{%0,%1,%2,%3}, {%4,%5,%6,%7}, {%8,%9}, {%0,%1,%2,%3};"
                 : "+f"(d0), "+f"(d1), "+f"(d2), "+f"(d3)
                 : "r"(a0), "r"(a1), "r"(a2), "r"(a3), "r"(b0), "r"(b1));
}

// sample-major: row stride 128B, 16B chunk index ^= (row&7)
__device__ __forceinline__ u32 swz(u32 row, u32 chunk) {
    return row * 128u + ((chunk ^ (row & 7u)) << 4);
}

// B row permutation: gate-quad-aligned fragment ownership
__device__ __forceinline__ int brow(int g) {
    int q = g >> 6, j = g & 63;
    int warpN = j >> 4, jl = j & 15;
    int hi = jl >> 3, a = (jl & 7) >> 1, e = jl & 1;
    return warpN * 64 + 8 * (q + 4 * hi) + 2 * a + e;
}

// ---------------- kernel 1: transpose [N][C][T] -> [T][C][N] fp16 -----------
__global__ void athx_transpose_kernel(const float* __restrict__ in, int C, int which) {
    __shared__ float tile[32][33];
    u16* out = which ? g_xt_wrf : g_xt_obs;
    const int c  = blockIdx.z;
    const int n0 = blockIdx.x * 32;
    const int t0 = blockIdx.y * 32;
    const int tx = threadIdx.x, ty = threadIdx.y;
    #pragma unroll
    for (int r = 0; r < 4; ++r) {
        int n = n0 + ty + r * 8;
        int t = t0 + tx;
        if (t < TSTEPS)
            tile[ty + r * 8][tx] = in[((size_t)n * C + c) * TSTEPS + t];
    }
    __syncthreads();
    #pragma unroll
    for (int r = 0; r < 4; ++r) {
        int t = t0 + ty + r * 8;
        int n = n0 + tx;
        if (t < TSTEPS)
            out[((size_t)t * C + c) * NS + n] =
                __half_as_ushort(__float2half_rn(tile[tx][ty + r * 8]));
    }
}

// ---------------- kernel 2: HMMA dual-LSTM, fp16, trans-ldsm x-path ---------
__global__ __launch_bounds__(512, 1)
void athx_lstm_mma(const float* __restrict__ oWih, const float* __restrict__ oWhh,
                   const float* __restrict__ obih, const float* __restrict__ obhh,
                   const float* __restrict__ wWih, const float* __restrict__ wWhh,
                   const float* __restrict__ wbih, const float* __restrict__ wbhh)
{
    extern __shared__ char smem[];
    const bool wrf = (blockIdx.x >= 64);
    const int  C   = wrf ? 56 : 32;
    const int  KCX = wrf ? 4 : 2;         // x k-chunks (16 cols each)
    const u16* xt = wrf ? g_xt_wrf : g_xt_obs;
    const float* Wih = wrf ? wWih : oWih;
    const float* Whh = wrf ? wWhh : oWhh;
    const float* bih = wrf ? wbih : obih;
    const float* bhh = wrf ? wbhh : obhh;
    const int n0  = (blockIdx.x & 63) * 128;
    const int tid = threadIdx.x;
    const int wid = tid >> 5;
    const int lane = tid & 31;
    const int warpM = wid >> 2;
    const int warpN = wid & 3;

    const u32 smb = smem_u32(smem);
    const int NCHUNK = C * 16;           // 16B chunks per x tile

    // fetch x_t straight into channel-major stage, chunk-swizzled:
    // smem chunk v of channel ch holds gmem samples [ (v^(ch&7))*8 .. +8 )
#define XFETCH(TIDX, STG_OFF)                                                    \
    {                                                                            \
        const u16* src = xt + (size_t)(TIDX) * C * NS;                           \
        char* dst = smem + (STG_OFF);                                            \
        for (int i = tid; i < NCHUNK; i += 512) {                                \
            int ch = i >> 4, v = i & 15;                                         \
            cp_async16(dst + ch * 256 + v * 16,                                  \
                       src + (size_t)ch * NS + n0 + (v ^ (ch & 7)) * 8);         \
        }                                                                        \
        cp_commit();                                                             \
    }

    // ---- zero ALL smem (h=0, BX pad cols, stage pad rows) ----
    for (int i = tid; i < SM_TOTAL / 16; i += 512)
        ((uint4*)smem)[i] = make_uint4(0, 0, 0, 0);
    __syncthreads();

    // ---- prefetch x_0 into stage0 (after zero; pad rows C..63 stay 0) ----
    XFETCH(0, SM_ST0)

    // ---- fill B_h (Whh fp16), B_x (Wih fp16) ----
    for (int i = tid; i < 256 * 64; i += 512) {
        int g = i >> 6, k = i & 63;
        u32 off = swz((u32)brow(g), (u32)(k >> 3)) + (k & 7) * 2;
        *(__half*)(smem + SM_BH + off) = __float2half_rn(Whh[i]);
    }
    for (int i = tid; i < 256 * C; i += 512) {
        int g = i / C, ch = i - g * C;
        u32 off = swz((u32)brow(g), (u32)(ch >> 3)) + (ch & 7) * 2;
        *(__half*)(smem + SM_BX + off) = __float2half_rn(Wih[i]);
    }

    // ---- bias into registers (per-thread 16 gates, fp32) ----
    const int jbase = warpN * 16 + (lane & 3) * 2;
    float breg[16];
    #pragma unroll
    for (int q = 0; q < 4; ++q)
        #pragma unroll
        for (int h2i = 0; h2i < 2; ++h2i)
            #pragma unroll
            for (int e = 0; e < 2; ++e) {
                int g = q * 64 + jbase + h2i * 8 + e;
                breg[q * 4 + h2i * 2 + e] = bih[g] + bhh[g];
            }

    cp_wait_all();
    __syncthreads();    // stage0 + B fills + zeros visible to all

    // ---- per-thread ldmatrix geometry ----
    const int g8 = lane >> 3, l = lane & 7;
    const u32 aRow = (u32)(warpM * 32 + (g8 & 1) * 8 + l);
    const u32 bRow = (u32)(warpN * 64 + ((g8 >> 1) & 1) * 8 + l);
    const u32 gAc = (u32)(g8 >> 1);
    const u32 gBc = (u32)(g8 & 1);
    const u32 lx = (u32)l;
    const u32 aB  = smb + SM_AH + aRow * 128;
    const u32 bhB = smb + SM_BH + bRow * 128;
    const u32 bxB = smb + SM_BX + bRow * 128;
    // trans-ldsm geometry for channel-major stage
    const u32 stRowB = (u32)(gAc * 8 + (u32)l) * 256u;                     // channel row
    const u32 sxT0 = (((u32)(warpM * 4) + (u32)(g8 & 1)) ^ (u32)l) << 4;   // samples mt=0
    const u32 sxT1 = (((u32)(warpM * 4) + (u32)(g8 & 1) + 2u) ^ (u32)l) << 4; // mt=1

    float acc[2][8][4];
    float cst[16];
    #pragma unroll
    for (int i = 0; i < 16; ++i) cst[i] = 0.0f;

    // sample-major A (h-part)
#define MMA1(A_B, B_B, KC)                                                              \
    for (int ks = 0; ks < (KC); ++ks) {                                                 \
        u32 a[8];                                                                       \
        u32 ca = ((2u * ks + gAc) ^ lx) << 4;                                           \
        ldsm4(a[0], a[1], a[2], a[3], (A_B) + ca);                                      \
        ldsm4(a[4], a[5], a[6], a[7], (A_B) + 2048 + ca);                               \
        u32 cb = ((2u * ks + gBc) ^ lx) << 4;                                           \
        _Pragma("unroll")                                                               \
        for (int ntp = 0; ntp < 4; ++ntp) {                                             \
            u32 b0, b1, b2, b3;                                                         \
            ldsm4(b0, b1, b2, b3, (B_B) + ntp * 2048 + cb);                             \
            _Pragma("unroll")                                                           \
            for (int mt = 0; mt < 2; ++mt) {                                            \
                mma_fp16(acc[mt][2*ntp][0], acc[mt][2*ntp][1], acc[mt][2*ntp][2], acc[mt][2*ntp][3], \
                         a[4*mt], a[4*mt+1], a[4*mt+2], a[4*mt+3], b0, b1);             \
                mma_fp16(acc[mt][2*ntp+1][0], acc[mt][2*ntp+1][1], acc[mt][2*ntp+1][2], acc[mt][2*ntp+1][3], \
                         a[4*mt], a[4*mt+1], a[4*mt+2], a[4*mt+3], b2, b3);             \
            }                                                                           \
        }                                                                               \
    }

    // channel-major stage A via ldmatrix.trans (x-part)
#define MMA1T(STG_ABS, B_B, KC)                                                         \
    for (int ks = 0; ks < (KC); ++ks) {                                                 \
        u32 a[8];                                                                       \
        u32 ab = (STG_ABS) + stRowB + (u32)ks * 4096u;                                  \
        ldsm4t(a[0], a[1], a[2], a[3], ab + sxT0);                                      \
        ldsm4t(a[4], a[5], a[6], a[7], ab + sxT1);                                      \
        u32 cb = ((2u * ks + gBc) ^ lx) << 4;                                           \
        _Pragma("unroll")                                                               \
        for (int ntp = 0; ntp < 4; ++ntp) {                                             \
            u32 b0, b1, b2, b3;                                                         \
            ldsm4(b0, b1, b2, b3, (B_B) + ntp * 2048 + cb);                             \
            _Pragma("unroll")                                                           \
            for (int mt = 0; mt < 2; ++mt) {                                            \
                mma_fp16(acc[mt][2*ntp][0], acc[mt][2*ntp][1], acc[mt][2*ntp][2], acc[mt][2*ntp][3], \
                         a[4*mt], a[4*mt+1], a[4*mt+2], a[4*mt+3], b0, b1);             \
                mma_fp16(acc[mt][2*ntp+1][0], acc[mt][2*ntp+1][1], acc[mt][2*ntp+1][2], acc[mt][2*ntp+1][3], \
                         a[4*mt], a[4*mt+1], a[4*mt+2], a[4*mt+3], b2, b3);             \
            }                                                                           \
        }                                                                               \
    }

#define ZERO_ACC()                                                                      \
    _Pragma("unroll")                                                                   \
    for (int mt = 0; mt < 2; ++mt)                                                      \
        _Pragma("unroll")                                                               \
        for (int nt = 0; nt < 8; ++nt)                                                  \
            _Pragma("unroll")                                                           \
            for (int r = 0; r < 4; ++r) acc[mt][nt][r] = 0.0f;

    // ---- prologue x-mma: acc = Xpart_0 (from stage0, trans) ----
    ZERO_ACC()
    MMA1T(smb + SM_ST0, bxB, KCX)

    for (int t = 0; t < TSTEPS; ++t) {
        __syncthreads();   // sync1: h STS from t-1 visible; stage slot (t+1)&1 free

        // fetch x_{t+1} directly into its stage slot (overlaps h-mma)
        if (t + 1 < TSTEPS) {
            XFETCH(t + 1, ((t + 1) & 1) ? SM_ST1 : SM_ST0)
        }

        // h-part: acc += h_{t-1} . Whh^T
        MMA1(aB, bhB, 4)

        // ---- epilogue: fp32 gates, fp32 cell state ----
        float hval[16];
        #pragma unroll
        for (int mt = 0; mt < 2; ++mt)
            #pragma unroll
            for (int d = 0; d < 2; ++d)
                #pragma unroll
                for (int h2i = 0; h2i < 2; ++h2i)
                    #pragma unroll
                    for (int e = 0; e < 2; ++e) {
                        int r = 2 * d + e;
                        int ci = ((mt * 2 + d) * 2 + h2i) * 2 + e;
                        int bi = h2i * 2 + e;
                        float gi = sigm_a(acc[mt][4*h2i + 0][r] + breg[bi]);
                        float gf = sigm_a(acc[mt][4*h2i + 1][r] + breg[4 + bi]);
                        float gg = tanh_a(acc[mt][4*h2i + 2][r] + breg[8 + bi]);
                        float go = sigm_a(acc[mt][4*h2i + 3][r] + breg[12 + bi]);
                        float cc = fmaf(gf, cst[ci], gi * gg);
                        cst[ci] = cc;
                        hval[ci] = go * tanh_a(cc);
                    }

        cp_wait_all();     // own x_{t+1} chunks landed
        __syncthreads();   // sync2: stage fully staged; h-mma reads of AH done

        if (t == TSTEPS - 1) {
            const int off = wrf ? 64 : 0;
            #pragma unroll
            for (int mt = 0; mt < 2; ++mt)
                #pragma unroll
                for (int d = 0; d < 2; ++d)
                    #pragma unroll
                    for (int h2i = 0; h2i < 2; ++h2i)
                        #pragma unroll
                        for (int e = 0; e < 2; ++e) {
                            int s = warpM * 32 + mt * 16 + (lane >> 2) + 8 * d;
                            int j = warpN * 16 + h2i * 8 + (lane & 3) * 2 + e;
                            int ci = ((mt * 2 + d) * 2 + h2i) * 2 + e;
                            g_featT[(size_t)(off + j) * NS + n0 + s] = hval[ci];
                        }
        } else {
            // STS h_t -> AH (fp16, sample-major)
            #pragma unroll
            for (int mt = 0; mt < 2; ++mt)
                #pragma unroll
                for (int d = 0; d < 2; ++d)
                    #pragma unroll
                    for (int h2i = 0; h2i < 2; ++h2i) {
                        int ci = ((mt * 2 + d) * 2 + h2i) * 2;
                        __half hh0 = __float2half_rn(hval[ci]);
                        __half hh1 = __float2half_rn(hval[ci + 1]);
                        u32 hi32 = (u32)__half_as_ushort(hh0) | ((u32)__half_as_ushort(hh1) << 16);
                        u32 s  = (u32)(warpM * 32 + mt * 16 + (lane >> 2) + 8 * d);
                        u32 jp = (u32)(warpN * 16 + h2i * 8 + (lane & 3) * 2);
                        u32 off = swz(s, jp >> 3) + (jp & 7) * 2;
                        *(u32*)(smem + SM_AH + off) = hi32;
                    }
            // tail x-mma for t+1 straight from stage (trans) — overlaps epilogues
            ZERO_ACC()
            MMA1T(((t + 1) & 1) ? (smb + SM_ST1) : (smb + SM_ST0), bxB, KCX)
        }
    }
#undef MMA1
#undef MMA1T
#undef ZERO_ACC
#undef XFETCH
}

// ---------------- kernel 3: MLP heads (1024 threads, 2 samples/thread) ------
#define SPAD 132
__device__ __forceinline__ u64 dup2(float x) {
    u64 r; asm("mov.b64 %0, {%1,%1};" : "=l"(r) : "f"(x)); return r;
}
__device__ __forceinline__ void unpack2(u64 v, float& x, float& y) {
    asm("mov.b64 {%0,%1}, %2;" : "=f"(x), "=f"(y) : "l"(v));
}
__device__ __forceinline__ u64 ffma2(u64 a, u64 b, u64 c) {
    u64 d; asm("fma.rn.f32x2 %0, %1, %2, %3;" : "=l"(d) : "l"(a), "l"(b), "l"(c)); return d;
}

template <int IN, int OUT, bool RELU>
__device__ __forceinline__ void athx_layer2(const float* __restrict__ A,
                                            const float* __restrict__ wt,
                                            const float* __restrict__ bs,
                                            float* __restrict__ Bout,
                                            int gx, int sx) {
    constexpr int R = OUT / 16;
    u64 acc2[R];
    #pragma unroll
    for (int r = 0; r < R; ++r) acc2[r] = 0ull;
    for (int k = 0; k < IN; ++k) {
        u64 a2 = *(const u64*)(A + k * SPAD + sx * 2);
        #pragma unroll
        for (int r = 0; r < R; ++r)
            acc2[r] = ffma2(a2, dup2(wt[k * OUT + gx + 16 * r]), acc2[r]);
    }
    #pragma unroll
    for (int r = 0; r < R; ++r) {
        int u = gx + 16 * r;
        float bb = bs[u];
        float v0, v1;
        unpack2(acc2[r], v0, v1);
        v0 += bb; v1 += bb;
        if (RELU) { v0 = fmaxf(v0, 0.0f); v1 = fmaxf(v1, 0.0f); }
        *(float2*)(Bout + u * SPAD + sx * 2) = make_float2(v0, v1);
    }
}

__global__ __launch_bounds__(1024, 1) void athx_head_kernel(
    const float* __restrict__ fW1, const float* __restrict__ fb1,
    const float* __restrict__ fW2, const float* __restrict__ fb2,
    const float* __restrict__ fW3, const float* __restrict__ fb3,
    const float* __restrict__ oW1, const float* __restrict__ ob1,
    const float* __restrict__ oW2, const float* __restrict__ ob2,
    const float* __restrict__ oW3, const float* __restrict__ ob3,
    float* __restrict__ out)
{
    extern __shared__ float sm[];
    float* A   = sm;
    float* B   = A + 128 * SPAD;
    float* w1t = B + 96 * SPAD;
    float* w2t = w1t + 128 * 96;
    float* w3t = w2t + 96 * 64;
    float* bs1 = w3t + 64 * 48;
    float* bs2 = bs1 + 96;
    float* bs3 = bs2 + 64;

    const int head = blockIdx.y;
    const float* W1 = head ? oW1 : fW1; const float* b1 = head ? ob1 : fb1;
    const float* W2 = head ? oW2 : fW2; const float* b2 = head ? ob2 : fb2;
    const float* W3 = head ? oW3 : fW3; const float* b3 = head ? ob3 : fb3;
    const int n0  = blockIdx.x * 128;
    const int tid = threadIdx.x;
    const int gx  = tid & 15, sx = tid >> 4;   // sx 0..63, 2 samples each

    for (int idx = tid; idx < 128 * 128; idx += 1024) {
        int k = idx >> 7, s = idx & 127;
        A[k * SPAD + s] = g_featT[(size_t)k * NS + n0 + s];
    }
    for (int idx = tid; idx < 96 * 128; idx += 1024) {
        int u = idx >> 7, k = idx & 127;
        w1t[k * 96 + u] = W1[idx];
    }
    for (int idx = tid; idx < 64 * 96; idx += 1024) {
        int u = idx / 96, k = idx - u * 96;
        w2t[k * 64 + u] = W2[idx];
    }
    for (int idx = tid; idx < 48 * 64; idx += 1024) {
        int u = idx >> 6, k = idx & 63;
        w3t[k * 48 + u] = W3[idx];
    }
    if (tid < 96) bs1[tid] = b1[tid];
    if (tid < 64) bs2[tid] = b2[tid];
    if (tid < 48) bs3[tid] = b3[tid];
    __syncthreads();

    athx_layer2<128, 96, true>(A, w1t, bs1, B, gx, sx);
    __syncthreads();
    athx_layer2<96, 64, true>(B, w2t, bs2, A, gx, sx);
    __syncthreads();

    {
        u64 acc2[3];
        #pragma unroll
        for (int r = 0; r < 3; ++r) acc2[r] = 0ull;
        for (int k = 0; k < 64; ++k) {
            u64 a2 = *(const u64*)(A + k * SPAD + sx * 2);
            #pragma unroll
            for (int r = 0; r < 3; ++r)
                acc2[r] = ffma2(a2, dup2(w3t[k * 48 + gx + 16 * r]), acc2[r]);
        }
        #pragma unroll
        for (int r = 0; r < 3; ++r) {
            int u = gx + 16 * r;
            float bb = bs3[u];
            float v0, v1;
            unpack2(acc2[r], v0, v1);
            int n = n0 + sx * 2;
            out[(size_t)n * 96 + head * 48 + u]       = v0 + bb;
            out[(size_t)(n + 1) * 96 + head * 48 + u] = v1 + bb;
        }
    }
}

// ---------------- launch ----------------------------------------------------
extern "C" void kernel_launch(void* const* d_in, const int* in_sizes, int n_in,
                              void* d_out, int out_size) {
    const float* X_obs  = (const float*)d_in[0];
    const float* X_wrf  = (const float*)d_in[1];
    const float* oWih   = (const float*)d_in[2];
    const float* oWhh   = (const float*)d_in[3];
    const float* obih   = (const float*)d_in[4];
    const float* obhh   = (const float*)d_in[5];
    const float* wWih   = (const float*)d_in[6];
    const float* wWhh   = (const float*)d_in[7];
    const float* wbih   = (const float*)d_in[8];
    const float* wbhh   = (const float*)d_in[9];
    const float* fW1 = (const float*)d_in[10]; const float* fb1 = (const float*)d_in[11];
    const float* fW2 = (const float*)d_in[12]; const float* fb2 = (const float*)d_in[13];
    const float* fW3 = (const float*)d_in[14]; const float* fb3 = (const float*)d_in[15];
    const float* oW1 = (const float*)d_in[16]; const float* ob1 = (const float*)d_in[17];
    const float* oW2 = (const float*)d_in[18]; const float* ob2 = (const float*)d_in[19];
    const float* oW3 = (const float*)d_in[20]; const float* ob3 = (const float*)d_in[21];
    float* out = (float*)d_out;

    const int HEAD_SMEM = (128 * SPAD + 96 * SPAD + 128 * 96 + 96 * 64 + 64 * 48
                           + 96 + 64 + 48) * 4;
    cudaFuncSetAttribute(athx_lstm_mma, cudaFuncAttributeMaxDynamicSharedMemorySize, SM_TOTAL);
    cudaFuncSetAttribute(athx_head_kernel, cudaFuncAttributeMaxDynamicSharedMemorySize, HEAD_SMEM);

    athx_transpose_kernel<<<dim3(NS / 32, 3, 32), dim3(32, 8)>>>(X_obs, 32, 0);
    athx_transpose_kernel<<<dim3(NS / 32, 3, 56), dim3(32, 8)>>>(X_wrf, 56, 1);

    athx_lstm_mma<<<128, 512, SM_TOTAL>>>(oWih, oWhh, obih, obhh,
                                          wWih, wWhh, wbih, wbhh);

    athx_head_kernel<<<dim3(NS / 128, 2), 1024, HEAD_SMEM>>>(
        fW1, fb1, fW2, fb2, fW3, fb3,
        oW1, ob1, oW2, ob2, oW3, ob3, out);
}

// round 11
// speedup vs baseline: 4.1356x; 1.1040x over previous
#include <cuda_runtime.h>
#include <cuda_fp16.h>
#include <cstdint>

#define NS     8192
#define TSTEPS 72

typedef unsigned long long u64;
typedef unsigned int       u32;
typedef unsigned short     u16;

// ---------------- scratch (device globals; no allocation allowed) ----------
__device__ u16   g_xt_obs[TSTEPS * 32 * NS];   // [T][C1][N] fp16
__device__ u16   g_xt_wrf[TSTEPS * 56 * NS];   // [T][C2][N] fp16
__device__ float g_featT[128 * NS];            // [128][N]

// ---------------- smem layout (bytes) for LSTM kernel ----------------------
#define SM_AH    0          // h [2 groups][64x64] fp16 sample-major, 2x8 KB
#define SM_BH    16384      // Whh [256x64] fp16, 32 KB
#define SM_BX    49152      // Wih [256x64] fp16, 32 KB
#define SM_ST0   81920      // stage buf0: half [64 ch rows][128 samples] 16 KB
#define SM_ST1   98304      // stage buf1
#define SM_TOTAL 114688

// ---------------- math helpers ---------------------------------------------
__device__ __forceinline__ float tanh_a(float x) {
    float y; asm("tanh.approx.f32 %0, %1;" : "=f"(y) : "f"(x)); return y;
}
__device__ __forceinline__ float sigm_a(float x) {
    return fmaf(0.5f, tanh_a(0.5f * x), 0.5f);
}

// ---------------- PTX helpers -----------------------------------------------
__device__ __forceinline__ u32 smem_u32(const void* p) {
    u32 a;
    asm("{ .reg .u64 t; cvta.to.shared.u64 t, %1; cvt.u32.u64 %0, t; }" : "=r"(a) : "l"(p));
    return a;
}
__device__ __forceinline__ void cp_async16(char* smem_dst, const void* gsrc) {
    u32 sa = smem_u32(smem_dst);
    asm volatile("cp.async.ca.shared.global [%0], [%1], 16;\n" :: "r"(sa), "l"(gsrc));
}
__device__ __forceinline__ void cp_commit()   { asm volatile("cp.async.commit_group;\n"); }
__device__ __forceinline__ void cp_wait_all() { asm volatile("cp.async.wait_all;\n"); }

__device__ __forceinline__ void ldsm4(u32& r0, u32& r1, u32& r2, u32& r3, u32 addr) {
    asm volatile("ldmatrix.sync.aligned.m8n8.x4.shared.b16 {%0,%1,%2,%3}, [%4];"
                 : "=r"(r0), "=r"(r1), "=r"(r2), "=r"(r3) : "r"(addr));
}
__device__ __forceinline__ void ldsm4t(u32& r0, u32& r1, u32& r2, u32& r3, u32 addr) {
    asm volatile("ldmatrix.sync.aligned.m8n8.x4.trans.shared.b16 {%0,%1,%2,%3}, [%4];"
                 : "=r"(r0), "=r"(r1), "=r"(r2), "=r"(r3) : "r"(addr));
}
__device__ __forceinline__ void mma_fp16(float& d0, float& d1, float& d2, float& d3,
                                         u32 a0, u32 a1, u32 a2, u32 a3,
                                         u32 b0, u32 b1) {
    asm volatile("mma.sync.aligned.m16n8k16.row.col.f32.f16.f16.f32 "
                 "{%0,%1,%2,%3}, {%4,%5,%6,%7}, {%8,%9}, {%0,%1,%2,%3};"
                 : "+f"(d0), "+f"(d1), "+f"(d2), "+f"(d3)
                 : "r"(a0), "r"(a1), "r"(a2), "r"(a3), "r"(b0), "r"(b1));
}

// sample-major: row stride 128B, 16B chunk index ^= (row&7)
__device__ __forceinline__ u32 swz(u32 row, u32 chunk) {
    return row * 128u + ((chunk ^ (row & 7u)) << 4);
}

// B row permutation: gate-quad-aligned fragment ownership
__device__ __forceinline__ int brow(int g) {
    int q = g >> 6, j = g & 63;
    int warpN = j >> 4, jl = j & 15;
    int hi = jl >> 3, a = (jl & 7) >> 1, e = jl & 1;
    return warpN * 64 + 8 * (q + 4 * hi) + 2 * a + e;
}

// group-scoped barrier: 256 threads, ids 1 and 2
#define GBAR(id) asm volatile("bar.sync %0, 256;" :: "r"(id) : "memory")

// ---------------- kernel 1: transpose [N][C][T] -> [T][C][N] fp16 -----------
__global__ void athx_transpose_kernel(const float* __restrict__ in, int C, int which) {
    __shared__ float tile[32][33];
    u16* out = which ? g_xt_wrf : g_xt_obs;
    const int c  = blockIdx.z;
    const int n0 = blockIdx.x * 32;
    const int t0 = blockIdx.y * 32;
    const int tx = threadIdx.x, ty = threadIdx.y;
    #pragma unroll
    for (int r = 0; r < 4; ++r) {
        int n = n0 + ty + r * 8;
        int t = t0 + tx;
        if (t < TSTEPS)
            tile[ty + r * 8][tx] = in[((size_t)n * C + c) * TSTEPS + t];
    }
    __syncthreads();
    #pragma unroll
    for (int r = 0; r < 4; ++r) {
        int t = t0 + ty + r * 8;
        int n = n0 + tx;
        if (t < TSTEPS)
            out[((size_t)t * C + c) * NS + n] =
                __half_as_ushort(__float2half_rn(tile[tx][ty + r * 8]));
    }
}

// ---------------- kernel 2: HMMA dual-LSTM, anti-phase 2-group --------------
// 512 thr = 2 groups x 8 warps; each group: independent 64-sample LSTM slice.
__global__ __launch_bounds__(512, 1)
void athx_lstm_mma(const float* __restrict__ oWih, const float* __restrict__ oWhh,
                   const float* __restrict__ obih, const float* __restrict__ obhh,
                   const float* __restrict__ wWih, const float* __restrict__ wWhh,
                   const float* __restrict__ wbih, const float* __restrict__ wbhh)
{
    extern __shared__ char smem[];
    const bool wrf = (blockIdx.x >= 64);
    const int  C   = wrf ? 56 : 32;
    const int  KCX = wrf ? 4 : 2;         // x k-chunks (16 cols each)
    const u16* xt = wrf ? g_xt_wrf : g_xt_obs;
    const float* Wih = wrf ? wWih : oWih;
    const float* Whh = wrf ? wWhh : oWhh;
    const float* bih = wrf ? wbih : obih;
    const float* bhh = wrf ? wbhh : obhh;
    const int n0  = (blockIdx.x & 63) * 128;
    const int tid = threadIdx.x;
    const int lane = tid & 31;
    const int grp  = tid >> 8;            // 0 or 1 (8 warps each)
    const int tg   = tid & 255;           // thread-in-group
    const int wg   = (tid >> 5) & 7;      // warp-in-group
    const int warpM = wg >> 2;            // 0..1 (32 samples each within group)
    const int warpN = wg & 3;

    const u32 smb = smem_u32(smem);
    const int barid = 1 + grp;

    // per-group x fetch: chunks v = grp*8 .. grp*8+7 of each channel row
#define XFETCH(TIDX, STG_OFF)                                                    \
    {                                                                            \
        const u16* src = xt + (size_t)(TIDX) * C * NS;                           \
        char* dst = smem + (STG_OFF);                                            \
        for (int i = tg; i < C * 8; i += 256) {                                  \
            int ch = i >> 3, vv = (i & 7) + grp * 8;                             \
            cp_async16(dst + ch * 256 + vv * 16,                                 \
                       src + (size_t)ch * NS + n0 + (vv ^ (ch & 7)) * 8);        \
        }                                                                        \
        cp_commit();                                                             \
    }

    // ---- zero ALL smem (h=0, BX pad cols, stage pad rows) ----
    for (int i = tid; i < SM_TOTAL / 16; i += 512)
        ((uint4*)smem)[i] = make_uint4(0, 0, 0, 0);
    __syncthreads();

    // ---- prefetch x_0 (own group's half) ----
    XFETCH(0, SM_ST0)

    // ---- fill B_h (Whh fp16), B_x (Wih fp16) — full CTA ----
    for (int i = tid; i < 256 * 64; i += 512) {
        int g = i >> 6, k = i & 63;
        u32 off = swz((u32)brow(g), (u32)(k >> 3)) + (k & 7) * 2;
        *(__half*)(smem + SM_BH + off) = __float2half_rn(Whh[i]);
    }
    for (int i = tid; i < 256 * C; i += 512) {
        int g = i / C, ch = i - g * C;
        u32 off = swz((u32)brow(g), (u32)(ch >> 3)) + (ch & 7) * 2;
        *(__half*)(smem + SM_BX + off) = __float2half_rn(Wih[i]);
    }

    // ---- bias into registers (per-thread 16 gates, fp32) ----
    const int jbase = warpN * 16 + (lane & 3) * 2;
    float breg[16];
    #pragma unroll
    for (int q = 0; q < 4; ++q)
        #pragma unroll
        for (int h2i = 0; h2i < 2; ++h2i)
            #pragma unroll
            for (int e = 0; e < 2; ++e) {
                int g = q * 64 + jbase + h2i * 8 + e;
                breg[q * 4 + h2i * 2 + e] = bih[g] + bhh[g];
            }

    cp_wait_all();
    __syncthreads();    // B fills + zeros + both stage halves visible

    // ---- per-thread ldmatrix geometry ----
    const int g8 = lane >> 3, l = lane & 7;
    const u32 aRow = (u32)(warpM * 32 + (g8 & 1) * 8 + l);   // 0..47 local
    const u32 bRow = (u32)(warpN * 64 + ((g8 >> 1) & 1) * 8 + l);
    const u32 gAc = (u32)(g8 >> 1);
    const u32 gBc = (u32)(g8 & 1);
    const u32 lx = (u32)l;
    const u32 aB  = smb + SM_AH + (u32)grp * 8192u + aRow * 128;
    const u32 bhB = smb + SM_BH + bRow * 128;
    const u32 bxB = smb + SM_BX + bRow * 128;
    // trans-ldsm geometry: channel rows shared; sample chunks offset by group
    const u32 stRowB = (u32)(gAc * 8 + (u32)l) * 256u;
    const u32 sxT0 = (((u32)(warpM * 4) + (u32)(g8 & 1) + (u32)(grp * 8)) ^ (u32)l) << 4;
    const u32 sxT1 = (((u32)(warpM * 4) + (u32)(g8 & 1) + 2u + (u32)(grp * 8)) ^ (u32)l) << 4;

    float acc[2][8][4];
    float cst[16];
    #pragma unroll
    for (int i = 0; i < 16; ++i) cst[i] = 0.0f;

    // sample-major A (h-part, group-local tile)
#define MMA1(A_B, B_B, KC)                                                              \
    for (int ks = 0; ks < (KC); ++ks) {                                                 \
        u32 a[8];                                                                       \
        u32 ca = ((2u * ks + gAc) ^ lx) << 4;                                           \
        ldsm4(a[0], a[1], a[2], a[3], (A_B) + ca);                                      \
        ldsm4(a[4], a[5], a[6], a[7], (A_B) + 2048 + ca);                               \
        u32 cb = ((2u * ks + gBc) ^ lx) << 4;                                           \
        _Pragma("unroll")                                                               \
        for (int ntp = 0; ntp < 4; ++ntp) {                                             \
            u32 b0, b1, b2, b3;                                                         \
            ldsm4(b0, b1, b2, b3, (B_B) + ntp * 2048 + cb);                             \
            _Pragma("unroll")                                                           \
            for (int mt = 0; mt < 2; ++mt) {                                            \
                mma_fp16(acc[mt][2*ntp][0], acc[mt][2*ntp][1], acc[mt][2*ntp][2], acc[mt][2*ntp][3], \
                         a[4*mt], a[4*mt+1], a[4*mt+2], a[4*mt+3], b0, b1);             \
                mma_fp16(acc[mt][2*ntp+1][0], acc[mt][2*ntp+1][1], acc[mt][2*ntp+1][2], acc[mt][2*ntp+1][3], \
                         a[4*mt], a[4*mt+1], a[4*mt+2], a[4*mt+3], b2, b3);             \
            }                                                                           \
        }                                                                               \
    }

    // channel-major stage A via ldmatrix.trans (x-part)
#define MMA1T(STG_ABS, B_B, KC)                                                         \
    for (int ks = 0; ks < (KC); ++ks) {                                                 \
        u32 a[8];                                                                       \
        u32 ab = (STG_ABS) + stRowB + (u32)ks * 4096u;                                  \
        ldsm4t(a[0], a[1], a[2], a[3], ab + sxT0);                                      \
        ldsm4t(a[4], a[5], a[6], a[7], ab + sxT1);                                      \
        u32 cb = ((2u * ks + gBc) ^ lx) << 4;                                           \
        _Pragma("unroll")                                                               \
        for (int ntp = 0; ntp < 4; ++ntp) {                                             \
            u32 b0, b1, b2, b3;                                                         \
            ldsm4(b0, b1, b2, b3, (B_B) + ntp * 2048 + cb);                             \
            _Pragma("unroll")                                                           \
            for (int mt = 0; mt < 2; ++mt) {                                            \
                mma_fp16(acc[mt][2*ntp][0], acc[mt][2*ntp][1], acc[mt][2*ntp][2], acc[mt][2*ntp][3], \
                         a[4*mt], a[4*mt+1], a[4*mt+2], a[4*mt+3], b0, b1);             \
                mma_fp16(acc[mt][2*ntp+1][0], acc[mt][2*ntp+1][1], acc[mt][2*ntp+1][2], acc[mt][2*ntp+1][3], \
                         a[4*mt], a[4*mt+1], a[4*mt+2], a[4*mt+3], b2, b3);             \
            }                                                                           \
        }                                                                               \
    }

#define ZERO_ACC()                                                                      \
    _Pragma("unroll")                                                                   \
    for (int mt = 0; mt < 2; ++mt)                                                      \
        _Pragma("unroll")                                                               \
        for (int nt = 0; nt < 8; ++nt)                                                  \
            _Pragma("unroll")                                                           \
            for (int r = 0; r < 4; ++r) acc[mt][nt][r] = 0.0f;

    // ---- prologue x-mma: acc = Xpart_0 (from stage0, trans) ----
    ZERO_ACC()
    MMA1T(smb + SM_ST0, bxB, KCX)

    for (int t = 0; t < TSTEPS; ++t) {
        GBAR(barid);   // gbar1: group's h STS from t-1 visible; stage slot free

        // fetch own group's half of x_{t+1} (overlaps h-mma)
        if (t + 1 < TSTEPS) {
            XFETCH(t + 1, ((t + 1) & 1) ? SM_ST1 : SM_ST0)
        }

        // h-part: acc += h_{t-1} . Whh^T   (group-local h tile)
        MMA1(aB, bhB, 4)

        // ---- epilogue: fp32 gates, fp32 cell state ----
        float hval[16];
        #pragma unroll
        for (int mt = 0; mt < 2; ++mt)
            #pragma unroll
            for (int d = 0; d < 2; ++d)
                #pragma unroll
                for (int h2i = 0; h2i < 2; ++h2i)
                    #pragma unroll
                    for (int e = 0; e < 2; ++e) {
                        int r = 2 * d + e;
                        int ci = ((mt * 2 + d) * 2 + h2i) * 2 + e;
                        int bi = h2i * 2 + e;
                        float gi = sigm_a(acc[mt][4*h2i + 0][r] + breg[bi]);
                        float gf = sigm_a(acc[mt][4*h2i + 1][r] + breg[4 + bi]);
                        float gg = tanh_a(acc[mt][4*h2i + 2][r] + breg[8 + bi]);
                        float go = sigm_a(acc[mt][4*h2i + 3][r] + breg[12 + bi]);
                        float cc = fmaf(gf, cst[ci], gi * gg);
                        cst[ci] = cc;
                        hval[ci] = go * tanh_a(cc);
                    }

        cp_wait_all();     // own x_{t+1} chunks landed
        GBAR(barid);       // gbar2: group staged x_{t+1}; group h-mma reads done

        if (t == TSTEPS - 1) {
            const int off = wrf ? 64 : 0;
            #pragma unroll
            for (int mt = 0; mt < 2; ++mt)
                #pragma unroll
                for (int d = 0; d < 2; ++d)
                    #pragma unroll
                    for (int h2i = 0; h2i < 2; ++h2i)
                        #pragma unroll
                        for (int e = 0; e < 2; ++e) {
                            int s = grp * 64 + warpM * 32 + mt * 16 + (lane >> 2) + 8 * d;
                            int j = warpN * 16 + h2i * 8 + (lane & 3) * 2 + e;
                            int ci = ((mt * 2 + d) * 2 + h2i) * 2 + e;
                            g_featT[(size_t)(off + j) * NS + n0 + s] = hval[ci];
                        }
        } else {
            // STS h_t -> group-local AH (fp16, sample-major)
            #pragma unroll
            for (int mt = 0; mt < 2; ++mt)
                #pragma unroll
                for (int d = 0; d < 2; ++d)
                    #pragma unroll
                    for (int h2i = 0; h2i < 2; ++h2i) {
                        int ci = ((mt * 2 + d) * 2 + h2i) * 2;
                        __half hh0 = __float2half_rn(hval[ci]);
                        __half hh1 = __float2half_rn(hval[ci + 1]);
                        u32 hi32 = (u32)__half_as_ushort(hh0) | ((u32)__half_as_ushort(hh1) << 16);
                        u32 s  = (u32)(warpM * 32 + mt * 16 + (lane >> 2) + 8 * d);
                        u32 jp = (u32)(warpN * 16 + h2i * 8 + (lane & 3) * 2);
                        u32 off = (u32)grp * 8192u + swz(s, jp >> 3) + (jp & 7) * 2;
                        *(u32*)(smem + SM_AH + off) = hi32;
                    }
            // tail x-mma for t+1 straight from stage (trans) — anti-phase overlap
            ZERO_ACC()
            MMA1T(((t + 1) & 1) ? (smb + SM_ST1) : (smb + SM_ST0), bxB, KCX)
        }
    }
#undef MMA1
#undef MMA1T
#undef ZERO_ACC
#undef XFETCH
}

// ---------------- kernel 3: MLP heads (512 threads, 4 samples/thread) -------
#define SPAD 132
__device__ __forceinline__ u64 dup2(float x) {
    u64 r; asm("mov.b64 %0, {%1,%1};" : "=l"(r) : "f"(x)); return r;
}
__device__ __forceinline__ void unpack2(u64 v, float& x, float& y) {
    asm("mov.b64 {%0,%1}, %2;" : "=f"(x), "=f"(y) : "l"(v));
}
__device__ __forceinline__ u64 ffma2(u64 a, u64 b, u64 c) {
    u64 d; asm("fma.rn.f32x2 %0, %1, %2, %3;" : "=l"(d) : "l"(a), "l"(b), "l"(c)); return d;
}

template <int IN, int OUT, bool RELU>
__device__ __forceinline__ void athx_layer4(const float* __restrict__ A,
                                            const float* __restrict__ wt,
                                            const float* __restrict__ bs,
                                            float* __restrict__ Bout,
                                            int gx, int sx) {
    constexpr int R = OUT / 16;
    u64 acc2[2][R];
    #pragma unroll
    for (int sp = 0; sp < 2; ++sp)
        #pragma unroll
        for (int r = 0; r < R; ++r) acc2[sp][r] = 0ull;
    for (int k = 0; k < IN; ++k) {
        ulonglong2 p = *(const ulonglong2*)(A + k * SPAD + sx * 4);
        u64 a2[2] = {p.x, p.y};
        #pragma unroll
        for (int r = 0; r < R; ++r) {
            u64 b2 = dup2(wt[k * OUT + gx + 16 * r]);
            #pragma unroll
            for (int sp = 0; sp < 2; ++sp) acc2[sp][r] = ffma2(a2[sp], b2, acc2[sp][r]);
        }
    }
    #pragma unroll
    for (int r = 0; r < R; ++r) {
        int u = gx + 16 * r;
        float bb = bs[u];
        float hv[4];
        #pragma unroll
        for (int sp = 0; sp < 2; ++sp) {
            float v0, v1;
            unpack2(acc2[sp][r], v0, v1);
            v0 += bb; v1 += bb;
            hv[2 * sp]     = RELU ? fmaxf(v0, 0.0f) : v0;
            hv[2 * sp + 1] = RELU ? fmaxf(v1, 0.0f) : v1;
        }
        *(float4*)(Bout + u * SPAD + sx * 4) = make_float4(hv[0], hv[1], hv[2], hv[3]);
    }
}

__global__ __launch_bounds__(512, 1) void athx_head_kernel(
    const float* __restrict__ fW1, const float* __restrict__ fb1,
    const float* __restrict__ fW2, const float* __restrict__ fb2,
    const float* __restrict__ fW3, const float* __restrict__ fb3,
    const float* __restrict__ oW1, const float* __restrict__ ob1,
    const float* __restrict__ oW2, const float* __restrict__ ob2,
    const float* __restrict__ oW3, const float* __restrict__ ob3,
    float* __restrict__ out)
{
    extern __shared__ float sm[];
    float* A   = sm;
    float* B   = A + 128 * SPAD;
    float* w1t = B + 96 * SPAD;
    float* w2t = w1t + 128 * 96;
    float* w3t = w2t + 96 * 64;
    float* bs1 = w3t + 64 * 48;
    float* bs2 = bs1 + 96;
    float* bs3 = bs2 + 64;

    const int head = blockIdx.y;
    const float* W1 = head ? oW1 : fW1; const float* b1 = head ? ob1 : fb1;
    const float* W2 = head ? oW2 : fW2; const float* b2 = head ? ob2 : fb2;
    const float* W3 = head ? oW3 : fW3; const float* b3 = head ? ob3 : fb3;
    const int n0  = blockIdx.x * 128;
    const int tid = threadIdx.x;
    const int gx  = tid & 15, sx = tid >> 4;   // sx 0..31, 4 samples each

    for (int idx = tid; idx < 128 * 128; idx += 512) {
        int k = idx >> 7, s = idx & 127;
        A[k * SPAD + s] = g_featT[(size_t)k * NS + n0 + s];
    }
    for (int idx = tid; idx < 96 * 128; idx += 512) {
        int u = idx >> 7, k = idx & 127;
        w1t[k * 96 + u] = W1[idx];
    }
    for (int idx = tid; idx < 64 * 96; idx += 512) {
        int u = idx / 96, k = idx - u * 96;
        w2t[k * 64 + u] = W2[idx];
    }
    for (int idx = tid; idx < 48 * 64; idx += 512) {
        int u = idx >> 6, k = idx & 63;
        w3t[k * 48 + u] = W3[idx];
    }
    if (tid < 96) bs1[tid] = b1[tid];
    if (tid < 64) bs2[tid] = b2[tid];
    if (tid < 48) bs3[tid] = b3[tid];
    __syncthreads();

    athx_layer4<128, 96, true>(A, w1t, bs1, B, gx, sx);
    __syncthreads();
    athx_layer4<96, 64, true>(B, w2t, bs2, A, gx, sx);
    __syncthreads();

    {
        u64 acc2[2][3];
        #pragma unroll
        for (int sp = 0; sp < 2; ++sp)
            #pragma unroll
            for (int r = 0; r < 3; ++r) acc2[sp][r] = 0ull;
        for (int k = 0; k < 64; ++k) {
            ulonglong2 p = *(const ulonglong2*)(A + k * SPAD + sx * 4);
            u64 a2[2] = {p.x, p.y};
            #pragma unroll
            for (int r = 0; r < 3; ++r) {
                u64 b2 = dup2(w3t[k * 48 + gx + 16 * r]);
                #pragma unroll
                for (int sp = 0; sp < 2; ++sp) acc2[sp][r] = ffma2(a2[sp], b2, acc2[sp][r]);
            }
        }
        #pragma unroll
        for (int r = 0; r < 3; ++r) {
            int u = gx + 16 * r;
            float bb = bs3[u];
            #pragma unroll
            for (int sp = 0; sp < 2; ++sp) {
                float v0, v1;
                unpack2(acc2[sp][r], v0, v1);
                int n = n0 + sx * 4 + 2 * sp;
                out[(size_t)n * 96 + head * 48 + u]       = v0 + bb;
                out[(size_t)(n + 1) * 96 + head * 48 + u] = v1 + bb;
            }
        }
    }
}

// ---------------- launch ----------------------------------------------------
extern "C" void kernel_launch(void* const* d_in, const int* in_sizes, int n_in,
                              void* d_out, int out_size) {
    const float* X_obs  = (const float*)d_in[0];
    const float* X_wrf  = (const float*)d_in[1];
    const float* oWih   = (const float*)d_in[2];
    const float* oWhh   = (const float*)d_in[3];
    const float* obih   = (const float*)d_in[4];
    const float* obhh   = (const float*)d_in[5];
    const float* wWih   = (const float*)d_in[6];
    const float* wWhh   = (const float*)d_in[7];
    const float* wbih   = (const float*)d_in[8];
    const float* wbhh   = (const float*)d_in[9];
    const float* fW1 = (const float*)d_in[10]; const float* fb1 = (const float*)d_in[11];
    const float* fW2 = (const float*)d_in[12]; const float* fb2 = (const float*)d_in[13];
    const float* fW3 = (const float*)d_in[14]; const float* fb3 = (const float*)d_in[15];
    const float* oW1 = (const float*)d_in[16]; const float* ob1 = (const float*)d_in[17];
    const float* oW2 = (const float*)d_in[18]; const float* ob2 = (const float*)d_in[19];
    const float* oW3 = (const float*)d_in[20]; const float* ob3 = (const float*)d_in[21];
    float* out = (float*)d_out;

    const int HEAD_SMEM = (128 * SPAD + 96 * SPAD + 128 * 96 + 96 * 64 + 64 * 48
                           + 96 + 64 + 48) * 4;
    cudaFuncSetAttribute(athx_lstm_mma, cudaFuncAttributeMaxDynamicSharedMemorySize, SM_TOTAL);
    cudaFuncSetAttribute(athx_head_kernel, cudaFuncAttributeMaxDynamicSharedMemorySize, HEAD_SMEM);

    athx_transpose_kernel<<<dim3(NS / 32, 3, 32), dim3(32, 8)>>>(X_obs, 32, 0);
    athx_transpose_kernel<<<dim3(NS / 32, 3, 56), dim3(32, 8)>>>(X_wrf, 56, 1);

    athx_lstm_mma<<<128, 512, SM_TOTAL>>>(oWih, oWhh, obih, obhh,
                                          wWih, wWhh, wbih, wbhh);

    athx_head_kernel<<<dim3(NS / 128, 2), 512, HEAD_SMEM>>>(
        fW1, fb1, fW2, fb2, fW3, fb3,
        oW1, ob1, oW2, ob2, oW3, ob3, out);
}

// round 12
// speedup vs baseline: 4.2132x; 1.0188x over previous
#include <cuda_runtime.h>
#include <cuda_fp16.h>
#include <cstdint>

#define NS     8192
#define TSTEPS 72

typedef unsigned long long u64;
typedef unsigned int       u32;
typedef unsigned short     u16;

// ---------------- scratch (device globals; no allocation allowed) ----------
__device__ u16   g_xt_obs[TSTEPS * 32 * NS];   // [T][C1][N] fp16
__device__ u16   g_xt_wrf[TSTEPS * 56 * NS];   // [T][C2][N] fp16
__device__ float g_featT[128 * NS];            // [128][N]

// ---------------- smem layout (bytes) for LSTM kernel ----------------------
#define SM_AH    0          // h [4 groups][32x64] fp16 sample-major, 4x4 KB
#define SM_BH    16384      // Whh [256x64] fp16, 32 KB
#define SM_BX    49152      // Wih [256x64] fp16, 32 KB
#define SM_ST0   81920      // stage buf0: [4 groups][64 ch rows x 80B]
#define STG_GRP  5120       // 64 rows x 80 B
#define STG_BUF  20480      // 4 groups
#define SM_ST1   102400     // stage buf1
#define SM_TOTAL 122880

// ---------------- math helpers ---------------------------------------------
__device__ __forceinline__ float tanh_a(float x) {
    float y; asm("tanh.approx.f32 %0, %1;" : "=f"(y) : "f"(x)); return y;
}
__device__ __forceinline__ float sigm_a(float x) {
    return fmaf(0.5f, tanh_a(0.5f * x), 0.5f);
}

// ---------------- PTX helpers -----------------------------------------------
__device__ __forceinline__ u32 smem_u32(const void* p) {
    u32 a;
    asm("{ .reg .u64 t; cvta.to.shared.u64 t, %1; cvt.u32.u64 %0, t; }" : "=r"(a) : "l"(p));
    return a;
}
__device__ __forceinline__ void cp_async16(char* smem_dst, const void* gsrc) {
    u32 sa = smem_u32(smem_dst);
    asm volatile("cp.async.ca.shared.global [%0], [%1], 16;\n" :: "r"(sa), "l"(gsrc));
}
__device__ __forceinline__ void cp_commit()   { asm volatile("cp.async.commit_group;\n"); }
__device__ __forceinline__ void cp_wait_all() { asm volatile("cp.async.wait_all;\n"); }

__device__ __forceinline__ void ldsm4(u32& r0, u32& r1, u32& r2, u32& r3, u32 addr) {
    asm volatile("ldmatrix.sync.aligned.m8n8.x4.shared.b16 {%0,%1,%2,%3}, [%4];"
                 : "=r"(r0), "=r"(r1), "=r"(r2), "=r"(r3) : "r"(addr));
}
__device__ __forceinline__ void ldsm4t(u32& r0, u32& r1, u32& r2, u32& r3, u32 addr) {
    asm volatile("ldmatrix.sync.aligned.m8n8.x4.trans.shared.b16 {%0,%1,%2,%3}, [%4];"
                 : "=r"(r0), "=r"(r1), "=r"(r2), "=r"(r3) : "r"(addr));
}
__device__ __forceinline__ void mma_fp16(float& d0, float& d1, float& d2, float& d3,
                                         u32 a0, u32 a1, u32 a2, u32 a3,
                                         u32 b0, u32 b1) {
    asm volatile("mma.sync.aligned.m16n8k16.row.col.f32.f16.f16.f32 "
                 "{%0,%1,%2,%3}, {%4,%5,%6,%7}, {%8,%9}, {%0,%1,%2,%3};"
                 : "+f"(d0), "+f"(d1), "+f"(d2), "+f"(d3)
                 : "r"(a0), "r"(a1), "r"(a2), "r"(a3), "r"(b0), "r"(b1));
}

// sample-major: row stride 128B, 16B chunk index ^= (row&7)
__device__ __forceinline__ u32 swz(u32 row, u32 chunk) {
    return row * 128u + ((chunk ^ (row & 7u)) << 4);
}

// B row permutation: gate-quad-aligned fragment ownership
__device__ __forceinline__ int brow(int g) {
    int q = g >> 6, j = g & 63;
    int warpN = j >> 4, jl = j & 15;
    int hi = jl >> 3, a = (jl & 7) >> 1, e = jl & 1;
    return warpN * 64 + 8 * (q + 4 * hi) + 2 * a + e;
}

// group-scoped barrier: 128 threads, ids 1..4
#define GBAR(id) asm volatile("bar.sync %0, 128;" :: "r"(id) : "memory")

// ---------------- kernel 1: transpose [N][C][T] -> [T][C][N] fp16 -----------
__global__ void athx_transpose_kernel(const float* __restrict__ in, int C, int which) {
    __shared__ float tile[32][33];
    u16* out = which ? g_xt_wrf : g_xt_obs;
    const int c  = blockIdx.z;
    const int n0 = blockIdx.x * 32;
    const int t0 = blockIdx.y * 32;
    const int tx = threadIdx.x, ty = threadIdx.y;
    #pragma unroll
    for (int r = 0; r < 4; ++r) {
        int n = n0 + ty + r * 8;
        int t = t0 + tx;
        if (t < TSTEPS)
            tile[ty + r * 8][tx] = in[((size_t)n * C + c) * TSTEPS + t];
    }
    __syncthreads();
    #pragma unroll
    for (int r = 0; r < 4; ++r) {
        int t = t0 + ty + r * 8;
        int n = n0 + tx;
        if (t < TSTEPS)
            out[((size_t)t * C + c) * NS + n] =
                __half_as_ushort(__float2half_rn(tile[tx][ty + r * 8]));
    }
}

// ---------------- kernel 2: HMMA dual-LSTM, 4-group anti-phase --------------
// 512 thr = 4 groups x 4 warps; each group: independent 32-sample LSTM slice.
__global__ __launch_bounds__(512, 1)
void athx_lstm_mma(const float* __restrict__ oWih, const float* __restrict__ oWhh,
                   const float* __restrict__ obih, const float* __restrict__ obhh,
                   const float* __restrict__ wWih, const float* __restrict__ wWhh,
                   const float* __restrict__ wbih, const float* __restrict__ wbhh)
{
    extern __shared__ char smem[];
    const bool wrf = (blockIdx.x >= 64);
    const int  C   = wrf ? 56 : 32;
    const int  KCX = wrf ? 4 : 2;         // x k-chunks (16 cols each)
    const u16* xt = wrf ? g_xt_wrf : g_xt_obs;
    const float* Wih = wrf ? wWih : oWih;
    const float* Whh = wrf ? wWhh : oWhh;
    const float* bih = wrf ? wbih : obih;
    const float* bhh = wrf ? wbhh : obhh;
    const int n0  = (blockIdx.x & 63) * 128;
    const int tid = threadIdx.x;
    const int lane = tid & 31;
    const int grp  = tid >> 7;            // 0..3 (4 warps each)
    const int tg   = tid & 127;           // thread-in-group
    const int warpN = (tid >> 5) & 3;     // warp-in-group = gate column group

    const u32 smb = smem_u32(smem);
    const int barid = 1 + grp;

    // per-group x fetch into padded-stride stage: [ch row x 80B], 4 chunks/row
#define XFETCH(TIDX, STG_OFF)                                                    \
    {                                                                            \
        const u16* src = xt + (size_t)(TIDX) * C * NS + n0 + grp * 32;           \
        char* dst = smem + (STG_OFF) + grp * STG_GRP;                            \
        for (int i = tg; i < C * 4; i += 128) {                                  \
            int ch = i >> 2, j = i & 3;                                          \
            cp_async16(dst + ch * 80 + j * 16,                                   \
                       src + (size_t)ch * NS + j * 8);                           \
        }                                                                        \
        cp_commit();                                                             \
    }

    // ---- zero ALL smem (h=0, BX pad cols, stage pad rows) ----
    for (int i = tid; i < SM_TOTAL / 16; i += 512)
        ((uint4*)smem)[i] = make_uint4(0, 0, 0, 0);
    __syncthreads();

    // ---- prefetch x_0 (own group's quarter) ----
    XFETCH(0, SM_ST0)

    // ---- fill B_h (Whh fp16), B_x (Wih fp16) — full CTA ----
    for (int i = tid; i < 256 * 64; i += 512) {
        int g = i >> 6, k = i & 63;
        u32 off = swz((u32)brow(g), (u32)(k >> 3)) + (k & 7) * 2;
        *(__half*)(smem + SM_BH + off) = __float2half_rn(Whh[i]);
    }
    for (int i = tid; i < 256 * C; i += 512) {
        int g = i / C, ch = i - g * C;
        u32 off = swz((u32)brow(g), (u32)(ch >> 3)) + (ch & 7) * 2;
        *(__half*)(smem + SM_BX + off) = __float2half_rn(Wih[i]);
    }

    // ---- bias into registers (per-thread 16 gates, fp32) ----
    const int jbase = warpN * 16 + (lane & 3) * 2;
    float breg[16];
    #pragma unroll
    for (int q = 0; q < 4; ++q)
        #pragma unroll
        for (int h2i = 0; h2i < 2; ++h2i)
            #pragma unroll
            for (int e = 0; e < 2; ++e) {
                int g = q * 64 + jbase + h2i * 8 + e;
                breg[q * 4 + h2i * 2 + e] = bih[g] + bhh[g];
            }

    cp_wait_all();
    __syncthreads();    // B fills + zeros + all stage quarters visible

    // ---- per-thread ldmatrix geometry ----
    const int g8 = lane >> 3, l = lane & 7;
    const u32 aRow = (u32)((g8 & 1) * 8 + l);                // 0..15 local
    const u32 bRow = (u32)(warpN * 64 + ((g8 >> 1) & 1) * 8 + l);
    const u32 gAc = (u32)(g8 >> 1);
    const u32 gBc = (u32)(g8 & 1);
    const u32 lx = (u32)l;
    const u32 aB  = smb + SM_AH + (u32)grp * 4096u + aRow * 128;
    const u32 bhB = smb + SM_BH + bRow * 128;
    const u32 bxB = smb + SM_BX + bRow * 128;
    // trans-ldsm geometry for padded-stride stage (no XOR needed)
    const u32 stRowB = (u32)(gAc * 8 + (u32)l) * 80u;        // channel row offset
    const u32 sxT0 = ((u32)(g8 & 1)) << 4;                   // sample chunks 0/1
    const u32 sxT1 = sxT0 + 32u;                             // sample chunks 2/3

    float acc[2][8][4];
    float cst[16];
    #pragma unroll
    for (int i = 0; i < 16; ++i) cst[i] = 0.0f;

    // sample-major A (h-part, group-local 32x64 tile)
#define MMA1(A_B, B_B, KC)                                                              \
    for (int ks = 0; ks < (KC); ++ks) {                                                 \
        u32 a[8];                                                                       \
        u32 ca = ((2u * ks + gAc) ^ lx) << 4;                                           \
        ldsm4(a[0], a[1], a[2], a[3], (A_B) + ca);                                      \
        ldsm4(a[4], a[5], a[6], a[7], (A_B) + 2048 + ca);                               \
        u32 cb = ((2u * ks + gBc) ^ lx) << 4;                                           \
        _Pragma("unroll")                                                               \
        for (int ntp = 0; ntp < 4; ++ntp) {                                             \
            u32 b0, b1, b2, b3;                                                         \
            ldsm4(b0, b1, b2, b3, (B_B) + ntp * 2048 + cb);                             \
            _Pragma("unroll")                                                           \
            for (int mt = 0; mt < 2; ++mt) {                                            \
                mma_fp16(acc[mt][2*ntp][0], acc[mt][2*ntp][1], acc[mt][2*ntp][2], acc[mt][2*ntp][3], \
                         a[4*mt], a[4*mt+1], a[4*mt+2], a[4*mt+3], b0, b1);             \
                mma_fp16(acc[mt][2*ntp+1][0], acc[mt][2*ntp+1][1], acc[mt][2*ntp+1][2], acc[mt][2*ntp+1][3], \
                         a[4*mt], a[4*mt+1], a[4*mt+2], a[4*mt+3], b2, b3);             \
            }                                                                           \
        }                                                                               \
    }

    // padded-stride stage A via ldmatrix.trans (x-part)
#define MMA1T(STG_ABS, B_B, KC)                                                         \
    for (int ks = 0; ks < (KC); ++ks) {                                                 \
        u32 a[8];                                                                       \
        u32 ab = (STG_ABS) + stRowB + (u32)ks * 1280u;                                  \
        ldsm4t(a[0], a[1], a[2], a[3], ab + sxT0);                                      \
        ldsm4t(a[4], a[5], a[6], a[7], ab + sxT1);                                      \
        u32 cb = ((2u * ks + gBc) ^ lx) << 4;                                           \
        _Pragma("unroll")                                                               \
        for (int ntp = 0; ntp < 4; ++ntp) {                                             \
            u32 b0, b1, b2, b3;                                                         \
            ldsm4(b0, b1, b2, b3, (B_B) + ntp * 2048 + cb);                             \
            _Pragma("unroll")                                                           \
            for (int mt = 0; mt < 2; ++mt) {                                            \
                mma_fp16(acc[mt][2*ntp][0], acc[mt][2*ntp][1], acc[mt][2*ntp][2], acc[mt][2*ntp][3], \
                         a[4*mt], a[4*mt+1], a[4*mt+2], a[4*mt+3], b0, b1);             \
                mma_fp16(acc[mt][2*ntp+1][0], acc[mt][2*ntp+1][1], acc[mt][2*ntp+1][2], acc[mt][2*ntp+1][3], \
                         a[4*mt], a[4*mt+1], a[4*mt+2], a[4*mt+3], b2, b3);             \
            }                                                                           \
        }                                                                               \
    }

#define ZERO_ACC()                                                                      \
    _Pragma("unroll")                                                                   \
    for (int mt = 0; mt < 2; ++mt)                                                      \
        _Pragma("unroll")                                                               \
        for (int nt = 0; nt < 8; ++nt)                                                  \
            _Pragma("unroll")                                                           \
            for (int r = 0; r < 4; ++r) acc[mt][nt][r] = 0.0f;

    // ---- prologue x-mma: acc = Xpart_0 (from stage0, trans) ----
    ZERO_ACC()
    MMA1T(smb + SM_ST0 + (u32)grp * STG_GRP, bxB, KCX)

    for (int t = 0; t < TSTEPS; ++t) {
        GBAR(barid);   // gbar1: group's h STS from t-1 visible; stage slot free

        // fetch own group's quarter of x_{t+1} (overlaps h-mma)
        if (t + 1 < TSTEPS) {
            XFETCH(t + 1, ((t + 1) & 1) ? SM_ST1 : SM_ST0)
        }

        // h-part: acc += h_{t-1} . Whh^T   (group-local h tile)
        MMA1(aB, bhB, 4)

        // ---- epilogue: fp32 gates, fp32 cell state ----
        float hval[16];
        #pragma unroll
        for (int mt = 0; mt < 2; ++mt)
            #pragma unroll
            for (int d = 0; d < 2; ++d)
                #pragma unroll
                for (int h2i = 0; h2i < 2; ++h2i)
                    #pragma unroll
                    for (int e = 0; e < 2; ++e) {
                        int r = 2 * d + e;
                        int ci = ((mt * 2 + d) * 2 + h2i) * 2 + e;
                        int bi = h2i * 2 + e;
                        float gi = sigm_a(acc[mt][4*h2i + 0][r] + breg[bi]);
                        float gf = sigm_a(acc[mt][4*h2i + 1][r] + breg[4 + bi]);
                        float gg = tanh_a(acc[mt][4*h2i + 2][r] + breg[8 + bi]);
                        float go = sigm_a(acc[mt][4*h2i + 3][r] + breg[12 + bi]);
                        float cc = fmaf(gf, cst[ci], gi * gg);
                        cst[ci] = cc;
                        hval[ci] = go * tanh_a(cc);
                    }

        cp_wait_all();     // own x_{t+1} chunks landed
        GBAR(barid);       // gbar2: group staged x_{t+1}; group h-mma reads done

        if (t == TSTEPS - 1) {
            const int off = wrf ? 64 : 0;
            #pragma unroll
            for (int mt = 0; mt < 2; ++mt)
                #pragma unroll
                for (int d = 0; d < 2; ++d)
                    #pragma unroll
                    for (int h2i = 0; h2i < 2; ++h2i)
                        #pragma unroll
                        for (int e = 0; e < 2; ++e) {
                            int s = grp * 32 + mt * 16 + (lane >> 2) + 8 * d;
                            int j = warpN * 16 + h2i * 8 + (lane & 3) * 2 + e;
                            int ci = ((mt * 2 + d) * 2 + h2i) * 2 + e;
                            g_featT[(size_t)(off + j) * NS + n0 + s] = hval[ci];
                        }
        } else {
            // STS h_t -> group-local AH (fp16, sample-major)
            #pragma unroll
            for (int mt = 0; mt < 2; ++mt)
                #pragma unroll
                for (int d = 0; d < 2; ++d)
                    #pragma unroll
                    for (int h2i = 0; h2i < 2; ++h2i) {
                        int ci = ((mt * 2 + d) * 2 + h2i) * 2;
                        __half hh0 = __float2half_rn(hval[ci]);
                        __half hh1 = __float2half_rn(hval[ci + 1]);
                        u32 hi32 = (u32)__half_as_ushort(hh0) | ((u32)__half_as_ushort(hh1) << 16);
                        u32 s  = (u32)(mt * 16 + (lane >> 2) + 8 * d);
                        u32 jp = (u32)(warpN * 16 + h2i * 8 + (lane & 3) * 2);
                        u32 off = (u32)grp * 4096u + swz(s, jp >> 3) + (jp & 7) * 2;
                        *(u32*)(smem + SM_AH + off) = hi32;
                    }
            // tail x-mma for t+1 straight from stage (trans) — anti-phase overlap
            ZERO_ACC()
            MMA1T((((t + 1) & 1) ? (smb + SM_ST1) : (smb + SM_ST0)) + (u32)grp * STG_GRP,
                  bxB, KCX)
        }
    }
#undef MMA1
#undef MMA1T
#undef ZERO_ACC
#undef XFETCH
}

// ---------------- kernel 3: MLP heads (512 threads, 4 samples/thread) -------
#define SPAD 132
__device__ __forceinline__ u64 dup2(float x) {
    u64 r; asm("mov.b64 %0, {%1,%1};" : "=l"(r) : "f"(x)); return r;
}
__device__ __forceinline__ void unpack2(u64 v, float& x, float& y) {
    asm("mov.b64 {%0,%1}, %2;" : "=f"(x), "=f"(y) : "l"(v));
}
__device__ __forceinline__ u64 ffma2(u64 a, u64 b, u64 c) {
    u64 d; asm("fma.rn.f32x2 %0, %1, %2, %3;" : "=l"(d) : "l"(a), "l"(b), "l"(c)); return d;
}

template <int IN, int OUT, bool RELU>
__device__ __forceinline__ void athx_layer4(const float* __restrict__ A,
                                            const float* __restrict__ wt,
                                            const float* __restrict__ bs,
                                            float* __restrict__ Bout,
                                            int gx, int sx) {
    constexpr int R = OUT / 16;
    u64 acc2[2][R];
    #pragma unroll
    for (int sp = 0; sp < 2; ++sp)
        #pragma unroll
        for (int r = 0; r < R; ++r) acc2[sp][r] = 0ull;
    for (int k = 0; k < IN; ++k) {
        ulonglong2 p = *(const ulonglong2*)(A + k * SPAD + sx * 4);
        u64 a2[2] = {p.x, p.y};
        #pragma unroll
        for (int r = 0; r < R; ++r) {
            u64 b2 = dup2(wt[k * OUT + gx + 16 * r]);
            #pragma unroll
            for (int sp = 0; sp < 2; ++sp) acc2[sp][r] = ffma2(a2[sp], b2, acc2[sp][r]);
        }
    }
    #pragma unroll
    for (int r = 0; r < R; ++r) {
        int u = gx + 16 * r;
        float bb = bs[u];
        float hv[4];
        #pragma unroll
        for (int sp = 0; sp < 2; ++sp) {
            float v0, v1;
            unpack2(acc2[sp][r], v0, v1);
            v0 += bb; v1 += bb;
            hv[2 * sp]     = RELU ? fmaxf(v0, 0.0f) : v0;
            hv[2 * sp + 1] = RELU ? fmaxf(v1, 0.0f) : v1;
        }
        *(float4*)(Bout + u * SPAD + sx * 4) = make_float4(hv[0], hv[1], hv[2], hv[3]);
    }
}

__global__ __launch_bounds__(512, 1) void athx_head_kernel(
    const float* __restrict__ fW1, const float* __restrict__ fb1,
    const float* __restrict__ fW2, const float* __restrict__ fb2,
    const float* __restrict__ fW3, const float* __restrict__ fb3,
    const float* __restrict__ oW1, const float* __restrict__ ob1,
    const float* __restrict__ oW2, const float* __restrict__ ob2,
    const float* __restrict__ oW3, const float* __restrict__ ob3,
    float* __restrict__ out)
{
    extern __shared__ float sm[];
    float* A   = sm;
    float* B   = A + 128 * SPAD;
    float* w1t = B + 96 * SPAD;
    float* w2t = w1t + 128 * 96;
    float* w3t = w2t + 96 * 64;
    float* bs1 = w3t + 64 * 48;
    float* bs2 = bs1 + 96;
    float* bs3 = bs2 + 64;

    const int head = blockIdx.y;
    const float* W1 = head ? oW1 : fW1; const float* b1 = head ? ob1 : fb1;
    const float* W2 = head ? oW2 : fW2; const float* b2 = head ? ob2 : fb2;
    const float* W3 = head ? oW3 : fW3; const float* b3 = head ? ob3 : fb3;
    const int n0  = blockIdx.x * 128;
    const int tid = threadIdx.x;
    const int gx  = tid & 15, sx = tid >> 4;   // sx 0..31, 4 samples each

    for (int idx = tid; idx < 128 * 128; idx += 512) {
        int k = idx >> 7, s = idx & 127;
        A[k * SPAD + s] = g_featT[(size_t)k * NS + n0 + s];
    }
    for (int idx = tid; idx < 96 * 128; idx += 512) {
        int u = idx >> 7, k = idx & 127;
        w1t[k * 96 + u] = W1[idx];
    }
    for (int idx = tid; idx < 64 * 96; idx += 512) {
        int u = idx / 96, k = idx - u * 96;
        w2t[k * 64 + u] = W2[idx];
    }
    for (int idx = tid; idx < 48 * 64; idx += 512) {
        int u = idx >> 6, k = idx & 63;
        w3t[k * 48 + u] = W3[idx];
    }
    if (tid < 96) bs1[tid] = b1[tid];
    if (tid < 64) bs2[tid] = b2[tid];
    if (tid < 48) bs3[tid] = b3[tid];
    __syncthreads();

    athx_layer4<128, 96, true>(A, w1t, bs1, B, gx, sx);
    __syncthreads();
    athx_layer4<96, 64, true>(B, w2t, bs2, A, gx, sx);
    __syncthreads();

    {
        u64 acc2[2][3];
        #pragma unroll
        for (int sp = 0; sp < 2; ++sp)
            #pragma unroll
            for (int r = 0; r < 3; ++r) acc2[sp][r] = 0ull;
        for (int k = 0; k < 64; ++k) {
            ulonglong2 p = *(const ulonglong2*)(A + k * SPAD + sx * 4);
            u64 a2[2] = {p.x, p.y};
            #pragma unroll
            for (int r = 0; r < 3; ++r) {
                u64 b2 = dup2(w3t[k * 48 + gx + 16 * r]);
                #pragma unroll
                for (int sp = 0; sp < 2; ++sp) acc2[sp][r] = ffma2(a2[sp], b2, acc2[sp][r]);
            }
        }
        #pragma unroll
        for (int r = 0; r < 3; ++r) {
            int u = gx + 16 * r;
            float bb = bs3[u];
            #pragma unroll
            for (int sp = 0; sp < 2; ++sp) {
                float v0, v1;
                unpack2(acc2[sp][r], v0, v1);
                int n = n0 + sx * 4 + 2 * sp;
                out[(size_t)n * 96 + head * 48 + u]       = v0 + bb;
                out[(size_t)(n + 1) * 96 + head * 48 + u] = v1 + bb;
            }
        }
    }
}

// ---------------- launch ----------------------------------------------------
extern "C" void kernel_launch(void* const* d_in, const int* in_sizes, int n_in,
                              void* d_out, int out_size) {
    const float* X_obs  = (const float*)d_in[0];
    const float* X_wrf  = (const float*)d_in[1];
    const float* oWih   = (const float*)d_in[2];
    const float* oWhh   = (const float*)d_in[3];
    const float* obih   = (const float*)d_in[4];
    const float* obhh   = (const float*)d_in[5];
    const float* wWih   = (const float*)d_in[6];
    const float* wWhh   = (const float*)d_in[7];
    const float* wbih   = (const float*)d_in[8];
    const float* wbhh   = (const float*)d_in[9];
    const float* fW1 = (const float*)d_in[10]; const float* fb1 = (const float*)d_in[11];
    const float* fW2 = (const float*)d_in[12]; const float* fb2 = (const float*)d_in[13];
    const float* fW3 = (const float*)d_in[14]; const float* fb3 = (const float*)d_in[15];
    const float* oW1 = (const float*)d_in[16]; const float* ob1 = (const float*)d_in[17];
    const float* oW2 = (const float*)d_in[18]; const float* ob2 = (const float*)d_in[19];
    const float* oW3 = (const float*)d_in[20]; const float* ob3 = (const float*)d_in[21];
    float* out = (float*)d_out;

    const int HEAD_SMEM = (128 * SPAD + 96 * SPAD + 128 * 96 + 96 * 64 + 64 * 48
                           + 96 + 64 + 48) * 4;
    cudaFuncSetAttribute(athx_lstm_mma, cudaFuncAttributeMaxDynamicSharedMemorySize, SM_TOTAL);
    cudaFuncSetAttribute(athx_head_kernel, cudaFuncAttributeMaxDynamicSharedMemorySize, HEAD_SMEM);

    athx_transpose_kernel<<<dim3(NS / 32, 3, 32), dim3(32, 8)>>>(X_obs, 32, 0);
    athx_transpose_kernel<<<dim3(NS / 32, 3, 56), dim3(32, 8)>>>(X_wrf, 56, 1);

    athx_lstm_mma<<<128, 512, SM_TOTAL>>>(oWih, oWhh, obih, obhh,
                                          wWih, wWhh, wbih, wbhh);

    athx_head_kernel<<<dim3(NS / 128, 2), 512, HEAD_SMEM>>>(
        fW1, fb1, fW2, fb2, fW3, fb3,
        oW1, ob1, oW2, ob2, oW3, ob3, out);
}

// round 13
// speedup vs baseline: 4.4830x; 1.0640x over previous
#include <cuda_runtime.h>
#include <cuda_fp16.h>
#include <cstdint>

#define NS     8192
#define TSTEPS 72

typedef unsigned long long u64;
typedef unsigned int       u32;
typedef unsigned short     u16;

// ---------------- scratch (device globals; no allocation allowed) ----------
__device__ u16   g_xt_obs[TSTEPS * 32 * NS];   // [T][C1][N] fp16
__device__ u16   g_xt_wrf[TSTEPS * 56 * NS];   // [T][C2][N] fp16
__device__ float g_featT[128 * NS];            // [128][N]

// ---------------- smem layout (bytes) for LSTM kernel ----------------------
#define SM_AH    0          // h [4 groups][32x64] fp16 sample-major, 4x4 KB
#define SM_BH    16384      // Whh [256x64] fp16, 32 KB
#define SM_BX    49152      // Wih [256x64] fp16, 32 KB
#define SM_ST0   81920      // stage buf0: [4 groups][64 ch rows x 80B]
#define STG_GRP  5120       // 64 rows x 80 B
#define STG_BUF  20480      // 4 groups
#define SM_ST1   102400     // stage buf1
#define SM_TOTAL 122880

// ---------------- math helpers ---------------------------------------------
__device__ __forceinline__ float tanh_a(float x) {
    float y; asm("tanh.approx.f32 %0, %1;" : "=f"(y) : "f"(x)); return y;
}
__device__ __forceinline__ float sigm_a(float x) {
    return fmaf(0.5f, tanh_a(0.5f * x), 0.5f);
}

// ---------------- PTX helpers -----------------------------------------------
__device__ __forceinline__ u32 smem_u32(const void* p) {
    u32 a;
    asm("{ .reg .u64 t; cvta.to.shared.u64 t, %1; cvt.u32.u64 %0, t; }" : "=r"(a) : "l"(p));
    return a;
}
__device__ __forceinline__ void cp_async16(char* smem_dst, const void* gsrc) {
    u32 sa = smem_u32(smem_dst);
    asm volatile("cp.async.ca.shared.global [%0], [%1], 16;\n" :: "r"(sa), "l"(gsrc));
}
__device__ __forceinline__ void cp_commit()   { asm volatile("cp.async.commit_group;\n"); }
__device__ __forceinline__ void cp_wait_all() { asm volatile("cp.async.wait_all;\n"); }

__device__ __forceinline__ void ldsm4(u32& r0, u32& r1, u32& r2, u32& r3, u32 addr) {
    asm volatile("ldmatrix.sync.aligned.m8n8.x4.shared.b16 {%0,%1,%2,%3}, [%4];"
                 : "=r"(r0), "=r"(r1), "=r"(r2), "=r"(r3) : "r"(addr));
}
__device__ __forceinline__ void ldsm4t(u32& r0, u32& r1, u32& r2, u32& r3, u32 addr) {
    asm volatile("ldmatrix.sync.aligned.m8n8.x4.trans.shared.b16 {%0,%1,%2,%3}, [%4];"
                 : "=r"(r0), "=r"(r1), "=r"(r2), "=r"(r3) : "r"(addr));
}
__device__ __forceinline__ void mma_fp16(float& d0, float& d1, float& d2, float& d3,
                                         u32 a0, u32 a1, u32 a2, u32 a3,
                                         u32 b0, u32 b1) {
    asm volatile("mma.sync.aligned.m16n8k16.row.col.f32.f16.f16.f32 "
                 "{%0,%1,%2,%3}, {%4,%5,%6,%7}, {%8,%9}, {%0,%1,%2,%3};"
                 : "+f"(d0), "+f"(d1), "+f"(d2), "+f"(d3)
                 : "r"(a0), "r"(a1), "r"(a2), "r"(a3), "r"(b0), "r"(b1));
}

// sample-major: row stride 128B, 16B chunk index ^= (row&7)
__device__ __forceinline__ u32 swz(u32 row, u32 chunk) {
    return row * 128u + ((chunk ^ (row & 7u)) << 4);
}

// B row permutation: gate-quad-aligned fragment ownership
__device__ __forceinline__ int brow(int g) {
    int q = g >> 6, j = g & 63;
    int warpN = j >> 4, jl = j & 15;
    int hi = jl >> 3, a = (jl & 7) >> 1, e = jl & 1;
    return warpN * 64 + 8 * (q + 4 * hi) + 2 * a + e;
}

// group-scoped barrier: 128 threads, ids 1..4
#define GBAR(id) asm volatile("bar.sync %0, 128;" :: "r"(id) : "memory")

// ---------------- kernel 1: transpose [N][C][T] -> [T][C][N] fp16 -----------
// 64-sample tiles: stores are 128B per warp-row (full-efficiency HBM writes).
__global__ void athx_transpose_kernel(const float* __restrict__ in, int C, int which) {
    __shared__ float tile[32][65];     // [t_local][n_local], stride 65 words
    u16* out = which ? g_xt_wrf : g_xt_obs;
    const int c  = blockIdx.z;
    const int n0 = blockIdx.x * 64;
    const int t0 = blockIdx.y * 32;
    const int tx = threadIdx.x, ty = threadIdx.y;  // 32 x 8
    if (t0 + tx < TSTEPS) {
        #pragma unroll
        for (int r = 0; r < 8; ++r) {
            int n = ty + r * 8;
            tile[tx][n] = in[((size_t)(n0 + n) * C + c) * TSTEPS + t0 + tx];
        }
    }
    __syncthreads();
    #pragma unroll
    for (int rr = 0; rr < 4; ++rr) {
        int tl = ty + 8 * rr;
        int t = t0 + tl;
        if (t < TSTEPS) {
            __half2 h2 = __floats2half2_rn(tile[tl][2 * tx], tile[tl][2 * tx + 1]);
            *(u32*)(&out[((size_t)t * C + c) * NS + n0 + 2 * tx]) = *(u32*)&h2;
        }
    }
}

// ---------------- kernel 2: HMMA dual-LSTM, 4-group anti-phase (R12) --------
__global__ __launch_bounds__(512, 1)
void athx_lstm_mma(const float* __restrict__ oWih, const float* __restrict__ oWhh,
                   const float* __restrict__ obih, const float* __restrict__ obhh,
                   const float* __restrict__ wWih, const float* __restrict__ wWhh,
                   const float* __restrict__ wbih, const float* __restrict__ wbhh)
{
    extern __shared__ char smem[];
    const bool wrf = (blockIdx.x >= 64);
    const int  C   = wrf ? 56 : 32;
    const int  KCX = wrf ? 4 : 2;         // x k-chunks (16 cols each)
    const u16* xt = wrf ? g_xt_wrf : g_xt_obs;
    const float* Wih = wrf ? wWih : oWih;
    const float* Whh = wrf ? wWhh : oWhh;
    const float* bih = wrf ? wbih : obih;
    const float* bhh = wrf ? wbhh : obhh;
    const int n0  = (blockIdx.x & 63) * 128;
    const int tid = threadIdx.x;
    const int lane = tid & 31;
    const int grp  = tid >> 7;            // 0..3 (4 warps each)
    const int tg   = tid & 127;           // thread-in-group
    const int warpN = (tid >> 5) & 3;     // warp-in-group = gate column group

    const u32 smb = smem_u32(smem);
    const int barid = 1 + grp;

    // per-group x fetch into padded-stride stage: [ch row x 80B], 4 chunks/row
#define XFETCH(TIDX, STG_OFF)                                                    \
    {                                                                            \
        const u16* src = xt + (size_t)(TIDX) * C * NS + n0 + grp * 32;           \
        char* dst = smem + (STG_OFF) + grp * STG_GRP;                            \
        for (int i = tg; i < C * 4; i += 128) {                                  \
            int ch = i >> 2, j = i & 3;                                          \
            cp_async16(dst + ch * 80 + j * 16,                                   \
                       src + (size_t)ch * NS + j * 8);                           \
        }                                                                        \
        cp_commit();                                                             \
    }

    // ---- zero ALL smem (h=0, BX pad cols, stage pad rows) ----
    for (int i = tid; i < SM_TOTAL / 16; i += 512)
        ((uint4*)smem)[i] = make_uint4(0, 0, 0, 0);
    __syncthreads();

    // ---- prefetch x_0 (own group's quarter) ----
    XFETCH(0, SM_ST0)

    // ---- fill B_h (Whh fp16), B_x (Wih fp16) — full CTA ----
    for (int i = tid; i < 256 * 64; i += 512) {
        int g = i >> 6, k = i & 63;
        u32 off = swz((u32)brow(g), (u32)(k >> 3)) + (k & 7) * 2;
        *(__half*)(smem + SM_BH + off) = __float2half_rn(Whh[i]);
    }
    for (int i = tid; i < 256 * C; i += 512) {
        int g = i / C, ch = i - g * C;
        u32 off = swz((u32)brow(g), (u32)(ch >> 3)) + (ch & 7) * 2;
        *(__half*)(smem + SM_BX + off) = __float2half_rn(Wih[i]);
    }

    // ---- bias into registers (per-thread 16 gates, fp32) ----
    const int jbase = warpN * 16 + (lane & 3) * 2;
    float breg[16];
    #pragma unroll
    for (int q = 0; q < 4; ++q)
        #pragma unroll
        for (int h2i = 0; h2i < 2; ++h2i)
            #pragma unroll
            for (int e = 0; e < 2; ++e) {
                int g = q * 64 + jbase + h2i * 8 + e;
                breg[q * 4 + h2i * 2 + e] = bih[g] + bhh[g];
            }

    cp_wait_all();
    __syncthreads();    // B fills + zeros + all stage quarters visible

    // ---- per-thread ldmatrix geometry ----
    const int g8 = lane >> 3, l = lane & 7;
    const u32 aRow = (u32)((g8 & 1) * 8 + l);                // 0..15 local
    const u32 bRow = (u32)(warpN * 64 + ((g8 >> 1) & 1) * 8 + l);
    const u32 gAc = (u32)(g8 >> 1);
    const u32 gBc = (u32)(g8 & 1);
    const u32 lx = (u32)l;
    const u32 aB  = smb + SM_AH + (u32)grp * 4096u + aRow * 128;
    const u32 bhB = smb + SM_BH + bRow * 128;
    const u32 bxB = smb + SM_BX + bRow * 128;
    // trans-ldsm geometry for padded-stride stage (no XOR needed)
    const u32 stRowB = (u32)(gAc * 8 + (u32)l) * 80u;        // channel row offset
    const u32 sxT0 = ((u32)(g8 & 1)) << 4;                   // sample chunks 0/1
    const u32 sxT1 = sxT0 + 32u;                             // sample chunks 2/3

    float acc[2][8][4];
    float cst[16];
    #pragma unroll
    for (int i = 0; i < 16; ++i) cst[i] = 0.0f;

    // sample-major A (h-part, group-local 32x64 tile)
#define MMA1(A_B, B_B, KC)                                                              \
    for (int ks = 0; ks < (KC); ++ks) {                                                 \
        u32 a[8];                                                                       \
        u32 ca = ((2u * ks + gAc) ^ lx) << 4;                                           \
        ldsm4(a[0], a[1], a[2], a[3], (A_B) + ca);                                      \
        ldsm4(a[4], a[5], a[6], a[7], (A_B) + 2048 + ca);                               \
        u32 cb = ((2u * ks + gBc) ^ lx) << 4;                                           \
        _Pragma("unroll")                                                               \
        for (int ntp = 0; ntp < 4; ++ntp) {                                             \
            u32 b0, b1, b2, b3;                                                         \
            ldsm4(b0, b1, b2, b3, (B_B) + ntp * 2048 + cb);                             \
            _Pragma("unroll")                                                           \
            for (int mt = 0; mt < 2; ++mt) {                                            \
                mma_fp16(acc[mt][2*ntp][0], acc[mt][2*ntp][1], acc[mt][2*ntp][2], acc[mt][2*ntp][3], \
                         a[4*mt], a[4*mt+1], a[4*mt+2], a[4*mt+3], b0, b1);             \
                mma_fp16(acc[mt][2*ntp+1][0], acc[mt][2*ntp+1][1], acc[mt][2*ntp+1][2], acc[mt][2*ntp+1][3], \
                         a[4*mt], a[4*mt+1], a[4*mt+2], a[4*mt+3], b2, b3);             \
            }                                                                           \
        }                                                                               \
    }

    // padded-stride stage A via ldmatrix.trans (x-part)
#define MMA1T(STG_ABS, B_B, KC)                                                         \
    for (int ks = 0; ks < (KC); ++ks) {                                                 \
        u32 a[8];                                                                       \
        u32 ab = (STG_ABS) + stRowB + (u32)ks * 1280u;                                  \
        ldsm4t(a[0], a[1], a[2], a[3], ab + sxT0);                                      \
        ldsm4t(a[4], a[5], a[6], a[7], ab + sxT1);                                      \
        u32 cb = ((2u * ks + gBc) ^ lx) << 4;                                           \
        _Pragma("unroll")                                                               \
        for (int ntp = 0; ntp < 4; ++ntp) {                                             \
            u32 b0, b1, b2, b3;                                                         \
            ldsm4(b0, b1, b2, b3, (B_B) + ntp * 2048 + cb);                             \
            _Pragma("unroll")                                                           \
            for (int mt = 0; mt < 2; ++mt) {                                            \
                mma_fp16(acc[mt][2*ntp][0], acc[mt][2*ntp][1], acc[mt][2*ntp][2], acc[mt][2*ntp][3], \
                         a[4*mt], a[4*mt+1], a[4*mt+2], a[4*mt+3], b0, b1);             \
                mma_fp16(acc[mt][2*ntp+1][0], acc[mt][2*ntp+1][1], acc[mt][2*ntp+1][2], acc[mt][2*ntp+1][3], \
                         a[4*mt], a[4*mt+1], a[4*mt+2], a[4*mt+3], b2, b3);             \
            }                                                                           \
        }                                                                               \
    }

#define ZERO_ACC()                                                                      \
    _Pragma("unroll")                                                                   \
    for (int mt = 0; mt < 2; ++mt)                                                      \
        _Pragma("unroll")                                                               \
        for (int nt = 0; nt < 8; ++nt)                                                  \
            _Pragma("unroll")                                                           \
            for (int r = 0; r < 4; ++r) acc[mt][nt][r] = 0.0f;

    // ---- prologue x-mma: acc = Xpart_0 (from stage0, trans) ----
    ZERO_ACC()
    MMA1T(smb + SM_ST0 + (u32)grp * STG_GRP, bxB, KCX)

    for (int t = 0; t < TSTEPS; ++t) {
        GBAR(barid);   // gbar1: group's h STS from t-1 visible; stage slot free

        // fetch own group's quarter of x_{t+1} (overlaps h-mma)
        if (t + 1 < TSTEPS) {
            XFETCH(t + 1, ((t + 1) & 1) ? SM_ST1 : SM_ST0)
        }

        // h-part: acc += h_{t-1} . Whh^T   (group-local h tile)
        MMA1(aB, bhB, 4)

        // ---- epilogue: fp32 gates, fp32 cell state ----
        float hval[16];
        #pragma unroll
        for (int mt = 0; mt < 2; ++mt)
            #pragma unroll
            for (int d = 0; d < 2; ++d)
                #pragma unroll
                for (int h2i = 0; h2i < 2; ++h2i)
                    #pragma unroll
                    for (int e = 0; e < 2; ++e) {
                        int r = 2 * d + e;
                        int ci = ((mt * 2 + d) * 2 + h2i) * 2 + e;
                        int bi = h2i * 2 + e;
                        float gi = sigm_a(acc[mt][4*h2i + 0][r] + breg[bi]);
                        float gf = sigm_a(acc[mt][4*h2i + 1][r] + breg[4 + bi]);
                        float gg = tanh_a(acc[mt][4*h2i + 2][r] + breg[8 + bi]);
                        float go = sigm_a(acc[mt][4*h2i + 3][r] + breg[12 + bi]);
                        float cc = fmaf(gf, cst[ci], gi * gg);
                        cst[ci] = cc;
                        hval[ci] = go * tanh_a(cc);
                    }

        cp_wait_all();     // own x_{t+1} chunks landed
        GBAR(barid);       // gbar2: group staged x_{t+1}; group h-mma reads done

        if (t == TSTEPS - 1) {
            const int off = wrf ? 64 : 0;
            #pragma unroll
            for (int mt = 0; mt < 2; ++mt)
                #pragma unroll
                for (int d = 0; d < 2; ++d)
                    #pragma unroll
                    for (int h2i = 0; h2i < 2; ++h2i)
                        #pragma unroll
                        for (int e = 0; e < 2; ++e) {
                            int s = grp * 32 + mt * 16 + (lane >> 2) + 8 * d;
                            int j = warpN * 16 + h2i * 8 + (lane & 3) * 2 + e;
                            int ci = ((mt * 2 + d) * 2 + h2i) * 2 + e;
                            g_featT[(size_t)(off + j) * NS + n0 + s] = hval[ci];
                        }
        } else {
            // STS h_t -> group-local AH (fp16, sample-major)
            #pragma unroll
            for (int mt = 0; mt < 2; ++mt)
                #pragma unroll
                for (int d = 0; d < 2; ++d)
                    #pragma unroll
                    for (int h2i = 0; h2i < 2; ++h2i) {
                        int ci = ((mt * 2 + d) * 2 + h2i) * 2;
                        __half hh0 = __float2half_rn(hval[ci]);
                        __half hh1 = __float2half_rn(hval[ci + 1]);
                        u32 hi32 = (u32)__half_as_ushort(hh0) | ((u32)__half_as_ushort(hh1) << 16);
                        u32 s  = (u32)(mt * 16 + (lane >> 2) + 8 * d);
                        u32 jp = (u32)(warpN * 16 + h2i * 8 + (lane & 3) * 2);
                        u32 off = (u32)grp * 4096u + swz(s, jp >> 3) + (jp & 7) * 2;
                        *(u32*)(smem + SM_AH + off) = hi32;
                    }
            // tail x-mma for t+1 straight from stage (trans) — anti-phase overlap
            ZERO_ACC()
            MMA1T((((t + 1) & 1) ? (smb + SM_ST1) : (smb + SM_ST0)) + (u32)grp * STG_GRP,
                  bxB, KCX)
        }
    }
#undef MMA1
#undef MMA1T
#undef ZERO_ACC
#undef XFETCH
}

// ---------------- kernel 3: MLP heads (LDS-lean tiling) ---------------------
#define SPAD 132
__device__ __forceinline__ u64 dup2(float x) {
    u64 r; asm("mov.b64 %0, {%1,%1};" : "=l"(r) : "f"(x)); return r;
}
__device__ __forceinline__ void unpack2(u64 v, float& x, float& y) {
    asm("mov.b64 {%0,%1}, %2;" : "=f"(x), "=f"(y) : "l"(v));
}
__device__ __forceinline__ u64 ffma2(u64 a, u64 b, u64 c) {
    u64 d; asm("fma.rn.f32x2 %0, %1, %2, %3;" : "=l"(d) : "l"(a), "l"(b), "l"(c)); return d;
}

// GX output-groups x (512/GX) sample-groups; SPT=128/(512/GX) samples/thread
template <int IN, int OUT, int GX, bool RELU>
__device__ __forceinline__ void athx_layerg(const float* __restrict__ A,
                                            const float* __restrict__ wt,
                                            const float* __restrict__ bs,
                                            float* __restrict__ Bout,
                                            int tid) {
    const int gx = tid & (GX - 1);
    const int sx = tid / GX;
    constexpr int NSX = 512 / GX;
    constexpr int SPT = 128 / NSX;
    constexpr int PAIRS = SPT / 2;
    constexpr int R = OUT / GX;
    u64 acc2[PAIRS][R];
    #pragma unroll
    for (int p = 0; p < PAIRS; ++p)
        #pragma unroll
        for (int r = 0; r < R; ++r) acc2[p][r] = 0ull;
    for (int k = 0; k < IN; ++k) {
        u64 a2[PAIRS];
        #pragma unroll
        for (int p = 0; p < PAIRS; ++p)
            a2[p] = *(const u64*)(A + k * SPAD + sx * SPT + 2 * p);
        #pragma unroll
        for (int r = 0; r < R; ++r) {
            u64 b2 = dup2(wt[k * OUT + gx + GX * r]);
            #pragma unroll
            for (int p = 0; p < PAIRS; ++p) acc2[p][r] = ffma2(a2[p], b2, acc2[p][r]);
        }
    }
    #pragma unroll
    for (int r = 0; r < R; ++r) {
        int u = gx + GX * r;
        float bb = bs[u];
        #pragma unroll
        for (int p = 0; p < PAIRS; ++p) {
            float v0, v1;
            unpack2(acc2[p][r], v0, v1);
            v0 += bb; v1 += bb;
            if (RELU) { v0 = fmaxf(v0, 0.0f); v1 = fmaxf(v1, 0.0f); }
            *(float2*)(Bout + u * SPAD + sx * SPT + 2 * p) = make_float2(v0, v1);
        }
    }
}

__global__ __launch_bounds__(512, 1) void athx_head_kernel(
    const float* __restrict__ fW1, const float* __restrict__ fb1,
    const float* __restrict__ fW2, const float* __restrict__ fb2,
    const float* __restrict__ fW3, const float* __restrict__ fb3,
    const float* __restrict__ oW1, const float* __restrict__ ob1,
    const float* __restrict__ oW2, const float* __restrict__ ob2,
    const float* __restrict__ oW3, const float* __restrict__ ob3,
    float* __restrict__ out)
{
    extern __shared__ float sm[];
    float* A   = sm;
    float* B   = A + 128 * SPAD;
    float* w1t = B + 96 * SPAD;
    float* w2t = w1t + 128 * 96;
    float* w3t = w2t + 96 * 64;
    float* bs1 = w3t + 64 * 48;
    float* bs2 = bs1 + 96;
    float* bs3 = bs2 + 64;

    const int head = blockIdx.y;
    const float* W1 = head ? oW1 : fW1; const float* b1 = head ? ob1 : fb1;
    const float* W2 = head ? oW2 : fW2; const float* b2 = head ? ob2 : fb2;
    const float* W3 = head ? oW3 : fW3; const float* b3 = head ? ob3 : fb3;
    const int n0  = blockIdx.x * 128;
    const int tid = threadIdx.x;

    for (int idx = tid; idx < 128 * 128; idx += 512) {
        int k = idx >> 7, s = idx & 127;
        A[k * SPAD + s] = g_featT[(size_t)k * NS + n0 + s];
    }
    // w1t[k][u]: u = gx + 32*r mapping matches athx_layerg<...,32,...>
    for (int idx = tid; idx < 96 * 128; idx += 512) {
        int u = idx >> 7, k = idx & 127;
        w1t[k * 96 + u] = W1[idx];
    }
    for (int idx = tid; idx < 64 * 96; idx += 512) {
        int u = idx / 96, k = idx - u * 96;
        w2t[k * 64 + u] = W2[idx];
    }
    for (int idx = tid; idx < 48 * 64; idx += 512) {
        int u = idx >> 6, k = idx & 63;
        w3t[k * 48 + u] = W3[idx];
    }
    if (tid < 96) bs1[tid] = b1[tid];
    if (tid < 64) bs2[tid] = b2[tid];
    if (tid < 48) bs3[tid] = b3[tid];
    __syncthreads();

    athx_layerg<128, 96, 32, true>(A, w1t, bs1, B, tid);
    __syncthreads();
    athx_layerg<96, 64, 32, true>(B, w2t, bs2, A, tid);
    __syncthreads();

    // layer 3 (64 -> 48): GX=16, 4 samples/thread, write to gmem
    {
        const int gx = tid & 15;
        const int sx = tid >> 4;        // 0..31, 4 samples each
        u64 acc2[2][3];
        #pragma unroll
        for (int p = 0; p < 2; ++p)
            #pragma unroll
            for (int r = 0; r < 3; ++r) acc2[p][r] = 0ull;
        for (int k = 0; k < 64; ++k) {
            ulonglong2 pq = *(const ulonglong2*)(A + k * SPAD + sx * 4);
            u64 a2[2] = {pq.x, pq.y};
            #pragma unroll
            for (int r = 0; r < 3; ++r) {
                u64 b2 = dup2(w3t[k * 48 + gx + 16 * r]);
                #pragma unroll
                for (int p = 0; p < 2; ++p) acc2[p][r] = ffma2(a2[p], b2, acc2[p][r]);
            }
        }
        #pragma unroll
        for (int r = 0; r < 3; ++r) {
            int u = gx + 16 * r;
            float bb = bs3[u];
            #pragma unroll
            for (int p = 0; p < 2; ++p) {
                float v0, v1;
                unpack2(acc2[p][r], v0, v1);
                int n = n0 + sx * 4 + 2 * p;
                out[(size_t)n * 96 + head * 48 + u]       = v0 + bb;
                out[(size_t)(n + 1) * 96 + head * 48 + u] = v1 + bb;
            }
        }
    }
}

// ---------------- launch ----------------------------------------------------
extern "C" void kernel_launch(void* const* d_in, const int* in_sizes, int n_in,
                              void* d_out, int out_size) {
    const float* X_obs  = (const float*)d_in[0];
    const float* X_wrf  = (const float*)d_in[1];
    const float* oWih   = (const float*)d_in[2];
    const float* oWhh   = (const float*)d_in[3];
    const float* obih   = (const float*)d_in[4];
    const float* obhh   = (const float*)d_in[5];
    const float* wWih   = (const float*)d_in[6];
    const float* wWhh   = (const float*)d_in[7];
    const float* wbih   = (const float*)d_in[8];
    const float* wbhh   = (const float*)d_in[9];
    const float* fW1 = (const float*)d_in[10]; const float* fb1 = (const float*)d_in[11];
    const float* fW2 = (const float*)d_in[12]; const float* fb2 = (const float*)d_in[13];
    const float* fW3 = (const float*)d_in[14]; const float* fb3 = (const float*)d_in[15];
    const float* oW1 = (const float*)d_in[16]; const float* ob1 = (const float*)d_in[17];
    const float* oW2 = (const float*)d_in[18]; const float* ob2 = (const float*)d_in[19];
    const float* oW3 = (const float*)d_in[20]; const float* ob3 = (const float*)d_in[21];
    float* out = (float*)d_out;

    const int HEAD_SMEM = (128 * SPAD + 96 * SPAD + 128 * 96 + 96 * 64 + 64 * 48
                           + 96 + 64 + 48) * 4;
    cudaFuncSetAttribute(athx_lstm_mma, cudaFuncAttributeMaxDynamicSharedMemorySize, SM_TOTAL);
    cudaFuncSetAttribute(athx_head_kernel, cudaFuncAttributeMaxDynamicSharedMemorySize, HEAD_SMEM);

    athx_transpose_kernel<<<dim3(NS / 64, 3, 32), dim3(32, 8)>>>(X_obs, 32, 0);
    athx_transpose_kernel<<<dim3(NS / 64, 3, 56), dim3(32, 8)>>>(X_wrf, 56, 1);

    athx_lstm_mma<<<128, 512, SM_TOTAL>>>(oWih, oWhh, obih, obhh,
                                          wWih, wWhh, wbih, wbhh);

    athx_head_kernel<<<dim3(NS / 128, 2), 512, HEAD_SMEM>>>(
        fW1, fb1, fW2, fb2, fW3, fb3,
        oW1, ob1, oW2, ob2, oW3, ob3, out);
}